// round 4
// baseline (speedup 1.0000x reference)
#include <cuda_runtime.h>
#include <math.h>
#include <stdint.h>

#define BB 256
#define LL 200
#define DD 512

// ---------------- scratch ----------------
__device__ float g_xproj[(size_t)BB * LL * 3 * DD];   // [B,L,3D] GRU input proj (+bih)
__device__ float g_sseq [(size_t)LL * BB * DD];       // [L,B,D] GRU outputs
__device__ float g_rx   [(size_t)LL * BB * DD];       // AUGRU x-projections (+bias), [L,B,D]
__device__ float g_ux   [(size_t)LL * BB * DD];
__device__ float g_nx   [(size_t)LL * BB * DD];
__device__ float g_u    [BB * DD];
__device__ float g_logits[LL * BB];
__device__ float g_att   [LL * BB];
__device__ float g_r     [BB * DD];
__device__ float g_ue    [BB * DD];
__device__ float g_h     [2 * BB * DD];
__device__ float g_hp    [BB * 3 * DD];               // GRU h-projection scratch
__device__ float g_zero  [BB * DD];

// grid-barrier state (count resets each use; gen is monotonic across launches)
__device__ unsigned int          g_bar_count = 0;
__device__ volatile unsigned int g_bar_gen   = 0;

__device__ __forceinline__ float sigf(float x) { return 1.0f / (1.0f + __expf(-x)); }

__device__ __forceinline__ uint32_t tf32r(float x) {
    uint32_t r;
    asm("cvt.rna.tf32.f32 %0, %1;" : "=r"(r) : "f"(x));
    return r;
}

__device__ __forceinline__ void mma8(float* d, const uint32_t* a, const uint32_t* b) {
    asm volatile(
        "mma.sync.aligned.m16n8k8.row.col.f32.tf32.tf32.f32 "
        "{%0,%1,%2,%3}, {%4,%5,%6,%7}, {%8,%9}, {%0,%1,%2,%3};"
        : "+f"(d[0]), "+f"(d[1]), "+f"(d[2]), "+f"(d[3])
        : "r"(a[0]), "r"(a[1]), "r"(a[2]), "r"(a[3]), "r"(b[0]), "r"(b[1]));
}

// software grid barrier: all nb blocks must be co-resident (nb <= #SMs here)
__device__ __forceinline__ void grid_barrier(int nb) {
    __syncthreads();
    if (threadIdx.x == 0) {
        __threadfence();
        unsigned int gen = g_bar_gen;
        unsigned int old = atomicAdd(&g_bar_count, 1u);
        if (old == (unsigned)(nb - 1)) {
            atomicExch(&g_bar_count, 0u);
            __threadfence();
            atomicAdd((unsigned int*)&g_bar_gen, 1u);
        } else {
            while (g_bar_gen == gen) { }
        }
        __threadfence();
    }
    __syncthreads();
}

// shared buffers for the mma core (single 36KB instance per kernel)
struct SmemBuf {
    uint32_t Ah[2][16][72], Al[2][16][72];
    uint32_t Wh[2][16][72], Wl[2][16][72];
};

// ============ 64x64xK=512 tf32 core (3xTF32), 128 threads, double-buffered ============
// acc += A[0:64, 0:512] * W[0:64, 0:512]^T  (C[m,n] = sum_k A[m,k]*W[n,k])
// MULR: A multiplied elementwise by R (same layout) at load time.
template<bool MULR>
__device__ __forceinline__ void mm_core64(
    SmemBuf* sb,
    const float* __restrict__ Arow, const float* __restrict__ Rrow, int lda,
    const float* __restrict__ Wrow, int ldw,
    float acc[2][4][4])
{
    const int tid  = threadIdx.x;
    const int lr   = tid >> 1;           // 0..63
    const int lk   = (tid & 1) << 3;     // 0 or 8
    const int lane = tid & 31;
    const int g    = lane >> 2;
    const int t    = lane & 3;
    const int w    = tid >> 5;
    const int mb   = (w >> 1) * 32;
    const int nb   = (w & 1) * 32;

    const float* ap = Arow + (size_t)lr * lda + lk;
    const float* rp = MULR ? (Rrow + (size_t)lr * lda + lk) : nullptr;
    const float* wp = Wrow + (size_t)lr * ldw + lk;

    float va[8], vw[8];

    auto GLOAD = [&](int k0) {
        float4 a0 = *(const float4*)(ap + k0);
        float4 a1 = *(const float4*)(ap + k0 + 4);
        float4 w0 = *(const float4*)(wp + k0);
        float4 w1 = *(const float4*)(wp + k0 + 4);
        if (MULR) {
            float4 r0 = *(const float4*)(rp + k0);
            float4 r1 = *(const float4*)(rp + k0 + 4);
            a0.x *= r0.x; a0.y *= r0.y; a0.z *= r0.z; a0.w *= r0.w;
            a1.x *= r1.x; a1.y *= r1.y; a1.z *= r1.z; a1.w *= r1.w;
        }
        va[0] = a0.x; va[1] = a0.y; va[2] = a0.z; va[3] = a0.w;
        va[4] = a1.x; va[5] = a1.y; va[6] = a1.z; va[7] = a1.w;
        vw[0] = w0.x; vw[1] = w0.y; vw[2] = w0.z; vw[3] = w0.w;
        vw[4] = w1.x; vw[5] = w1.y; vw[6] = w1.z; vw[7] = w1.w;
    };

    auto STS = [&](int s) {
        #pragma unroll
        for (int i = 0; i < 8; i++) {
            uint32_t ha = tf32r(va[i]);
            sb->Ah[s][lk + i][lr] = ha;
            sb->Al[s][lk + i][lr] = tf32r(va[i] - __uint_as_float(ha));
            uint32_t hw = tf32r(vw[i]);
            sb->Wh[s][lk + i][lr] = hw;
            sb->Wl[s][lk + i][lr] = tf32r(vw[i] - __uint_as_float(hw));
        }
    };

    auto COMP = [&](int s) {
        #pragma unroll
        for (int ks = 0; ks < 2; ks++) {
            const int kk = ks << 3;
            uint32_t ah[2][4], al[2][4], bh[4][2], bl[4][2];
            #pragma unroll
            for (int i = 0; i < 2; i++) {
                int m0 = mb + i * 16 + g;
                ah[i][0] = sb->Ah[s][kk + t][m0];     ah[i][1] = sb->Ah[s][kk + t][m0 + 8];
                ah[i][2] = sb->Ah[s][kk + t + 4][m0]; ah[i][3] = sb->Ah[s][kk + t + 4][m0 + 8];
                al[i][0] = sb->Al[s][kk + t][m0];     al[i][1] = sb->Al[s][kk + t][m0 + 8];
                al[i][2] = sb->Al[s][kk + t + 4][m0]; al[i][3] = sb->Al[s][kk + t + 4][m0 + 8];
            }
            #pragma unroll
            for (int j = 0; j < 4; j++) {
                int n0 = nb + j * 8 + g;
                bh[j][0] = sb->Wh[s][kk + t][n0]; bh[j][1] = sb->Wh[s][kk + t + 4][n0];
                bl[j][0] = sb->Wl[s][kk + t][n0]; bl[j][1] = sb->Wl[s][kk + t + 4][n0];
            }
            #pragma unroll
            for (int i = 0; i < 2; i++)
                #pragma unroll
                for (int j = 0; j < 4; j++) {
                    mma8(acc[i][j], ah[i], bh[j]);
                    mma8(acc[i][j], al[i], bh[j]);
                    mma8(acc[i][j], ah[i], bl[j]);
                }
        }
    };

    GLOAD(0);
    STS(0);
    __syncthreads();
    #pragma unroll 1
    for (int it = 1; it < DD / 16; it++) {
        GLOAD(it * 16);
        COMP((it - 1) & 1);
        STS(it & 1);
        __syncthreads();
    }
    COMP((DD / 16 - 1) & 1);
    __syncthreads();   // safe reuse of smem on next call
}

#define ZACC(acc) \
    _Pragma("unroll") for (int _i = 0; _i < 2; _i++) \
    _Pragma("unroll") for (int _j = 0; _j < 4; _j++) \
    _Pragma("unroll") for (int _e = 0; _e < 4; _e++) acc[_i][_j][_e] = 0.f;

#define EPI_SETUP() \
    const int lane_ = threadIdx.x & 31; \
    const int ge_ = lane_ >> 2, te_ = lane_ & 3; \
    const int we_ = threadIdx.x >> 5; \
    const int wm_ = we_ >> 1, wn_ = we_ & 1;

// ---------------- generic NT GEMM (+bias) ----------------
__global__ __launch_bounds__(128) void mm_big(
    const float* __restrict__ A, int lda,
    const float* __restrict__ W, int ldw, int woff,
    const float* __restrict__ bias,
    float* __restrict__ C, int ldc)
{
    __shared__ SmemBuf sb;
    float acc[2][4][4];
    ZACC(acc);

    mm_core64<false>(&sb, A + (size_t)blockIdx.x * 64 * lda, nullptr, lda,
                     W + (size_t)blockIdx.y * 64 * ldw + woff, ldw, acc);

    EPI_SETUP();
    const int r0 = blockIdx.x * 64 + wm_ * 32 + ge_;
    const int c0 = blockIdx.y * 64 + wn_ * 32 + 2 * te_;
    #pragma unroll
    for (int i = 0; i < 2; i++)
        #pragma unroll
        for (int j = 0; j < 4; j++) {
            int rr = r0 + i * 16;
            int cc = c0 + j * 8;
            float b0 = bias ? bias[cc] : 0.f;
            float b1 = bias ? bias[cc + 1] : 0.f;
            *(float2*)(C + (size_t)rr * ldc + cc) =
                make_float2(acc[i][j][0] + b0, acc[i][j][1] + b1);
            *(float2*)(C + (size_t)(rr + 8) * ldc + cc) =
                make_float2(acc[i][j][2] + b0, acc[i][j][3] + b1);
        }
}

// ---------------- persistent GRU: 200 steps in one launch ----------------
// grid = 96 blocks: gate = blk/32 (r,z,n), tile = blk%32 -> m (0..3), n (0..7)
#define GRU_GRID 96
__global__ __launch_bounds__(128) void gru_persist(
    const float* __restrict__ zero,
    const float* __restrict__ whh,     // [3D,D]
    const float* __restrict__ bhh,     // [3D]
    const float* __restrict__ xproj,   // [B,L,3D] (+bih)
    float* __restrict__ sseq,          // [L,B,D]
    float* __restrict__ hp)            // [B,3D]
{
    __shared__ SmemBuf sb;
    const int blk  = blockIdx.x;
    const int gate = blk >> 5;
    const int tt   = blk & 31;
    const int m    = tt >> 3;
    const int n    = tt & 7;
    const int gtid = blk * 128 + threadIdx.x;

    EPI_SETUP();
    const int r0 = m * 64 + wm_ * 32 + ge_;
    const int c0 = n * 64 + wn_ * 32 + 2 * te_;
    const float* Wg = whh + (size_t)(gate * DD + n * 64) * DD;

    for (int l = 0; l < LL; l++) {
        const float* hprev = l ? sseq + (size_t)(l - 1) * BB * DD : zero;

        float acc[2][4][4];
        ZACC(acc);
        mm_core64<false>(&sb, hprev + (size_t)m * 64 * DD, nullptr, DD, Wg, DD, acc);

        // write gate preactivation (+bhh) into hp[b, gate*D + c]
        #pragma unroll
        for (int i = 0; i < 2; i++)
            #pragma unroll
            for (int j = 0; j < 4; j++) {
                int cc = c0 + j * 8;
                float b0 = bhh[gate * DD + cc];
                float b1 = bhh[gate * DD + cc + 1];
                int rr = r0 + i * 16;
                *(float2*)(hp + (size_t)rr * 3 * DD + gate * DD + cc) =
                    make_float2(acc[i][j][0] + b0, acc[i][j][1] + b1);
                *(float2*)(hp + (size_t)(rr + 8) * 3 * DD + gate * DD + cc) =
                    make_float2(acc[i][j][2] + b0, acc[i][j][3] + b1);
            }

        grid_barrier(GRU_GRID);

        // fused gating over all elements
        float* hl = sseq + (size_t)l * BB * DD;
        for (int e = gtid; e < BB * DD; e += GRU_GRID * 128) {
            int b = e >> 9, d = e & (DD - 1);
            const float* xr = xproj + ((size_t)b * LL + l) * 3 * DD;
            const float* hr = hp + (size_t)b * 3 * DD;
            float r  = sigf(xr[d] + hr[d]);
            float z  = sigf(xr[DD + d] + hr[DD + d]);
            float nn = tanhf(xr[2 * DD + d] + r * hr[2 * DD + d]);
            float h0 = hprev[e];
            hl[e] = (1.f - z) * nn + z * h0;
        }

        grid_barrier(GRU_GRID);
    }
}

// ---------------- persistent AUGRU: 200 steps in one launch ----------------
// phase A (blocks 0..63): gate = blk/32 (r,u), 64x64 tiles over [256,512]
// phase B (blocks 0..31): hhat + output update, 64x64 tiles over [256,512]
__global__ __launch_bounds__(128) void augru_persist(
    const float* __restrict__ h_init,   // sseq[L-1]
    const float* __restrict__ reset_w,  // [D,2D] (h-half at col 0)
    const float* __restrict__ update_w,
    const float* __restrict__ hhat_w,
    const float* __restrict__ rx,       // [L,B,D] (+bias)
    const float* __restrict__ ux,
    const float* __restrict__ nx,
    const float* __restrict__ att,      // [L,B]
    float* __restrict__ hb,             // ping-pong [2,B,D]
    float* __restrict__ rbuf,
    float* __restrict__ uebuf,
    float* __restrict__ out)
{
    __shared__ SmemBuf sb;
    const int blk = blockIdx.x;
    EPI_SETUP();

    for (int l = 0; l < LL; l++) {
        const float* hc = (l == 0) ? h_init : hb + (size_t)(l & 1) * BB * DD;
        float* ho = (l == LL - 1) ? out : hb + (size_t)((l + 1) & 1) * BB * DD;

        if (blk < 64) {
            const int gate = blk >> 5;
            const int tt = blk & 31;
            const int m = tt >> 3, n = tt & 7;
            const float* W = gate ? update_w : reset_w;
            const float* X = (gate ? ux : rx) + (size_t)l * BB * DD;

            float acc[2][4][4];
            ZACC(acc);
            mm_core64<false>(&sb, hc + (size_t)m * 64 * DD, nullptr, DD,
                             W + (size_t)(n * 64) * (2 * DD), 2 * DD, acc);

            const int r0 = m * 64 + wm_ * 32 + ge_;
            const int c0 = n * 64 + wn_ * 32 + 2 * te_;
            #pragma unroll
            for (int i = 0; i < 2; i++)
                #pragma unroll
                for (int j = 0; j < 4; j++) {
                    int cc = c0 + j * 8;
                    #pragma unroll
                    for (int half = 0; half < 2; half++) {
                        int rr = r0 + i * 16 + half * 8;
                        size_t idx = (size_t)rr * DD + cc;
                        float v0 = acc[i][j][half * 2 + 0] + X[idx];
                        float v1 = acc[i][j][half * 2 + 1] + X[idx + 1];
                        if (gate == 0) {
                            *(float2*)(rbuf + idx) = make_float2(sigf(v0), sigf(v1));
                        } else {
                            float a = att[(size_t)l * BB + rr];
                            *(float2*)(uebuf + idx) = make_float2(a * sigf(v0), a * sigf(v1));
                        }
                    }
                }
        }

        grid_barrier(GRU_GRID);

        if (blk < 32) {
            const int m = blk >> 3, n = blk & 7;
            const float* X = nx + (size_t)l * BB * DD;

            float acc[2][4][4];
            ZACC(acc);
            mm_core64<true>(&sb, hc + (size_t)m * 64 * DD,
                            rbuf + (size_t)m * 64 * DD, DD,
                            hhat_w + (size_t)(n * 64) * (2 * DD), 2 * DD, acc);

            const int r0 = m * 64 + wm_ * 32 + ge_;
            const int c0 = n * 64 + wn_ * 32 + 2 * te_;
            #pragma unroll
            for (int i = 0; i < 2; i++)
                #pragma unroll
                for (int j = 0; j < 4; j++) {
                    int cc = c0 + j * 8;
                    #pragma unroll
                    for (int half = 0; half < 2; half++) {
                        int rr = r0 + i * 16 + half * 8;
                        size_t idx = (size_t)rr * DD + cc;
                        float hh0 = tanhf(acc[i][j][half * 2 + 0] + X[idx]);
                        float hh1 = tanhf(acc[i][j][half * 2 + 1] + X[idx + 1]);
                        float ue0 = uebuf[idx], ue1 = uebuf[idx + 1];
                        float h0 = hc[idx], h1 = hc[idx + 1];
                        *(float2*)(ho + idx) =
                            make_float2(h0 + ue0 * (hh0 - h0), h1 + ue1 * (hh1 - h1));
                    }
                }
        }

        grid_barrier(GRU_GRID);
    }
}

// ---------------- attention ----------------
__global__ void attn_logits(const float* __restrict__ s,   // [L,B,D]
                            const float* __restrict__ u,   // [B,D]
                            float* __restrict__ logits)    // [L,B]
{
    int gw = (blockIdx.x * blockDim.x + threadIdx.x) >> 5;
    int lane = threadIdx.x & 31;
    int b = gw & (BB - 1);
    const float4* sr = (const float4*)(s + (size_t)gw * DD);
    const float4* ur = (const float4*)(u + (size_t)b * DD);
    float acc = 0.f;
    #pragma unroll
    for (int k = lane; k < DD / 4; k += 32) {
        float4 a = sr[k], c = ur[k];
        acc += a.x * c.x + a.y * c.y + a.z * c.z + a.w * c.w;
    }
    #pragma unroll
    for (int o = 16; o > 0; o >>= 1) acc += __shfl_xor_sync(0xffffffffu, acc, o);
    if (lane == 0) logits[gw] = acc;
}

__global__ void attn_softmax(const float* __restrict__ logits, float* __restrict__ att)
{
    int b = blockIdx.x, t = threadIdx.x;
    __shared__ float red[256];
    float v = (t < LL) ? logits[t * BB + b] : -1e30f;
    red[t] = v;
    __syncthreads();
    for (int s = 128; s > 0; s >>= 1) {
        if (t < s) red[t] = fmaxf(red[t], red[t + s]);
        __syncthreads();
    }
    float mx = red[0];
    __syncthreads();
    float e = (t < LL) ? expf(v - mx) : 0.f;
    red[t] = e;
    __syncthreads();
    for (int s = 128; s > 0; s >>= 1) {
        if (t < s) red[t] += red[t + s];
        __syncthreads();
    }
    float inv = 1.f / red[0];
    if (t < LL) att[t * BB + b] = e * inv;
}

__global__ void zero_kernel(float* __restrict__ p, int n)
{
    int i = blockIdx.x * blockDim.x + threadIdx.x;
    if (i < n) p[i] = 0.f;
}

// ---------------- host ----------------
extern "C" void kernel_launch(void* const* d_in, const int* in_sizes, int n_in,
                              void* d_out, int out_size)
{
    const float* session  = (const float*)d_in[0];
    const float* target   = (const float*)d_in[1];
    const float* w        = (const float*)d_in[2];
    const float* wih      = (const float*)d_in[3];
    const float* whh      = (const float*)d_in[4];
    const float* bih      = (const float*)d_in[5];
    const float* bhh      = (const float*)d_in[6];
    const float* reset_w  = (const float*)d_in[7];
    const float* reset_b  = (const float*)d_in[8];
    const float* update_w = (const float*)d_in[9];
    const float* update_b = (const float*)d_in[10];
    const float* hhat_w   = (const float*)d_in[11];
    const float* hhat_b   = (const float*)d_in[12];
    float* out = (float*)d_out;

    float *xproj, *sseq, *rx, *ux, *nx, *u, *logits, *att, *rbuf, *uebuf, *hb, *hp, *zero;
    cudaGetSymbolAddress((void**)&xproj, g_xproj);
    cudaGetSymbolAddress((void**)&sseq,  g_sseq);
    cudaGetSymbolAddress((void**)&rx,    g_rx);
    cudaGetSymbolAddress((void**)&ux,    g_ux);
    cudaGetSymbolAddress((void**)&nx,    g_nx);
    cudaGetSymbolAddress((void**)&u,     g_u);
    cudaGetSymbolAddress((void**)&logits,g_logits);
    cudaGetSymbolAddress((void**)&att,   g_att);
    cudaGetSymbolAddress((void**)&rbuf,  g_r);
    cudaGetSymbolAddress((void**)&uebuf, g_ue);
    cudaGetSymbolAddress((void**)&hb,    g_h);
    cudaGetSymbolAddress((void**)&hp,    g_hp);
    cudaGetSymbolAddress((void**)&zero,  g_zero);

    zero_kernel<<<(BB * DD + 255) / 256, 256>>>(zero, BB * DD);

    // 1) x_proj[B,L,3D] = session @ Wih^T + bih
    {
        dim3 g(BB * LL / 64, 3 * DD / 64);
        mm_big<<<g, 128>>>(session, DD, wih, DD, 0, bih, xproj, 3 * DD);
    }

    // 2) persistent GRU (one launch, 200 steps)
    gru_persist<<<GRU_GRID, 128>>>(zero, whh, bhh, xproj, sseq, hp);

    // 3) u[b,:] = w @ target[b]
    {
        dim3 g(BB / 64, DD / 64);
        mm_big<<<g, 128>>>(target, DD, w, DD, 0, nullptr, u, DD);
    }

    // 4) AUGRU x-projections (x = s_seq), biases folded (x-half: woff = DD)
    {
        dim3 g(BB * LL / 64, DD / 64);
        mm_big<<<g, 128>>>(sseq, DD, reset_w,  2 * DD, DD, reset_b,  rx, DD);
        mm_big<<<g, 128>>>(sseq, DD, update_w, 2 * DD, DD, update_b, ux, DD);
        mm_big<<<g, 128>>>(sseq, DD, hhat_w,   2 * DD, DD, hhat_b,   nx, DD);
    }

    // 5) attention
    attn_logits<<<LL * BB / 8, 256>>>(sseq, u, logits);
    attn_softmax<<<BB, 256>>>(logits, att);

    // 6) persistent AUGRU (one launch, 200 steps); init h = s_seq[L-1]
    augru_persist<<<GRU_GRID, 128>>>(sseq + (size_t)(LL - 1) * BB * DD,
                                     reset_w, update_w, hhat_w,
                                     rx, ux, nx, att,
                                     hb, rbuf, uebuf, out);
}

// round 6
// speedup vs baseline: 1.0975x; 1.0975x over previous
#include <cuda_runtime.h>
#include <cuda_bf16.h>
#include <math.h>
#include <stdint.h>

#define BB 256
#define LL 200
#define DD 512
typedef uint32_t u32;

// ---------------- fp32 scratch ----------------
__device__ float g_xproj[(size_t)BB * LL * 3 * DD];   // [B,L,3D] (+bih)
__device__ float g_sseq [(size_t)LL * BB * DD];       // [L,B,D]
__device__ float g_rx   [(size_t)LL * BB * DD];
__device__ float g_ux   [(size_t)LL * BB * DD];
__device__ float g_nx   [(size_t)LL * BB * DD];
__device__ float g_u    [BB * DD];
__device__ float g_logits[LL * BB];
__device__ float g_att   [LL * BB];
__device__ float g_ue    [BB * DD];
__device__ float g_hf    [2 * BB * DD];
__device__ float g_hp    [BB * 3 * DD];
__device__ float g_zero  [BB * DD];                   // fp32 zeros == packed zeros

// ---------------- packed (bf16-pair) activations ----------------
__device__ u32 g_Psess[(size_t)BB * LL * DD];
__device__ u32 g_Ptar [BB * DD];
__device__ u32 g_Psseq[(size_t)LL * BB * DD];
__device__ u32 g_Phr  [BB * DD];
__device__ u32 g_Pp   [2 * BB * DD];

// ---------------- weight fragments (B-operand order) ----------------
__device__ u32 g_Fwih[1536 * DD];
__device__ u32 g_Fwhh[1536 * DD];
__device__ u32 g_Fw  [DD * DD];
__device__ u32 g_Frh [DD * DD];
__device__ u32 g_Fuh [DD * DD];
__device__ u32 g_Fhh [DD * DD];
__device__ u32 g_Frx [DD * DD];
__device__ u32 g_Fux [DD * DD];
__device__ u32 g_Fhx [DD * DD];

// grid barrier
__device__ unsigned int          g_cnt = 0;
__device__ volatile unsigned int g_gen = 0;

__device__ __forceinline__ float sigf(float x) { return 1.0f / (1.0f + __expf(-x)); }

__device__ __forceinline__ u32 packbf(float x) {
    __nv_bfloat16 hi = __float2bfloat16(x);
    float hf = __bfloat162float(hi);
    __nv_bfloat16 lo = __float2bfloat16(x - hf);
    return (u32)__bfloat16_as_ushort(hi) | ((u32)__bfloat16_as_ushort(lo) << 16);
}

__device__ __forceinline__ void grid_barrier(int nb) {
    __syncthreads();
    if (threadIdx.x == 0) {
        __threadfence();
        unsigned int gen = g_gen;
        unsigned int old = atomicAdd(&g_cnt, 1u);
        if (old == (unsigned)(nb - 1)) {
            atomicExch(&g_cnt, 0u);
            __threadfence();
            atomicAdd((unsigned int*)&g_gen, 1u);
        } else {
            while (g_gen == gen) { }
        }
        __threadfence();
    }
    __syncthreads();
}

__device__ __forceinline__ void mma16(float* d, const u32* a, u32 b0, u32 b1) {
    asm volatile(
        "mma.sync.aligned.m16n8k16.row.col.f32.bf16.bf16.f32 "
        "{%0,%1,%2,%3},{%4,%5,%6,%7},{%8,%9},{%0,%1,%2,%3};"
        : "+f"(d[0]), "+f"(d[1]), "+f"(d[2]), "+f"(d[3])
        : "r"(a[0]), "r"(a[1]), "r"(a[2]), "r"(a[3]), "r"(b0), "r"(b1));
}

// smem: A tile, [ok 0..15][row 0..127], plane stride 136 (conflict-free), double-buffered
struct MMSmem { u32 A[2][16][136]; };

#define ZACC(acc) \
    _Pragma("unroll") for (int _i = 0; _i < 2; _i++) \
    _Pragma("unroll") for (int _j = 0; _j < 4; _j++) \
    _Pragma("unroll") for (int _e = 0; _e < 4; _e++) acc[_i][_j][_e] = 0.f;

// ==================== 128x64 x K=512 double-bf16 core, 256 threads ====================
// Each packed word = (hi, lo). Two mmas per A-fragment:
//   normal A:     hi_a*hi_b + lo_a*lo_b
//   swapped A:    lo_a*hi_b + hi_a*lo_b      (16-bit rotate)
// Sum = exact (hi_a+lo_a)*(hi_b+lo_b).
__device__ __forceinline__ void mm_core(
    MMSmem* sm, const u32* __restrict__ Ap,
    const u32* __restrict__ F, int gnt0,
    float acc[2][4][4])
{
    const int tid  = threadIdx.x;
    const int lane = tid & 31;
    const int gq = lane >> 2, tq = lane & 3;
    const int w  = tid >> 5;
    const int wm = w >> 1, wn = w & 1;
    const int r  = tid >> 1, h = tid & 1;

    const u32* arow = Ap + (size_t)r * DD + h * 8;

    uint4 bv[4], nbv[4], na0, na1;

    // prime: A chunk 0 + B chunk 0
    uint4 va0 = *(const uint4*)(arow + 0);
    uint4 va1 = *(const uint4*)(arow + 4);
    #pragma unroll
    for (int nt = 0; nt < 4; nt++) {
        int gnt = gnt0 + wn * 4 + nt;
        bv[nt] = *(const uint4*)(F + (((size_t)gnt * 32 + 0) * 32 + lane) * 4);
    }

    {   // STS chunk 0 (j-rotation for conflict-free banks)
        u32 e0[4] = {va0.x, va0.y, va0.z, va0.w};
        u32 e1[4] = {va1.x, va1.y, va1.z, va1.w};
        #pragma unroll
        for (int j = 0; j < 4; j++) {
            int jj = (j + 2 * h) & 3;
            sm->A[0][h * 8 + 0 + jj][r] = e0[jj];
            sm->A[0][h * 8 + 4 + jj][r] = e1[jj];
        }
    }
    __syncthreads();

    #pragma unroll 1
    for (int s2 = 0; s2 < 32; s2++) {
        const int buf = s2 & 1;
        if (s2 < 31) {
            const u32* ar = arow + (s2 + 1) * 16;
            na0 = *(const uint4*)(ar);
            na1 = *(const uint4*)(ar + 4);
            #pragma unroll
            for (int nt = 0; nt < 4; nt++) {
                int gnt = gnt0 + wn * 4 + nt;
                nbv[nt] = *(const uint4*)(F + (((size_t)gnt * 32 + (s2 + 1)) * 32 + lane) * 4);
            }
        }
        #pragma unroll
        for (int sl = 0; sl < 2; sl++) {
            u32 a[2][4], as[2][4];
            #pragma unroll
            for (int mt = 0; mt < 2; mt++) {
                int rb = wm * 32 + mt * 16 + gq;
                a[mt][0] = sm->A[buf][sl * 8 + tq][rb];
                a[mt][1] = sm->A[buf][sl * 8 + tq][rb + 8];
                a[mt][2] = sm->A[buf][sl * 8 + tq + 4][rb];
                a[mt][3] = sm->A[buf][sl * 8 + tq + 4][rb + 8];
                #pragma unroll
                for (int q = 0; q < 4; q++)
                    as[mt][q] = __funnelshift_l(a[mt][q], a[mt][q], 16);
            }
            #pragma unroll
            for (int nt = 0; nt < 4; nt++) {
                u32 b0 = sl ? bv[nt].z : bv[nt].x;
                u32 b1 = sl ? bv[nt].w : bv[nt].y;
                #pragma unroll
                for (int mt = 0; mt < 2; mt++) {
                    mma16(acc[mt][nt], a[mt],  b0, b1);   // hi*hi + lo*lo
                    mma16(acc[mt][nt], as[mt], b0, b1);   // lo*hi + hi*lo
                }
            }
        }
        if (s2 < 31) {
            u32 e0[4] = {na0.x, na0.y, na0.z, na0.w};
            u32 e1[4] = {na1.x, na1.y, na1.z, na1.w};
            #pragma unroll
            for (int j = 0; j < 4; j++) {
                int jj = (j + 2 * h) & 3;
                sm->A[buf ^ 1][h * 8 + 0 + jj][r] = e0[jj];
                sm->A[buf ^ 1][h * 8 + 4 + jj][r] = e1[jj];
            }
            #pragma unroll
            for (int nt = 0; nt < 4; nt++) bv[nt] = nbv[nt];
        }
        __syncthreads();
    }
}

#define EPI_VARS() \
    const int lane_ = threadIdx.x & 31; \
    const int gq_ = lane_ >> 2, tq_ = lane_ & 3; \
    const int w_ = threadIdx.x >> 5; \
    const int wm_ = w_ >> 1, wn_ = w_ & 1;

// ---------------- generic GEMM (+bias), C[row][col] fp32 ----------------
__global__ __launch_bounds__(256) void mm_big(
    const u32* __restrict__ Ap,
    const u32* __restrict__ F,
    const float* __restrict__ bias,
    float* __restrict__ C, int ldc)
{
    __shared__ MMSmem sm;
    const int bm = blockIdx.x * 128, bn = blockIdx.y * 64;
    float acc[2][4][4];
    ZACC(acc);
    mm_core(&sm, Ap + (size_t)bm * DD, F, bn >> 3, acc);

    EPI_VARS();
    #pragma unroll
    for (int mt = 0; mt < 2; mt++)
        #pragma unroll
        for (int nt = 0; nt < 4; nt++) {
            int row = bm + wm_ * 32 + mt * 16 + gq_;
            int col = bn + wn_ * 32 + nt * 8 + 2 * tq_;
            float b0 = bias ? bias[col] : 0.f;
            float b1 = bias ? bias[col + 1] : 0.f;
            *(float2*)(C + (size_t)row * ldc + col) =
                make_float2(acc[mt][nt][0] + b0, acc[mt][nt][1] + b1);
            *(float2*)(C + (size_t)(row + 8) * ldc + col) =
                make_float2(acc[mt][nt][2] + b0, acc[mt][nt][3] + b1);
        }
}

// ---------------- persistent GRU ----------------
#define GRUB 48
__global__ __launch_bounds__(256) void gru_persist(
    const float* __restrict__ zero, const u32* __restrict__ Pzero,
    const u32* __restrict__ Fwhh, const float* __restrict__ bhh,
    const float* __restrict__ xproj,
    float* __restrict__ sseq, u32* __restrict__ Psseq,
    float* __restrict__ hp)
{
    __shared__ MMSmem sm;
    const int blk = blockIdx.x;
    const int mi = blk / 24, ni = blk % 24;
    const int bm = mi * 128, bn = ni * 64;
    const int gtid = blk * 256 + threadIdx.x;
    EPI_VARS();

    for (int l = 0; l < LL; l++) {
        const u32* Ap = l ? (Psseq + (size_t)(l - 1) * BB * DD) : Pzero;
        float acc[2][4][4];
        ZACC(acc);
        mm_core(&sm, Ap + (size_t)bm * DD, Fwhh, bn >> 3, acc);

        #pragma unroll
        for (int mt = 0; mt < 2; mt++)
            #pragma unroll
            for (int nt = 0; nt < 4; nt++) {
                int row = bm + wm_ * 32 + mt * 16 + gq_;
                int col = bn + wn_ * 32 + nt * 8 + 2 * tq_;
                float b0 = bhh[col], b1 = bhh[col + 1];
                *(float2*)(hp + (size_t)row * 1536 + col) =
                    make_float2(acc[mt][nt][0] + b0, acc[mt][nt][1] + b1);
                *(float2*)(hp + (size_t)(row + 8) * 1536 + col) =
                    make_float2(acc[mt][nt][2] + b0, acc[mt][nt][3] + b1);
            }

        grid_barrier(GRUB);

        const float* hprev = l ? (sseq + (size_t)(l - 1) * BB * DD) : zero;
        float* sl_ = sseq + (size_t)l * BB * DD;
        u32* pl = Psseq + (size_t)l * BB * DD;
        for (int e = gtid; e < BB * DD; e += GRUB * 256) {
            int b = e >> 9, d = e & (DD - 1);
            const float* xr = xproj + ((size_t)b * LL + l) * 1536;
            const float* hr = hp + (size_t)b * 1536;
            float rr = sigf(xr[d] + hr[d]);
            float zz = sigf(xr[512 + d] + hr[512 + d]);
            float nn = tanhf(xr[1024 + d] + rr * hr[1024 + d]);
            float h0 = hprev[e];
            float hn = (1.f - zz) * nn + zz * h0;
            sl_[e] = hn;
            pl[e] = packbf(hn);
        }

        grid_barrier(GRUB);
    }
}

// ---------------- persistent AUGRU ----------------
#define AUB 32
__global__ __launch_bounds__(256) void augru_persist(
    const float* __restrict__ hf_init, const u32* __restrict__ Pinit,
    const u32* __restrict__ Frh, const u32* __restrict__ Fuh, const u32* __restrict__ Fhh,
    const float* __restrict__ rx, const float* __restrict__ ux, const float* __restrict__ nx,
    const float* __restrict__ att,
    float* __restrict__ hf, u32* __restrict__ Pp,
    u32* __restrict__ Phr, float* __restrict__ ue,
    float* __restrict__ out)
{
    __shared__ MMSmem sm;
    const int blk = blockIdx.x;
    EPI_VARS();

    for (int l = 0; l < LL; l++) {
        const float* hc = l ? hf + (size_t)(l & 1) * BB * DD : hf_init;
        const u32* Pc = l ? Pp + (size_t)(l & 1) * BB * DD : Pinit;

        {   // phase A
            const int gate = blk >> 4, mi = (blk >> 3) & 1, ni = blk & 7;
            const int bm = mi * 128, bn = ni * 64;
            const u32* F = gate ? Fuh : Frh;
            const float* X = (gate ? ux : rx) + (size_t)l * BB * DD;
            float acc[2][4][4];
            ZACC(acc);
            mm_core(&sm, Pc + (size_t)bm * DD, F, bn >> 3, acc);

            #pragma unroll
            for (int mt = 0; mt < 2; mt++)
                #pragma unroll
                for (int nt = 0; nt < 4; nt++) {
                    int col = bn + wn_ * 32 + nt * 8 + 2 * tq_;
                    #pragma unroll
                    for (int half = 0; half < 2; half++) {
                        int row = bm + wm_ * 32 + mt * 16 + gq_ + half * 8;
                        size_t idx = (size_t)row * DD + col;
                        float v0 = acc[mt][nt][half * 2 + 0] + X[idx];
                        float v1 = acc[mt][nt][half * 2 + 1] + X[idx + 1];
                        if (gate == 0) {
                            Phr[idx]     = packbf(hc[idx] * sigf(v0));
                            Phr[idx + 1] = packbf(hc[idx + 1] * sigf(v1));
                        } else {
                            float a = att[(size_t)l * BB + row];
                            ue[idx]     = a * sigf(v0);
                            ue[idx + 1] = a * sigf(v1);
                        }
                    }
                }
        }

        grid_barrier(AUB);

        if (blk < 16) {   // phase B
            const int mi = blk >> 3, ni = blk & 7;
            const int bm = mi * 128, bn = ni * 64;
            const float* X = nx + (size_t)l * BB * DD;
            float acc[2][4][4];
            ZACC(acc);
            mm_core(&sm, Phr + (size_t)bm * DD, Fhh, bn >> 3, acc);

            float* ho = (l == LL - 1) ? out : hf + (size_t)((l + 1) & 1) * BB * DD;
            u32* Pn = Pp + (size_t)((l + 1) & 1) * BB * DD;
            #pragma unroll
            for (int mt = 0; mt < 2; mt++)
                #pragma unroll
                for (int nt = 0; nt < 4; nt++) {
                    int col = bn + wn_ * 32 + nt * 8 + 2 * tq_;
                    #pragma unroll
                    for (int half = 0; half < 2; half++) {
                        int row = bm + wm_ * 32 + mt * 16 + gq_ + half * 8;
                        size_t idx = (size_t)row * DD + col;
                        float hh0 = tanhf(acc[mt][nt][half * 2 + 0] + X[idx]);
                        float hh1 = tanhf(acc[mt][nt][half * 2 + 1] + X[idx + 1]);
                        float h0 = hc[idx], h1 = hc[idx + 1];
                        float u0 = ue[idx], u1 = ue[idx + 1];
                        float n0 = h0 + u0 * (hh0 - h0);
                        float n1 = h1 + u1 * (hh1 - h1);
                        ho[idx] = n0;  ho[idx + 1] = n1;
                        Pn[idx] = packbf(n0);  Pn[idx + 1] = packbf(n1);
                    }
                }
        }

        grid_barrier(AUB);
    }
}

// ---------------- conversion kernels ----------------
__global__ void pack_kernel(const float* __restrict__ x, u32* __restrict__ p, int n4)
{
    int i = blockIdx.x * 256 + threadIdx.x;
    if (i < n4) {
        float4 v = ((const float4*)x)[i];
        uint4 o;
        o.x = packbf(v.x); o.y = packbf(v.y); o.z = packbf(v.z); o.w = packbf(v.w);
        ((uint4*)p)[i] = o;
    }
}

__global__ void wfrag_kernel(const float* __restrict__ W, int ldw, int woff,
                             u32* __restrict__ F, int total)
{
    int idx = blockIdx.x * 256 + threadIdx.x;
    if (idx >= total) return;
    int j = idx & 3, lane = (idx >> 2) & 31, s2 = (idx >> 7) & 31, gnt = idx >> 12;
    int g = lane >> 2, t = lane & 3;
    int sl = s2 * 2 + (j >> 1), b = j & 1;
    int ok = sl * 8 + t + 4 * b;
    int n = gnt * 8 + g;
    F[idx] = packbf(W[(size_t)n * ldw + woff + ok]);
}

// ---------------- attention ----------------
__global__ void attn_logits(const float* __restrict__ s, const float* __restrict__ u,
                            float* __restrict__ logits)
{
    int gw = (blockIdx.x * blockDim.x + threadIdx.x) >> 5;
    int lane = threadIdx.x & 31;
    int b = gw & (BB - 1);
    const float4* sr = (const float4*)(s + (size_t)gw * DD);
    const float4* ur = (const float4*)(u + (size_t)b * DD);
    float acc = 0.f;
    #pragma unroll
    for (int k = lane; k < DD / 4; k += 32) {
        float4 a = sr[k], c = ur[k];
        acc += a.x * c.x + a.y * c.y + a.z * c.z + a.w * c.w;
    }
    #pragma unroll
    for (int o = 16; o > 0; o >>= 1) acc += __shfl_xor_sync(0xffffffffu, acc, o);
    if (lane == 0) logits[gw] = acc;
}

__global__ void attn_softmax(const float* __restrict__ logits, float* __restrict__ att)
{
    int b = blockIdx.x, t = threadIdx.x;
    __shared__ float red[256];
    float v = (t < LL) ? logits[t * BB + b] : -1e30f;
    red[t] = v;
    __syncthreads();
    for (int s = 128; s > 0; s >>= 1) {
        if (t < s) red[t] = fmaxf(red[t], red[t + s]);
        __syncthreads();
    }
    float mx = red[0];
    __syncthreads();
    float e = (t < LL) ? expf(v - mx) : 0.f;
    red[t] = e;
    __syncthreads();
    for (int s = 128; s > 0; s >>= 1) {
        if (t < s) red[t] += red[t + s];
        __syncthreads();
    }
    float inv = 1.f / red[0];
    if (t < LL) att[t * BB + b] = e * inv;
}

__global__ void zero_kernel(float* __restrict__ p, int n)
{
    int i = blockIdx.x * blockDim.x + threadIdx.x;
    if (i < n) p[i] = 0.f;
}

// ---------------- host ----------------
extern "C" void kernel_launch(void* const* d_in, const int* in_sizes, int n_in,
                              void* d_out, int out_size)
{
    const float* session  = (const float*)d_in[0];
    const float* target   = (const float*)d_in[1];
    const float* w        = (const float*)d_in[2];
    const float* wih      = (const float*)d_in[3];
    const float* whh      = (const float*)d_in[4];
    const float* bih      = (const float*)d_in[5];
    const float* bhh      = (const float*)d_in[6];
    const float* reset_w  = (const float*)d_in[7];
    const float* reset_b  = (const float*)d_in[8];
    const float* update_w = (const float*)d_in[9];
    const float* update_b = (const float*)d_in[10];
    const float* hhat_w   = (const float*)d_in[11];
    const float* hhat_b   = (const float*)d_in[12];
    float* out = (float*)d_out;

    float *xproj, *sseq, *rx, *ux, *nx, *u, *logits, *att, *ue, *hf, *hp, *zero;
    u32 *Psess, *Ptar, *Psseq, *Phr, *Pp;
    u32 *Fwih, *Fwhh, *Fw, *Frh, *Fuh, *Fhh, *Frx, *Fux, *Fhx;

    cudaGetSymbolAddress((void**)&xproj,  g_xproj);
    cudaGetSymbolAddress((void**)&sseq,   g_sseq);
    cudaGetSymbolAddress((void**)&rx,     g_rx);
    cudaGetSymbolAddress((void**)&ux,     g_ux);
    cudaGetSymbolAddress((void**)&nx,     g_nx);
    cudaGetSymbolAddress((void**)&u,      g_u);
    cudaGetSymbolAddress((void**)&logits, g_logits);
    cudaGetSymbolAddress((void**)&att,    g_att);
    cudaGetSymbolAddress((void**)&ue,     g_ue);
    cudaGetSymbolAddress((void**)&hf,     g_hf);
    cudaGetSymbolAddress((void**)&hp,     g_hp);
    cudaGetSymbolAddress((void**)&zero,   g_zero);
    cudaGetSymbolAddress((void**)&Psess,  g_Psess);
    cudaGetSymbolAddress((void**)&Ptar,   g_Ptar);
    cudaGetSymbolAddress((void**)&Psseq,  g_Psseq);
    cudaGetSymbolAddress((void**)&Phr,    g_Phr);
    cudaGetSymbolAddress((void**)&Pp,     g_Pp);
    cudaGetSymbolAddress((void**)&Fwih,   g_Fwih);
    cudaGetSymbolAddress((void**)&Fwhh,   g_Fwhh);
    cudaGetSymbolAddress((void**)&Fw,     g_Fw);
    cudaGetSymbolAddress((void**)&Frh,    g_Frh);
    cudaGetSymbolAddress((void**)&Fuh,    g_Fuh);
    cudaGetSymbolAddress((void**)&Fhh,    g_Fhh);
    cudaGetSymbolAddress((void**)&Frx,    g_Frx);
    cudaGetSymbolAddress((void**)&Fux,    g_Fux);
    cudaGetSymbolAddress((void**)&Fhx,    g_Fhx);

    // zeros (fp32 zero == packed zero)
    zero_kernel<<<(BB * DD + 255) / 256, 256>>>(zero, BB * DD);

    // pack activations
    pack_kernel<<<(BB * LL * DD / 4 + 255) / 256, 256>>>(session, Psess, BB * LL * DD / 4);
    pack_kernel<<<(BB * DD / 4 + 255) / 256, 256>>>(target, Ptar, BB * DD / 4);

    // weight fragments
    wfrag_kernel<<<(1536 * DD + 255) / 256, 256>>>(wih,      DD,      0,  Fwih, 1536 * DD);
    wfrag_kernel<<<(1536 * DD + 255) / 256, 256>>>(whh,      DD,      0,  Fwhh, 1536 * DD);
    wfrag_kernel<<<(DD * DD + 255) / 256, 256>>>(w,          DD,      0,  Fw,   DD * DD);
    wfrag_kernel<<<(DD * DD + 255) / 256, 256>>>(reset_w,    2 * DD,  0,  Frh,  DD * DD);
    wfrag_kernel<<<(DD * DD + 255) / 256, 256>>>(update_w,   2 * DD,  0,  Fuh,  DD * DD);
    wfrag_kernel<<<(DD * DD + 255) / 256, 256>>>(hhat_w,     2 * DD,  0,  Fhh,  DD * DD);
    wfrag_kernel<<<(DD * DD + 255) / 256, 256>>>(reset_w,    2 * DD,  DD, Frx,  DD * DD);
    wfrag_kernel<<<(DD * DD + 255) / 256, 256>>>(update_w,   2 * DD,  DD, Fux,  DD * DD);
    wfrag_kernel<<<(DD * DD + 255) / 256, 256>>>(hhat_w,     2 * DD,  DD, Fhx,  DD * DD);

    // 1) x_proj[B,L,3D] = session @ wih^T + bih
    {
        dim3 g(BB * LL / 128, 3 * DD / 64);
        mm_big<<<g, 256>>>(Psess, Fwih, bih, xproj, 3 * DD);
    }

    // 2) persistent GRU (one launch, 200 steps)
    gru_persist<<<GRUB, 256>>>(zero, (const u32*)zero, Fwhh, bhh, xproj, sseq, Psseq, hp);

    // 3) u = target @ w^T
    {
        dim3 g(BB / 128, DD / 64);
        mm_big<<<g, 256>>>(Ptar, Fw, nullptr, u, DD);
    }

    // 4) AUGRU x-projections
    {
        dim3 g(BB * LL / 128, DD / 64);
        mm_big<<<g, 256>>>(Psseq, Frx, reset_b,  rx, DD);
        mm_big<<<g, 256>>>(Psseq, Fux, update_b, ux, DD);
        mm_big<<<g, 256>>>(Psseq, Fhx, hhat_b,   nx, DD);
    }

    // 5) attention
    attn_logits<<<LL * BB / 8, 256>>>(sseq, u, logits);
    attn_softmax<<<BB, 256>>>(logits, att);

    // 6) persistent AUGRU; init h = sseq[L-1] (fp32 + packed view)
    augru_persist<<<AUB, 256>>>(sseq + (size_t)(LL - 1) * BB * DD,
                                Psseq + (size_t)(LL - 1) * BB * DD,
                                Frh, Fuh, Fhh,
                                rx, ux, nx, att,
                                hf, Pp, Phr, ue, out);
}

// round 7
// speedup vs baseline: 1.5821x; 1.4415x over previous
#include <cuda_runtime.h>
#include <cuda_bf16.h>
#include <math.h>
#include <stdint.h>

#define BB 256
#define LL 200
#define DD 512
#define BBDD (BB * DD)
typedef uint32_t u32;

// ---------------- fp32 scratch ----------------
__device__ float g_xproj[(size_t)BB * LL * 3 * DD];   // [B,L,3D] (+bih)
__device__ float g_sseq [(size_t)LL * BB * DD];       // [L,B,D]
__device__ float g_rx   [(size_t)LL * BB * DD];
__device__ float g_ux   [(size_t)LL * BB * DD];
__device__ float g_nx   [(size_t)LL * BB * DD];
__device__ float g_u    [BB * DD];
__device__ float g_logits[LL * BB];
__device__ float g_att   [LL * BB];
__device__ float g_ue    [BB * DD];
__device__ float g_hf    [2 * BB * DD];
__device__ float g_zero  [BB * DD];                   // fp32 zeros == packed zeros

// ---------------- packed (bf16-pair) activations ----------------
__device__ u32 g_Psess[(size_t)BB * LL * DD];
__device__ u32 g_Ptar [BB * DD];
__device__ u32 g_Psseq[(size_t)LL * BB * DD];
__device__ u32 g_Phr  [BB * DD];
__device__ u32 g_Pp   [2 * BB * DD];

// ---------------- weight fragments (B-operand order) ----------------
__device__ u32 g_Fwih[1536 * DD];
__device__ u32 g_Fwhh[1536 * DD];
__device__ u32 g_Fw  [DD * DD];
__device__ u32 g_Frh [DD * DD];
__device__ u32 g_Fuh [DD * DD];
__device__ u32 g_Fhh [DD * DD];
__device__ u32 g_Frx [DD * DD];
__device__ u32 g_Fux [DD * DD];
__device__ u32 g_Fhx [DD * DD];

// grid barrier
__device__ unsigned int          g_cnt = 0;
__device__ volatile unsigned int g_gen = 0;

__device__ __forceinline__ float sigf(float x) { return 1.0f / (1.0f + __expf(-x)); }

__device__ __forceinline__ u32 packbf(float x) {
    __nv_bfloat16 hi = __float2bfloat16(x);
    float hf = __bfloat162float(hi);
    __nv_bfloat16 lo = __float2bfloat16(x - hf);
    return (u32)__bfloat16_as_ushort(hi) | ((u32)__bfloat16_as_ushort(lo) << 16);
}

__device__ __forceinline__ void grid_barrier(int nb) {
    __syncthreads();
    if (threadIdx.x == 0) {
        __threadfence();
        unsigned int gen = g_gen;
        unsigned int old = atomicAdd(&g_cnt, 1u);
        if (old == (unsigned)(nb - 1)) {
            atomicExch(&g_cnt, 0u);
            __threadfence();
            atomicAdd((unsigned int*)&g_gen, 1u);
        } else {
            while (g_gen == gen) { }
        }
        __threadfence();
    }
    __syncthreads();
}

__device__ __forceinline__ void mma16(float* d, const u32* a, u32 b0, u32 b1) {
    asm volatile(
        "mma.sync.aligned.m16n8k16.row.col.f32.bf16.bf16.f32 "
        "{%0,%1,%2,%3},{%4,%5,%6,%7},{%8,%9},{%0,%1,%2,%3};"
        : "+f"(d[0]), "+f"(d[1]), "+f"(d[2]), "+f"(d[3])
        : "r"(a[0]), "r"(a[1]), "r"(a[2]), "r"(a[3]), "r"(b0), "r"(b1));
}

// ==================================================================
// 256-thread 128x64 core (unchanged from round 6 — proven correct)
// ==================================================================
struct MMSmem { u32 A[2][16][136]; };

__device__ __forceinline__ void mm_core(
    MMSmem* sm, const u32* __restrict__ Ap,
    const u32* __restrict__ F, int gnt0,
    float acc[2][4][4])
{
    const int tid  = threadIdx.x;
    const int lane = tid & 31;
    const int gq = lane >> 2, tq = lane & 3;
    const int w  = tid >> 5;
    const int wm = w >> 1, wn = w & 1;
    const int r  = tid >> 1, h = tid & 1;

    const u32* arow = Ap + (size_t)r * DD + h * 8;

    uint4 bv[4], nbv[4], na0, na1;

    uint4 va0 = *(const uint4*)(arow + 0);
    uint4 va1 = *(const uint4*)(arow + 4);
    #pragma unroll
    for (int nt = 0; nt < 4; nt++) {
        int gnt = gnt0 + wn * 4 + nt;
        bv[nt] = *(const uint4*)(F + (((size_t)gnt * 32 + 0) * 32 + lane) * 4);
    }
    {
        u32 e0[4] = {va0.x, va0.y, va0.z, va0.w};
        u32 e1[4] = {va1.x, va1.y, va1.z, va1.w};
        #pragma unroll
        for (int j = 0; j < 4; j++) {
            int jj = (j + 2 * h) & 3;
            sm->A[0][h * 8 + 0 + jj][r] = e0[jj];
            sm->A[0][h * 8 + 4 + jj][r] = e1[jj];
        }
    }
    __syncthreads();

    #pragma unroll 1
    for (int s2 = 0; s2 < 32; s2++) {
        const int buf = s2 & 1;
        if (s2 < 31) {
            const u32* ar = arow + (s2 + 1) * 16;
            na0 = *(const uint4*)(ar);
            na1 = *(const uint4*)(ar + 4);
            #pragma unroll
            for (int nt = 0; nt < 4; nt++) {
                int gnt = gnt0 + wn * 4 + nt;
                nbv[nt] = *(const uint4*)(F + (((size_t)gnt * 32 + (s2 + 1)) * 32 + lane) * 4);
            }
        }
        #pragma unroll
        for (int sl = 0; sl < 2; sl++) {
            u32 a[2][4], as[2][4];
            #pragma unroll
            for (int mt = 0; mt < 2; mt++) {
                int rb = wm * 32 + mt * 16 + gq;
                a[mt][0] = sm->A[buf][sl * 8 + tq][rb];
                a[mt][1] = sm->A[buf][sl * 8 + tq][rb + 8];
                a[mt][2] = sm->A[buf][sl * 8 + tq + 4][rb];
                a[mt][3] = sm->A[buf][sl * 8 + tq + 4][rb + 8];
                #pragma unroll
                for (int q = 0; q < 4; q++)
                    as[mt][q] = __funnelshift_l(a[mt][q], a[mt][q], 16);
            }
            #pragma unroll
            for (int nt = 0; nt < 4; nt++) {
                u32 b0 = sl ? bv[nt].z : bv[nt].x;
                u32 b1 = sl ? bv[nt].w : bv[nt].y;
                #pragma unroll
                for (int mt = 0; mt < 2; mt++) {
                    mma16(acc[mt][nt], a[mt],  b0, b1);
                    mma16(acc[mt][nt], as[mt], b0, b1);
                }
            }
        }
        if (s2 < 31) {
            u32 e0[4] = {na0.x, na0.y, na0.z, na0.w};
            u32 e1[4] = {na1.x, na1.y, na1.z, na1.w};
            #pragma unroll
            for (int j = 0; j < 4; j++) {
                int jj = (j + 2 * h) & 3;
                sm->A[buf ^ 1][h * 8 + 0 + jj][r] = e0[jj];
                sm->A[buf ^ 1][h * 8 + 4 + jj][r] = e1[jj];
            }
            #pragma unroll
            for (int nt = 0; nt < 4; nt++) bv[nt] = nbv[nt];
        }
        __syncthreads();
    }
}

__global__ __launch_bounds__(256) void mm_big(
    const u32* __restrict__ Ap,
    const u32* __restrict__ F,
    const float* __restrict__ bias,
    float* __restrict__ C, int ldc)
{
    __shared__ MMSmem sm;
    const int bm = blockIdx.x * 128, bn = blockIdx.y * 64;
    float acc[2][4][4];
    #pragma unroll
    for (int i = 0; i < 2; i++)
        #pragma unroll
        for (int j = 0; j < 4; j++)
            #pragma unroll
            for (int e = 0; e < 4; e++) acc[i][j][e] = 0.f;
    mm_core(&sm, Ap + (size_t)bm * DD, F, bn >> 3, acc);

    const int lane = threadIdx.x & 31;
    const int gq = lane >> 2, tq = lane & 3;
    const int w = threadIdx.x >> 5;
    const int wm = w >> 1, wn = w & 1;
    #pragma unroll
    for (int mt = 0; mt < 2; mt++)
        #pragma unroll
        for (int nt = 0; nt < 4; nt++) {
            int row = bm + wm * 32 + mt * 16 + gq;
            int col = bn + wn * 32 + nt * 8 + 2 * tq;
            float b0 = bias ? bias[col] : 0.f;
            float b1 = bias ? bias[col + 1] : 0.f;
            *(float2*)(C + (size_t)row * ldc + col) =
                make_float2(acc[mt][nt][0] + b0, acc[mt][nt][1] + b1);
            *(float2*)(C + (size_t)(row + 8) * ldc + col) =
                make_float2(acc[mt][nt][2] + b0, acc[mt][nt][3] + b1);
        }
}

// ==================================================================
// 128-thread 64-row x 32-col x NG-gate recurrence core
// ==================================================================
struct RSmem { u32 A[2][16][72]; };

template<int NG>
__device__ __forceinline__ void rec_core(
    RSmem* sm, const u32* __restrict__ Ap,
    const u32* const* Fp, const int* gb,
    float acc[NG][2][2][4])
{
    const int tid  = threadIdx.x;
    const int lane = tid & 31;
    const int gq = lane >> 2, tq = lane & 3;
    const int w  = tid >> 5;
    const int wm = w >> 1, wn = w & 1;
    const int r  = tid >> 1, h = tid & 1;

    const u32* arow = Ap + (size_t)r * DD + h * 8;

    uint4 bv[NG][2], nbv[NG][2], na0, na1;

    uint4 va0 = *(const uint4*)(arow + 0);
    uint4 va1 = *(const uint4*)(arow + 4);
    #pragma unroll
    for (int g = 0; g < NG; g++)
        #pragma unroll
        for (int nt = 0; nt < 2; nt++)
            bv[g][nt] = *(const uint4*)(Fp[g] +
                (((size_t)(gb[g] + wn * 2 + nt) * 32 + 0) * 32 + lane) * 4);
    {
        u32 e0[4] = {va0.x, va0.y, va0.z, va0.w};
        u32 e1[4] = {va1.x, va1.y, va1.z, va1.w};
        #pragma unroll
        for (int j = 0; j < 4; j++) {
            int jj = (j + 2 * h) & 3;
            sm->A[0][h * 8 + 0 + jj][r] = e0[jj];
            sm->A[0][h * 8 + 4 + jj][r] = e1[jj];
        }
    }
    __syncthreads();

    #pragma unroll 1
    for (int s2 = 0; s2 < 32; s2++) {
        const int buf = s2 & 1;
        if (s2 < 31) {
            const u32* ar = arow + (s2 + 1) * 16;
            na0 = *(const uint4*)(ar);
            na1 = *(const uint4*)(ar + 4);
            #pragma unroll
            for (int g = 0; g < NG; g++)
                #pragma unroll
                for (int nt = 0; nt < 2; nt++)
                    nbv[g][nt] = *(const uint4*)(Fp[g] +
                        (((size_t)(gb[g] + wn * 2 + nt) * 32 + (s2 + 1)) * 32 + lane) * 4);
        }
        #pragma unroll
        for (int sl = 0; sl < 2; sl++) {
            u32 a[2][4], as[2][4];
            #pragma unroll
            for (int mt = 0; mt < 2; mt++) {
                int rb = wm * 32 + mt * 16 + gq;
                a[mt][0] = sm->A[buf][sl * 8 + tq][rb];
                a[mt][1] = sm->A[buf][sl * 8 + tq][rb + 8];
                a[mt][2] = sm->A[buf][sl * 8 + tq + 4][rb];
                a[mt][3] = sm->A[buf][sl * 8 + tq + 4][rb + 8];
                #pragma unroll
                for (int q = 0; q < 4; q++)
                    as[mt][q] = __funnelshift_l(a[mt][q], a[mt][q], 16);
            }
            #pragma unroll
            for (int g = 0; g < NG; g++)
                #pragma unroll
                for (int nt = 0; nt < 2; nt++) {
                    u32 b0 = sl ? bv[g][nt].z : bv[g][nt].x;
                    u32 b1 = sl ? bv[g][nt].w : bv[g][nt].y;
                    #pragma unroll
                    for (int mt = 0; mt < 2; mt++) {
                        mma16(acc[g][mt][nt], a[mt],  b0, b1);
                        mma16(acc[g][mt][nt], as[mt], b0, b1);
                    }
                }
        }
        if (s2 < 31) {
            u32 e0[4] = {na0.x, na0.y, na0.z, na0.w};
            u32 e1[4] = {na1.x, na1.y, na1.z, na1.w};
            #pragma unroll
            for (int j = 0; j < 4; j++) {
                int jj = (j + 2 * h) & 3;
                sm->A[buf ^ 1][h * 8 + 0 + jj][r] = e0[jj];
                sm->A[buf ^ 1][h * 8 + 4 + jj][r] = e1[jj];
            }
            #pragma unroll
            for (int g = 0; g < NG; g++) {
                bv[g][0] = nbv[g][0];
                bv[g][1] = nbv[g][1];
            }
        }
        __syncthreads();
    }
}

#define REC_VARS() \
    const int lane_ = threadIdx.x & 31; \
    const int gq_ = lane_ >> 2, tq_ = lane_ & 3; \
    const int w_ = threadIdx.x >> 5; \
    const int wm_ = w_ >> 1, wn_ = w_ & 1;

// ---------------- persistent GRU (fused gates, 64 blocks x 128 thr) ----------------
#define RECB 64
__global__ __launch_bounds__(128) void gru2(
    const float* __restrict__ zero, const u32* __restrict__ Pzero,
    const u32* __restrict__ Fwhh, const float* __restrict__ bhh,
    const float* __restrict__ xproj,
    float* __restrict__ sseq, u32* __restrict__ Psseq)
{
    __shared__ RSmem sm;
    const int blk = blockIdx.x;
    const int mi = blk >> 4, di = blk & 15;
    const int bm = mi * 64, bnd = di * 32;
    REC_VARS();

    const u32* Fp[3] = {Fwhh, Fwhh, Fwhh};
    int gb[3] = {di * 4, 64 + di * 4, 128 + di * 4};   // r,z,n rows 0/512/1024

    // cache biases for this thread's 4 columns x 3 gates
    float bh[3][2][2];
    #pragma unroll
    for (int g = 0; g < 3; g++)
        #pragma unroll
        for (int nt = 0; nt < 2; nt++) {
            int col = bnd + wn_ * 16 + nt * 8 + 2 * tq_;
            bh[g][nt][0] = bhh[g * 512 + col];
            bh[g][nt][1] = bhh[g * 512 + col + 1];
        }

    for (int l = 0; l < LL; l++) {
        const u32* Ap = (l ? Psseq + (size_t)(l - 1) * BBDD : Pzero) + (size_t)bm * DD;
        float acc[3][2][2][4];
        #pragma unroll
        for (int g = 0; g < 3; g++)
            #pragma unroll
            for (int i = 0; i < 2; i++)
                #pragma unroll
                for (int j = 0; j < 2; j++)
                    #pragma unroll
                    for (int e = 0; e < 4; e++) acc[g][i][j][e] = 0.f;

        rec_core<3>(&sm, Ap, Fp, gb, acc);

        const float* hprev = l ? sseq + (size_t)(l - 1) * BBDD : zero;
        float* sl_ = sseq + (size_t)l * BBDD;
        u32* pl = Psseq + (size_t)l * BBDD;

        #pragma unroll
        for (int mt = 0; mt < 2; mt++)
            #pragma unroll
            for (int nt = 0; nt < 2; nt++) {
                int col = bnd + wn_ * 16 + nt * 8 + 2 * tq_;
                #pragma unroll
                for (int half = 0; half < 2; half++) {
                    int row = bm + wm_ * 32 + mt * 16 + gq_ + half * 8;
                    const float* xb = xproj + ((size_t)row * LL + l) * 1536;
                    size_t ix = (size_t)row * DD + col;
                    #pragma unroll
                    for (int c = 0; c < 2; c++) {
                        int e = half * 2 + c;
                        float rr = sigf(xb[col + c] + acc[0][mt][nt][e] + bh[0][nt][c]);
                        float zz = sigf(xb[512 + col + c] + acc[1][mt][nt][e] + bh[1][nt][c]);
                        float nn = tanhf(xb[1024 + col + c] +
                                         rr * (acc[2][mt][nt][e] + bh[2][nt][c]));
                        float h0 = hprev[ix + c];
                        float hn = nn + zz * (h0 - nn);
                        sl_[ix + c] = hn;
                        pl[ix + c] = packbf(hn);
                    }
                }
            }

        grid_barrier(RECB);
    }
}

// ---------------- persistent AUGRU (fused gates, 64 blocks x 128 thr) ----------------
__global__ __launch_bounds__(128) void augru2(
    const float* __restrict__ hlast, const u32* __restrict__ Pinit,
    const u32* __restrict__ Frh, const u32* __restrict__ Fuh, const u32* __restrict__ Fhh,
    const float* __restrict__ rx, const float* __restrict__ ux, const float* __restrict__ nx,
    const float* __restrict__ att,
    float* __restrict__ hf, u32* __restrict__ Pp,
    u32* __restrict__ Phr, float* __restrict__ ue,
    float* __restrict__ out)
{
    __shared__ RSmem sm;
    const int blk = blockIdx.x;
    const int mi = blk >> 4, di = blk & 15;
    const int bm = mi * 64, bnd = di * 32;
    REC_VARS();

    for (int l = 0; l < LL; l++) {
        const float* hc = l ? hf + (size_t)(l & 1) * BBDD : hlast;
        const u32* Pc = l ? Pp + (size_t)(l & 1) * BBDD : Pinit;

        {   // phase A: r and u_eff
            const u32* Fp[2] = {Frh, Fuh};
            int gb[2] = {di * 4, di * 4};
            float acc[2][2][2][4];
            #pragma unroll
            for (int g = 0; g < 2; g++)
                #pragma unroll
                for (int i = 0; i < 2; i++)
                    #pragma unroll
                    for (int j = 0; j < 2; j++)
                        #pragma unroll
                        for (int e = 0; e < 4; e++) acc[g][i][j][e] = 0.f;

            rec_core<2>(&sm, Pc + (size_t)bm * DD, Fp, gb, acc);

            const float* rxl = rx + (size_t)l * BBDD;
            const float* uxl = ux + (size_t)l * BBDD;
            #pragma unroll
            for (int mt = 0; mt < 2; mt++)
                #pragma unroll
                for (int nt = 0; nt < 2; nt++) {
                    int col = bnd + wn_ * 16 + nt * 8 + 2 * tq_;
                    #pragma unroll
                    for (int half = 0; half < 2; half++) {
                        int row = bm + wm_ * 32 + mt * 16 + gq_ + half * 8;
                        size_t ix = (size_t)row * DD + col;
                        float a = att[(size_t)l * BB + row];
                        #pragma unroll
                        for (int c = 0; c < 2; c++) {
                            int e = half * 2 + c;
                            float vr = acc[0][mt][nt][e] + rxl[ix + c];
                            float vu = acc[1][mt][nt][e] + uxl[ix + c];
                            Phr[ix + c] = packbf(hc[ix + c] * sigf(vr));
                            ue[ix + c]  = a * sigf(vu);
                        }
                    }
                }
        }

        grid_barrier(RECB);

        {   // phase B: hhat + output update
            const u32* Fp[1] = {Fhh};
            int gb[1] = {di * 4};
            float acc[1][2][2][4];
            #pragma unroll
            for (int i = 0; i < 2; i++)
                #pragma unroll
                for (int j = 0; j < 2; j++)
                    #pragma unroll
                    for (int e = 0; e < 4; e++) acc[0][i][j][e] = 0.f;

            rec_core<1>(&sm, Phr + (size_t)bm * DD, Fp, gb, acc);

            float* ho = (l == LL - 1) ? out : hf + (size_t)((l + 1) & 1) * BBDD;
            u32* Pn = Pp + (size_t)((l + 1) & 1) * BBDD;
            const float* nxl = nx + (size_t)l * BBDD;
            #pragma unroll
            for (int mt = 0; mt < 2; mt++)
                #pragma unroll
                for (int nt = 0; nt < 2; nt++) {
                    int col = bnd + wn_ * 16 + nt * 8 + 2 * tq_;
                    #pragma unroll
                    for (int half = 0; half < 2; half++) {
                        int row = bm + wm_ * 32 + mt * 16 + gq_ + half * 8;
                        size_t ix = (size_t)row * DD + col;
                        #pragma unroll
                        for (int c = 0; c < 2; c++) {
                            int e = half * 2 + c;
                            float hh = tanhf(acc[0][mt][nt][e] + nxl[ix + c]);
                            float h0 = hc[ix + c];
                            float u0 = ue[ix + c];
                            float hn = h0 + u0 * (hh - h0);
                            ho[ix + c] = hn;
                            Pn[ix + c] = packbf(hn);
                        }
                    }
                }
        }

        grid_barrier(RECB);
    }
}

// ---------------- conversion kernels ----------------
__global__ void pack_kernel(const float* __restrict__ x, u32* __restrict__ p, int n4)
{
    int i = blockIdx.x * 256 + threadIdx.x;
    if (i < n4) {
        float4 v = ((const float4*)x)[i];
        uint4 o;
        o.x = packbf(v.x); o.y = packbf(v.y); o.z = packbf(v.z); o.w = packbf(v.w);
        ((uint4*)p)[i] = o;
    }
}

__global__ void wfrag_kernel(const float* __restrict__ W, int ldw, int woff,
                             u32* __restrict__ F, int total)
{
    int idx = blockIdx.x * 256 + threadIdx.x;
    if (idx >= total) return;
    int j = idx & 3, lane = (idx >> 2) & 31, s2 = (idx >> 7) & 31, gnt = idx >> 12;
    int g = lane >> 2, t = lane & 3;
    int sl = s2 * 2 + (j >> 1), b = j & 1;
    int ok = sl * 8 + t + 4 * b;
    int n = gnt * 8 + g;
    F[idx] = packbf(W[(size_t)n * ldw + woff + ok]);
}

// ---------------- attention ----------------
__global__ void attn_logits(const float* __restrict__ s, const float* __restrict__ u,
                            float* __restrict__ logits)
{
    int gw = (blockIdx.x * blockDim.x + threadIdx.x) >> 5;
    int lane = threadIdx.x & 31;
    int b = gw & (BB - 1);
    const float4* sr = (const float4*)(s + (size_t)gw * DD);
    const float4* ur = (const float4*)(u + (size_t)b * DD);
    float acc = 0.f;
    #pragma unroll
    for (int k = lane; k < DD / 4; k += 32) {
        float4 a = sr[k], c = ur[k];
        acc += a.x * c.x + a.y * c.y + a.z * c.z + a.w * c.w;
    }
    #pragma unroll
    for (int o = 16; o > 0; o >>= 1) acc += __shfl_xor_sync(0xffffffffu, acc, o);
    if (lane == 0) logits[gw] = acc;
}

__global__ void attn_softmax(const float* __restrict__ logits, float* __restrict__ att)
{
    int b = blockIdx.x, t = threadIdx.x;
    __shared__ float red[256];
    float v = (t < LL) ? logits[t * BB + b] : -1e30f;
    red[t] = v;
    __syncthreads();
    for (int s = 128; s > 0; s >>= 1) {
        if (t < s) red[t] = fmaxf(red[t], red[t + s]);
        __syncthreads();
    }
    float mx = red[0];
    __syncthreads();
    float e = (t < LL) ? expf(v - mx) : 0.f;
    red[t] = e;
    __syncthreads();
    for (int s = 128; s > 0; s >>= 1) {
        if (t < s) red[t] += red[t + s];
        __syncthreads();
    }
    float inv = 1.f / red[0];
    if (t < LL) att[t * BB + b] = e * inv;
}

__global__ void zero_kernel(float* __restrict__ p, int n)
{
    int i = blockIdx.x * blockDim.x + threadIdx.x;
    if (i < n) p[i] = 0.f;
}

// ---------------- host ----------------
extern "C" void kernel_launch(void* const* d_in, const int* in_sizes, int n_in,
                              void* d_out, int out_size)
{
    const float* session  = (const float*)d_in[0];
    const float* target   = (const float*)d_in[1];
    const float* w        = (const float*)d_in[2];
    const float* wih      = (const float*)d_in[3];
    const float* whh      = (const float*)d_in[4];
    const float* bih      = (const float*)d_in[5];
    const float* bhh      = (const float*)d_in[6];
    const float* reset_w  = (const float*)d_in[7];
    const float* reset_b  = (const float*)d_in[8];
    const float* update_w = (const float*)d_in[9];
    const float* update_b = (const float*)d_in[10];
    const float* hhat_w   = (const float*)d_in[11];
    const float* hhat_b   = (const float*)d_in[12];
    float* out = (float*)d_out;

    float *xproj, *sseq, *rx, *ux, *nx, *u, *logits, *att, *ue, *hf, *zero;
    u32 *Psess, *Ptar, *Psseq, *Phr, *Pp;
    u32 *Fwih, *Fwhh, *Fw, *Frh, *Fuh, *Fhh, *Frx, *Fux, *Fhx;

    cudaGetSymbolAddress((void**)&xproj,  g_xproj);
    cudaGetSymbolAddress((void**)&sseq,   g_sseq);
    cudaGetSymbolAddress((void**)&rx,     g_rx);
    cudaGetSymbolAddress((void**)&ux,     g_ux);
    cudaGetSymbolAddress((void**)&nx,     g_nx);
    cudaGetSymbolAddress((void**)&u,      g_u);
    cudaGetSymbolAddress((void**)&logits, g_logits);
    cudaGetSymbolAddress((void**)&att,    g_att);
    cudaGetSymbolAddress((void**)&ue,     g_ue);
    cudaGetSymbolAddress((void**)&hf,     g_hf);
    cudaGetSymbolAddress((void**)&zero,   g_zero);
    cudaGetSymbolAddress((void**)&Psess,  g_Psess);
    cudaGetSymbolAddress((void**)&Ptar,   g_Ptar);
    cudaGetSymbolAddress((void**)&Psseq,  g_Psseq);
    cudaGetSymbolAddress((void**)&Phr,    g_Phr);
    cudaGetSymbolAddress((void**)&Pp,     g_Pp);
    cudaGetSymbolAddress((void**)&Fwih,   g_Fwih);
    cudaGetSymbolAddress((void**)&Fwhh,   g_Fwhh);
    cudaGetSymbolAddress((void**)&Fw,     g_Fw);
    cudaGetSymbolAddress((void**)&Frh,    g_Frh);
    cudaGetSymbolAddress((void**)&Fuh,    g_Fuh);
    cudaGetSymbolAddress((void**)&Fhh,    g_Fhh);
    cudaGetSymbolAddress((void**)&Frx,    g_Frx);
    cudaGetSymbolAddress((void**)&Fux,    g_Fux);
    cudaGetSymbolAddress((void**)&Fhx,    g_Fhx);

    // --- launches 1-5: minimum prerequisites for gru2 (so ncu -s 5 captures gru2) ---
    zero_kernel<<<(BB * DD + 255) / 256, 256>>>(zero, BB * DD);                       // 1
    pack_kernel<<<(BB * LL * DD / 4 + 255) / 256, 256>>>(session, Psess,
                                                         BB * LL * DD / 4);           // 2
    wfrag_kernel<<<(1536 * DD + 255) / 256, 256>>>(wih, DD, 0, Fwih, 1536 * DD);      // 3
    wfrag_kernel<<<(1536 * DD + 255) / 256, 256>>>(whh, DD, 0, Fwhh, 1536 * DD);      // 4
    {
        dim3 g(BB * LL / 128, 3 * DD / 64);
        mm_big<<<g, 256>>>(Psess, Fwih, bih, xproj, 3 * DD);                           // 5
    }

    // --- launch 6: persistent GRU (ncu capture target) ---
    gru2<<<RECB, 128>>>(zero, (const u32*)zero, Fwhh, bhh, xproj, sseq, Psseq);        // 6

    // --- remaining prep ---
    pack_kernel<<<(BB * DD / 4 + 255) / 256, 256>>>(target, Ptar, BB * DD / 4);
    wfrag_kernel<<<(DD * DD + 255) / 256, 256>>>(w,        DD,     0,  Fw,  DD * DD);
    wfrag_kernel<<<(DD * DD + 255) / 256, 256>>>(reset_w,  2 * DD, 0,  Frh, DD * DD);
    wfrag_kernel<<<(DD * DD + 255) / 256, 256>>>(update_w, 2 * DD, 0,  Fuh, DD * DD);
    wfrag_kernel<<<(DD * DD + 255) / 256, 256>>>(hhat_w,   2 * DD, 0,  Fhh, DD * DD);
    wfrag_kernel<<<(DD * DD + 255) / 256, 256>>>(reset_w,  2 * DD, DD, Frx, DD * DD);
    wfrag_kernel<<<(DD * DD + 255) / 256, 256>>>(update_w, 2 * DD, DD, Fux, DD * DD);
    wfrag_kernel<<<(DD * DD + 255) / 256, 256>>>(hhat_w,   2 * DD, DD, Fhx, DD * DD);

    // u = target @ w^T
    {
        dim3 g(BB / 128, DD / 64);
        mm_big<<<g, 256>>>(Ptar, Fw, nullptr, u, DD);
    }
    // AUGRU x-projections (biases folded)
    {
        dim3 g(BB * LL / 128, DD / 64);
        mm_big<<<g, 256>>>(Psseq, Frx, reset_b,  rx, DD);
        mm_big<<<g, 256>>>(Psseq, Fux, update_b, ux, DD);
        mm_big<<<g, 256>>>(Psseq, Fhx, hhat_b,   nx, DD);
    }
    // attention
    attn_logits<<<LL * BB / 8, 256>>>(sseq, u, logits);
    attn_softmax<<<BB, 256>>>(logits, att);

    // persistent AUGRU; init h = sseq[L-1]
    augru2<<<RECB, 128>>>(sseq + (size_t)(LL - 1) * BBDD,
                          Psseq + (size_t)(LL - 1) * BBDD,
                          Frh, Fuh, Fhh,
                          rx, ux, nx, att,
                          hf, Pp, Phr, ue, out);
}

// round 8
// speedup vs baseline: 1.7842x; 1.1278x over previous
#include <cuda_runtime.h>
#include <cuda_bf16.h>
#include <math.h>
#include <stdint.h>

#define BB 256
#define LL 200
#define DD 512
#define BBDD (BB * DD)
typedef uint32_t u32;

// ---------------- fp32 scratch ----------------
__device__ float g_xproj[(size_t)BB * LL * 3 * DD];   // [B,L,3D] (+bih)
__device__ float g_sseq [(size_t)LL * BB * DD];       // [L,B,D]
__device__ float g_rx   [(size_t)LL * BB * DD];
__device__ float g_ux   [(size_t)LL * BB * DD];
__device__ float g_nx   [(size_t)LL * BB * DD];
__device__ float g_u    [BB * DD];
__device__ float g_logits[LL * BB];
__device__ float g_att   [LL * BB];
__device__ float g_ue    [BB * DD];
__device__ float g_hf    [2 * BB * DD];
__device__ float g_zero  [BB * DD];                   // fp32 zeros == packed zeros

// ---------------- packed (bf16-pair) activations ----------------
__device__ u32 g_Psess[(size_t)BB * LL * DD];
__device__ u32 g_Ptar [BB * DD];
__device__ u32 g_Psseq[(size_t)LL * BB * DD];
__device__ u32 g_Phr  [BB * DD];
__device__ u32 g_Pp   [2 * BB * DD];

// ---------------- weight fragments (B-operand order) ----------------
__device__ u32 g_Fwih[1536 * DD];
__device__ u32 g_Fwhh[1536 * DD];
__device__ u32 g_Fw  [DD * DD];
__device__ u32 g_Frh [DD * DD];
__device__ u32 g_Fuh [DD * DD];
__device__ u32 g_Fhh [DD * DD];
__device__ u32 g_Frx [DD * DD];
__device__ u32 g_Fux [DD * DD];
__device__ u32 g_Fhx [DD * DD];

// grid barrier
__device__ unsigned int          g_cnt = 0;
__device__ volatile unsigned int g_gen = 0;

__device__ __forceinline__ float sigf(float x) { return 1.0f / (1.0f + __expf(-x)); }

__device__ __forceinline__ u32 packbf(float x) {
    __nv_bfloat16 hi = __float2bfloat16(x);
    float hf = __bfloat162float(hi);
    __nv_bfloat16 lo = __float2bfloat16(x - hf);
    return (u32)__bfloat16_as_ushort(hi) | ((u32)__bfloat16_as_ushort(lo) << 16);
}

__device__ __forceinline__ void grid_barrier(int nb) {
    __syncthreads();
    if (threadIdx.x == 0) {
        __threadfence();
        unsigned int gen = g_gen;
        unsigned int old = atomicAdd(&g_cnt, 1u);
        if (old == (unsigned)(nb - 1)) {
            atomicExch(&g_cnt, 0u);
            __threadfence();
            atomicAdd((unsigned int*)&g_gen, 1u);
        } else {
            while (g_gen == gen) { }
        }
        __threadfence();
    }
    __syncthreads();
}

__device__ __forceinline__ void mma16(float* d, const u32* a, u32 b0, u32 b1) {
    asm volatile(
        "mma.sync.aligned.m16n8k16.row.col.f32.bf16.bf16.f32 "
        "{%0,%1,%2,%3},{%4,%5,%6,%7},{%8,%9},{%0,%1,%2,%3};"
        : "+f"(d[0]), "+f"(d[1]), "+f"(d[2]), "+f"(d[3])
        : "r"(a[0]), "r"(a[1]), "r"(a[2]), "r"(a[3]), "r"(b0), "r"(b1));
}

// ==================================================================
// 256-thread 128x64 core (unchanged — proven correct)
// ==================================================================
struct MMSmem { u32 A[2][16][136]; };

__device__ __forceinline__ void mm_core(
    MMSmem* sm, const u32* __restrict__ Ap,
    const u32* __restrict__ F, int gnt0,
    float acc[2][4][4])
{
    const int tid  = threadIdx.x;
    const int lane = tid & 31;
    const int gq = lane >> 2, tq = lane & 3;
    const int w  = tid >> 5;
    const int wm = w >> 1, wn = w & 1;
    const int r  = tid >> 1, h = tid & 1;

    const u32* arow = Ap + (size_t)r * DD + h * 8;

    uint4 bv[4], nbv[4], na0, na1;

    uint4 va0 = *(const uint4*)(arow + 0);
    uint4 va1 = *(const uint4*)(arow + 4);
    #pragma unroll
    for (int nt = 0; nt < 4; nt++) {
        int gnt = gnt0 + wn * 4 + nt;
        bv[nt] = *(const uint4*)(F + (((size_t)gnt * 32 + 0) * 32 + lane) * 4);
    }
    {
        u32 e0[4] = {va0.x, va0.y, va0.z, va0.w};
        u32 e1[4] = {va1.x, va1.y, va1.z, va1.w};
        #pragma unroll
        for (int j = 0; j < 4; j++) {
            int jj = (j + 2 * h) & 3;
            sm->A[0][h * 8 + 0 + jj][r] = e0[jj];
            sm->A[0][h * 8 + 4 + jj][r] = e1[jj];
        }
    }
    __syncthreads();

    #pragma unroll 1
    for (int s2 = 0; s2 < 32; s2++) {
        const int buf = s2 & 1;
        if (s2 < 31) {
            const u32* ar = arow + (s2 + 1) * 16;
            na0 = *(const uint4*)(ar);
            na1 = *(const uint4*)(ar + 4);
            #pragma unroll
            for (int nt = 0; nt < 4; nt++) {
                int gnt = gnt0 + wn * 4 + nt;
                nbv[nt] = *(const uint4*)(F + (((size_t)gnt * 32 + (s2 + 1)) * 32 + lane) * 4);
            }
        }
        #pragma unroll
        for (int sl = 0; sl < 2; sl++) {
            u32 a[2][4], as[2][4];
            #pragma unroll
            for (int mt = 0; mt < 2; mt++) {
                int rb = wm * 32 + mt * 16 + gq;
                a[mt][0] = sm->A[buf][sl * 8 + tq][rb];
                a[mt][1] = sm->A[buf][sl * 8 + tq][rb + 8];
                a[mt][2] = sm->A[buf][sl * 8 + tq + 4][rb];
                a[mt][3] = sm->A[buf][sl * 8 + tq + 4][rb + 8];
                #pragma unroll
                for (int q = 0; q < 4; q++)
                    as[mt][q] = __funnelshift_l(a[mt][q], a[mt][q], 16);
            }
            #pragma unroll
            for (int nt = 0; nt < 4; nt++) {
                u32 b0 = sl ? bv[nt].z : bv[nt].x;
                u32 b1 = sl ? bv[nt].w : bv[nt].y;
                #pragma unroll
                for (int mt = 0; mt < 2; mt++) {
                    mma16(acc[mt][nt], a[mt],  b0, b1);
                    mma16(acc[mt][nt], as[mt], b0, b1);
                }
            }
        }
        if (s2 < 31) {
            u32 e0[4] = {na0.x, na0.y, na0.z, na0.w};
            u32 e1[4] = {na1.x, na1.y, na1.z, na1.w};
            #pragma unroll
            for (int j = 0; j < 4; j++) {
                int jj = (j + 2 * h) & 3;
                sm->A[buf ^ 1][h * 8 + 0 + jj][r] = e0[jj];
                sm->A[buf ^ 1][h * 8 + 4 + jj][r] = e1[jj];
            }
            #pragma unroll
            for (int nt = 0; nt < 4; nt++) bv[nt] = nbv[nt];
        }
        __syncthreads();
    }
}

__global__ __launch_bounds__(256) void mm_big(
    const u32* __restrict__ Ap,
    const u32* __restrict__ F,
    const float* __restrict__ bias,
    float* __restrict__ C, int ldc)
{
    __shared__ MMSmem sm;
    const int bm = blockIdx.x * 128, bn = blockIdx.y * 64;
    float acc[2][4][4];
    #pragma unroll
    for (int i = 0; i < 2; i++)
        #pragma unroll
        for (int j = 0; j < 4; j++)
            #pragma unroll
            for (int e = 0; e < 4; e++) acc[i][j][e] = 0.f;
    mm_core(&sm, Ap + (size_t)bm * DD, F, bn >> 3, acc);

    const int lane = threadIdx.x & 31;
    const int gq = lane >> 2, tq = lane & 3;
    const int w = threadIdx.x >> 5;
    const int wm = w >> 1, wn = w & 1;
    #pragma unroll
    for (int mt = 0; mt < 2; mt++)
        #pragma unroll
        for (int nt = 0; nt < 4; nt++) {
            int row = bm + wm * 32 + mt * 16 + gq;
            int col = bn + wn * 32 + nt * 8 + 2 * tq;
            float b0 = bias ? bias[col] : 0.f;
            float b1 = bias ? bias[col + 1] : 0.f;
            *(float2*)(C + (size_t)row * ldc + col) =
                make_float2(acc[mt][nt][0] + b0, acc[mt][nt][1] + b1);
            *(float2*)(C + (size_t)(row + 8) * ldc + col) =
                make_float2(acc[mt][nt][2] + b0, acc[mt][nt][3] + b1);
        }
}

// ==================================================================
// 128-thread 64-row x 16-col x NG-gate recurrence core (128-block grids)
// ==================================================================
struct RSmem { u32 A[2][16][72]; };

template<int NG>
__device__ __forceinline__ void rec_core(
    RSmem* sm, const u32* __restrict__ Ap,
    const u32* const* Fp, const int* gb,
    float acc[NG][2][4])
{
    const int tid  = threadIdx.x;
    const int lane = tid & 31;
    const int gq = lane >> 2, tq = lane & 3;
    const int w  = tid >> 5;
    const int wm = w >> 1, wn = w & 1;
    const int r  = tid >> 1, h = tid & 1;

    const u32* arow = Ap + (size_t)r * DD + h * 8;

    uint4 bv[NG], nbv[NG], na0, na1;

    uint4 va0 = *(const uint4*)(arow + 0);
    uint4 va1 = *(const uint4*)(arow + 4);
    #pragma unroll
    for (int g = 0; g < NG; g++)
        bv[g] = *(const uint4*)(Fp[g] +
            (((size_t)(gb[g] + wn) * 32 + 0) * 32 + lane) * 4);
    {
        u32 e0[4] = {va0.x, va0.y, va0.z, va0.w};
        u32 e1[4] = {va1.x, va1.y, va1.z, va1.w};
        #pragma unroll
        for (int j = 0; j < 4; j++) {
            int jj = (j + 2 * h) & 3;
            sm->A[0][h * 8 + 0 + jj][r] = e0[jj];
            sm->A[0][h * 8 + 4 + jj][r] = e1[jj];
        }
    }
    __syncthreads();

    #pragma unroll 1
    for (int s2 = 0; s2 < 32; s2++) {
        const int buf = s2 & 1;
        if (s2 < 31) {
            const u32* ar = arow + (s2 + 1) * 16;
            na0 = *(const uint4*)(ar);
            na1 = *(const uint4*)(ar + 4);
            #pragma unroll
            for (int g = 0; g < NG; g++)
                nbv[g] = *(const uint4*)(Fp[g] +
                    (((size_t)(gb[g] + wn) * 32 + (s2 + 1)) * 32 + lane) * 4);
        }
        #pragma unroll
        for (int sl = 0; sl < 2; sl++) {
            u32 a[2][4], as[2][4];
            #pragma unroll
            for (int mt = 0; mt < 2; mt++) {
                int rb = wm * 32 + mt * 16 + gq;
                a[mt][0] = sm->A[buf][sl * 8 + tq][rb];
                a[mt][1] = sm->A[buf][sl * 8 + tq][rb + 8];
                a[mt][2] = sm->A[buf][sl * 8 + tq + 4][rb];
                a[mt][3] = sm->A[buf][sl * 8 + tq + 4][rb + 8];
                #pragma unroll
                for (int q = 0; q < 4; q++)
                    as[mt][q] = __funnelshift_l(a[mt][q], a[mt][q], 16);
            }
            #pragma unroll
            for (int g = 0; g < NG; g++) {
                u32 b0 = sl ? bv[g].z : bv[g].x;
                u32 b1 = sl ? bv[g].w : bv[g].y;
                #pragma unroll
                for (int mt = 0; mt < 2; mt++) {
                    mma16(acc[g][mt], a[mt],  b0, b1);
                    mma16(acc[g][mt], as[mt], b0, b1);
                }
            }
        }
        if (s2 < 31) {
            u32 e0[4] = {na0.x, na0.y, na0.z, na0.w};
            u32 e1[4] = {na1.x, na1.y, na1.z, na1.w};
            #pragma unroll
            for (int j = 0; j < 4; j++) {
                int jj = (j + 2 * h) & 3;
                sm->A[buf ^ 1][h * 8 + 0 + jj][r] = e0[jj];
                sm->A[buf ^ 1][h * 8 + 4 + jj][r] = e1[jj];
            }
            #pragma unroll
            for (int g = 0; g < NG; g++) bv[g] = nbv[g];
        }
        __syncthreads();
    }
}

#define REC_VARS() \
    const int lane_ = threadIdx.x & 31; \
    const int gq_ = lane_ >> 2, tq_ = lane_ & 3; \
    const int w_ = threadIdx.x >> 5; \
    const int wm_ = w_ >> 1, wn_ = w_ & 1;

// ---------------- persistent GRU (128 blocks x 128 thr, 64x16 tiles) ----------------
#define RECB 128
__global__ __launch_bounds__(128) void gru2(
    const float* __restrict__ zero, const u32* __restrict__ Pzero,
    const u32* __restrict__ Fwhh, const float* __restrict__ bhh,
    const float* __restrict__ xproj,
    float* __restrict__ sseq, u32* __restrict__ Psseq)
{
    __shared__ RSmem sm;
    const int blk = blockIdx.x;
    const int mi = blk >> 5, di = blk & 31;        // 4 row-tiles x 32 col-tiles
    const int bm = mi * 64, bnd = di * 16;
    REC_VARS();

    const u32* Fp[3] = {Fwhh, Fwhh, Fwhh};
    int gb[3] = {di * 2, 64 + di * 2, 128 + di * 2};   // r,z,n (512-col gates, 64 gnt each)

    const int col = bnd + wn_ * 8 + 2 * tq_;
    float bh[3][2];
    #pragma unroll
    for (int g = 0; g < 3; g++) {
        bh[g][0] = bhh[g * 512 + col];
        bh[g][1] = bhh[g * 512 + col + 1];
    }

    for (int l = 0; l < LL; l++) {
        const u32* Ap = (l ? Psseq + (size_t)(l - 1) * BBDD : Pzero) + (size_t)bm * DD;
        float acc[3][2][4];
        #pragma unroll
        for (int g = 0; g < 3; g++)
            #pragma unroll
            for (int i = 0; i < 2; i++)
                #pragma unroll
                for (int e = 0; e < 4; e++) acc[g][i][e] = 0.f;

        rec_core<3>(&sm, Ap, Fp, gb, acc);

        const float* hprev = l ? sseq + (size_t)(l - 1) * BBDD : zero;
        float* sl_ = sseq + (size_t)l * BBDD;
        u32* pl = Psseq + (size_t)l * BBDD;

        #pragma unroll
        for (int mt = 0; mt < 2; mt++)
            #pragma unroll
            for (int half = 0; half < 2; half++) {
                int row = bm + wm_ * 32 + mt * 16 + gq_ + half * 8;
                const float* xb = xproj + ((size_t)row * LL + l) * 1536;
                size_t ix = (size_t)row * DD + col;
                #pragma unroll
                for (int c = 0; c < 2; c++) {
                    int e = half * 2 + c;
                    float rr = sigf(xb[col + c] + acc[0][mt][e] + bh[0][c]);
                    float zz = sigf(xb[512 + col + c] + acc[1][mt][e] + bh[1][c]);
                    float nn = tanhf(xb[1024 + col + c] + rr * (acc[2][mt][e] + bh[2][c]));
                    float h0 = hprev[ix + c];
                    float hn = nn + zz * (h0 - nn);
                    sl_[ix + c] = hn;
                    pl[ix + c] = packbf(hn);
                }
            }

        grid_barrier(RECB);
    }
}

// ---------------- persistent AUGRU (128 blocks x 128 thr) ----------------
__global__ __launch_bounds__(128) void augru2(
    const float* __restrict__ hlast, const u32* __restrict__ Pinit,
    const u32* __restrict__ Frh, const u32* __restrict__ Fuh, const u32* __restrict__ Fhh,
    const float* __restrict__ rx, const float* __restrict__ ux, const float* __restrict__ nx,
    const float* __restrict__ att,
    float* __restrict__ hf, u32* __restrict__ Pp,
    u32* __restrict__ Phr, float* __restrict__ ue,
    float* __restrict__ out)
{
    __shared__ RSmem sm;
    const int blk = blockIdx.x;
    const int mi = blk >> 5, di = blk & 31;
    const int bm = mi * 64, bnd = di * 16;
    REC_VARS();
    const int col = bnd + wn_ * 8 + 2 * tq_;

    for (int l = 0; l < LL; l++) {
        const float* hc = l ? hf + (size_t)(l & 1) * BBDD : hlast;
        const u32* Pc = l ? Pp + (size_t)(l & 1) * BBDD : Pinit;

        {   // phase A: r and u_eff
            const u32* Fp[2] = {Frh, Fuh};
            int gb[2] = {di * 2, di * 2};
            float acc[2][2][4];
            #pragma unroll
            for (int g = 0; g < 2; g++)
                #pragma unroll
                for (int i = 0; i < 2; i++)
                    #pragma unroll
                    for (int e = 0; e < 4; e++) acc[g][i][e] = 0.f;

            rec_core<2>(&sm, Pc + (size_t)bm * DD, Fp, gb, acc);

            const float* rxl = rx + (size_t)l * BBDD;
            const float* uxl = ux + (size_t)l * BBDD;
            #pragma unroll
            for (int mt = 0; mt < 2; mt++)
                #pragma unroll
                for (int half = 0; half < 2; half++) {
                    int row = bm + wm_ * 32 + mt * 16 + gq_ + half * 8;
                    size_t ix = (size_t)row * DD + col;
                    float a = att[(size_t)l * BB + row];
                    #pragma unroll
                    for (int c = 0; c < 2; c++) {
                        int e = half * 2 + c;
                        float vr = acc[0][mt][e] + rxl[ix + c];
                        float vu = acc[1][mt][e] + uxl[ix + c];
                        Phr[ix + c] = packbf(hc[ix + c] * sigf(vr));
                        ue[ix + c]  = a * sigf(vu);
                    }
                }
        }

        grid_barrier(RECB);

        {   // phase B: hhat + output update
            const u32* Fp[1] = {Fhh};
            int gb[1] = {di * 2};
            float acc[1][2][4];
            #pragma unroll
            for (int i = 0; i < 2; i++)
                #pragma unroll
                for (int e = 0; e < 4; e++) acc[0][i][e] = 0.f;

            rec_core<1>(&sm, Phr + (size_t)bm * DD, Fp, gb, acc);

            float* ho = (l == LL - 1) ? out : hf + (size_t)((l + 1) & 1) * BBDD;
            u32* Pn = Pp + (size_t)((l + 1) & 1) * BBDD;
            const float* nxl = nx + (size_t)l * BBDD;
            #pragma unroll
            for (int mt = 0; mt < 2; mt++)
                #pragma unroll
                for (int half = 0; half < 2; half++) {
                    int row = bm + wm_ * 32 + mt * 16 + gq_ + half * 8;
                    size_t ix = (size_t)row * DD + col;
                    #pragma unroll
                    for (int c = 0; c < 2; c++) {
                        int e = half * 2 + c;
                        float hh = tanhf(acc[0][mt][e] + nxl[ix + c]);
                        float h0 = hc[ix + c];
                        float u0 = ue[ix + c];
                        float hn = h0 + u0 * (hh - h0);
                        ho[ix + c] = hn;
                        Pn[ix + c] = packbf(hn);
                    }
                }
        }

        grid_barrier(RECB);
    }
}

// ---------------- conversion kernels ----------------
__global__ void pack_kernel(const float* __restrict__ x, u32* __restrict__ p, int n4)
{
    int i = blockIdx.x * 256 + threadIdx.x;
    if (i < n4) {
        float4 v = ((const float4*)x)[i];
        uint4 o;
        o.x = packbf(v.x); o.y = packbf(v.y); o.z = packbf(v.z); o.w = packbf(v.w);
        ((uint4*)p)[i] = o;
    }
}

__global__ void wfrag_kernel(const float* __restrict__ W, int ldw, int woff,
                             u32* __restrict__ F, int total)
{
    int idx = blockIdx.x * 256 + threadIdx.x;
    if (idx >= total) return;
    int j = idx & 3, lane = (idx >> 2) & 31, s2 = (idx >> 7) & 31, gnt = idx >> 12;
    int g = lane >> 2, t = lane & 3;
    int sl = s2 * 2 + (j >> 1), b = j & 1;
    int ok = sl * 8 + t + 4 * b;
    int n = gnt * 8 + g;
    F[idx] = packbf(W[(size_t)n * ldw + woff + ok]);
}

// ---------------- attention ----------------
__global__ void attn_logits(const float* __restrict__ s, const float* __restrict__ u,
                            float* __restrict__ logits)
{
    int gw = (blockIdx.x * blockDim.x + threadIdx.x) >> 5;
    int lane = threadIdx.x & 31;
    int b = gw & (BB - 1);
    const float4* sr = (const float4*)(s + (size_t)gw * DD);
    const float4* ur = (const float4*)(u + (size_t)b * DD);
    float acc = 0.f;
    #pragma unroll
    for (int k = lane; k < DD / 4; k += 32) {
        float4 a = sr[k], c = ur[k];
        acc += a.x * c.x + a.y * c.y + a.z * c.z + a.w * c.w;
    }
    #pragma unroll
    for (int o = 16; o > 0; o >>= 1) acc += __shfl_xor_sync(0xffffffffu, acc, o);
    if (lane == 0) logits[gw] = acc;
}

__global__ void attn_softmax(const float* __restrict__ logits, float* __restrict__ att)
{
    int b = blockIdx.x, t = threadIdx.x;
    __shared__ float red[256];
    float v = (t < LL) ? logits[t * BB + b] : -1e30f;
    red[t] = v;
    __syncthreads();
    for (int s = 128; s > 0; s >>= 1) {
        if (t < s) red[t] = fmaxf(red[t], red[t + s]);
        __syncthreads();
    }
    float mx = red[0];
    __syncthreads();
    float e = (t < LL) ? expf(v - mx) : 0.f;
    red[t] = e;
    __syncthreads();
    for (int s = 128; s > 0; s >>= 1) {
        if (t < s) red[t] += red[t + s];
        __syncthreads();
    }
    float inv = 1.f / red[0];
    if (t < LL) att[t * BB + b] = e * inv;
}

__global__ void zero_kernel(float* __restrict__ p, int n)
{
    int i = blockIdx.x * blockDim.x + threadIdx.x;
    if (i < n) p[i] = 0.f;
}

// ---------------- host ----------------
extern "C" void kernel_launch(void* const* d_in, const int* in_sizes, int n_in,
                              void* d_out, int out_size)
{
    const float* session  = (const float*)d_in[0];
    const float* target   = (const float*)d_in[1];
    const float* w        = (const float*)d_in[2];
    const float* wih      = (const float*)d_in[3];
    const float* whh      = (const float*)d_in[4];
    const float* bih      = (const float*)d_in[5];
    const float* bhh      = (const float*)d_in[6];
    const float* reset_w  = (const float*)d_in[7];
    const float* reset_b  = (const float*)d_in[8];
    const float* update_w = (const float*)d_in[9];
    const float* update_b = (const float*)d_in[10];
    const float* hhat_w   = (const float*)d_in[11];
    const float* hhat_b   = (const float*)d_in[12];
    float* out = (float*)d_out;

    float *xproj, *sseq, *rx, *ux, *nx, *u, *logits, *att, *ue, *hf, *zero;
    u32 *Psess, *Ptar, *Psseq, *Phr, *Pp;
    u32 *Fwih, *Fwhh, *Fw, *Frh, *Fuh, *Fhh, *Frx, *Fux, *Fhx;

    cudaGetSymbolAddress((void**)&xproj,  g_xproj);
    cudaGetSymbolAddress((void**)&sseq,   g_sseq);
    cudaGetSymbolAddress((void**)&rx,     g_rx);
    cudaGetSymbolAddress((void**)&ux,     g_ux);
    cudaGetSymbolAddress((void**)&nx,     g_nx);
    cudaGetSymbolAddress((void**)&u,      g_u);
    cudaGetSymbolAddress((void**)&logits, g_logits);
    cudaGetSymbolAddress((void**)&att,    g_att);
    cudaGetSymbolAddress((void**)&ue,     g_ue);
    cudaGetSymbolAddress((void**)&hf,     g_hf);
    cudaGetSymbolAddress((void**)&zero,   g_zero);
    cudaGetSymbolAddress((void**)&Psess,  g_Psess);
    cudaGetSymbolAddress((void**)&Ptar,   g_Ptar);
    cudaGetSymbolAddress((void**)&Psseq,  g_Psseq);
    cudaGetSymbolAddress((void**)&Phr,    g_Phr);
    cudaGetSymbolAddress((void**)&Pp,     g_Pp);
    cudaGetSymbolAddress((void**)&Fwih,   g_Fwih);
    cudaGetSymbolAddress((void**)&Fwhh,   g_Fwhh);
    cudaGetSymbolAddress((void**)&Fw,     g_Fw);
    cudaGetSymbolAddress((void**)&Frh,    g_Frh);
    cudaGetSymbolAddress((void**)&Fuh,    g_Fuh);
    cudaGetSymbolAddress((void**)&Fhh,    g_Fhh);
    cudaGetSymbolAddress((void**)&Frx,    g_Frx);
    cudaGetSymbolAddress((void**)&Fux,    g_Fux);
    cudaGetSymbolAddress((void**)&Fhx,    g_Fhx);

    // launches 1-3, then mm_big as our #4 (harness pre-launches ~2 → ncu -s 5 slot)
    zero_kernel<<<(BB * DD + 255) / 256, 256>>>(zero, BB * DD);                       // 1
    pack_kernel<<<(BB * LL * DD / 4 + 255) / 256, 256>>>(session, Psess,
                                                         BB * LL * DD / 4);           // 2
    wfrag_kernel<<<(1536 * DD + 255) / 256, 256>>>(wih, DD, 0, Fwih, 1536 * DD);      // 3
    {
        dim3 g(BB * LL / 128, 3 * DD / 64);
        mm_big<<<g, 256>>>(Psess, Fwih, bih, xproj, 3 * DD);                           // 4 <- ncu
    }
    wfrag_kernel<<<(1536 * DD + 255) / 256, 256>>>(whh, DD, 0, Fwhh, 1536 * DD);      // 5

    // persistent GRU
    gru2<<<RECB, 128>>>(zero, (const u32*)zero, Fwhh, bhh, xproj, sseq, Psseq);        // 6

    // remaining prep
    pack_kernel<<<(BB * DD / 4 + 255) / 256, 256>>>(target, Ptar, BB * DD / 4);
    wfrag_kernel<<<(DD * DD + 255) / 256, 256>>>(w,        DD,     0,  Fw,  DD * DD);
    wfrag_kernel<<<(DD * DD + 255) / 256, 256>>>(reset_w,  2 * DD, 0,  Frh, DD * DD);
    wfrag_kernel<<<(DD * DD + 255) / 256, 256>>>(update_w, 2 * DD, 0,  Fuh, DD * DD);
    wfrag_kernel<<<(DD * DD + 255) / 256, 256>>>(hhat_w,   2 * DD, 0,  Fhh, DD * DD);
    wfrag_kernel<<<(DD * DD + 255) / 256, 256>>>(reset_w,  2 * DD, DD, Frx, DD * DD);
    wfrag_kernel<<<(DD * DD + 255) / 256, 256>>>(update_w, 2 * DD, DD, Fux, DD * DD);
    wfrag_kernel<<<(DD * DD + 255) / 256, 256>>>(hhat_w,   2 * DD, DD, Fhx, DD * DD);

    // u = target @ w^T
    {
        dim3 g(BB / 128, DD / 64);
        mm_big<<<g, 256>>>(Ptar, Fw, nullptr, u, DD);
    }
    // AUGRU x-projections (biases folded)
    {
        dim3 g(BB * LL / 128, DD / 64);
        mm_big<<<g, 256>>>(Psseq, Frx, reset_b,  rx, DD);
        mm_big<<<g, 256>>>(Psseq, Fux, update_b, ux, DD);
        mm_big<<<g, 256>>>(Psseq, Fhx, hhat_b,   nx, DD);
    }
    // attention
    attn_logits<<<LL * BB / 8, 256>>>(sseq, u, logits);
    attn_softmax<<<BB, 256>>>(logits, att);

    // persistent AUGRU; init h = sseq[L-1]
    augru2<<<RECB, 128>>>(sseq + (size_t)(LL - 1) * BBDD,
                          Psseq + (size_t)(LL - 1) * BBDD,
                          Frh, Fuh, Fhh,
                          rx, ux, nx, att,
                          hf, Pp, Phr, ue, out);
}

// round 9
// speedup vs baseline: 2.1607x; 1.2110x over previous
#include <cuda_runtime.h>
#include <cuda_bf16.h>
#include <math.h>
#include <stdint.h>

#define BB 256
#define LL 200
#define DD 512
#define BBDD (BB * DD)
typedef uint32_t u32;

// ---------------- fp32 scratch ----------------
__device__ float g_xproj[(size_t)BB * LL * 3 * DD];   // [B,L,3D] (+bih)
__device__ float g_sseq [(size_t)LL * BB * DD];       // [L,B,D]
__device__ float g_rx   [(size_t)LL * BB * DD];
__device__ float g_ux   [(size_t)LL * BB * DD];
__device__ float g_nx   [(size_t)LL * BB * DD];
__device__ float g_u    [BB * DD];
__device__ float g_logits[LL * BB];
__device__ float g_att   [LL * BB];
__device__ float g_ue    [BB * DD];
__device__ float g_hf    [2 * BB * DD];
__device__ float g_zero  [BB * DD];                   // fp32 zeros == packed zeros

// ---------------- packed (bf16-pair) activations ----------------
__device__ u32 g_Psess[(size_t)BB * LL * DD];
__device__ u32 g_Ptar [BB * DD];
__device__ u32 g_Psseq[(size_t)LL * BB * DD];
__device__ u32 g_Phr  [BB * DD];
__device__ u32 g_Pp   [2 * BB * DD];

// ---------------- weight fragments (B-operand order) ----------------
__device__ u32 g_Fwih[1536 * DD];
__device__ u32 g_Fwhh[1536 * DD];
__device__ u32 g_Fw  [DD * DD];
__device__ u32 g_Frh [DD * DD];
__device__ u32 g_Fuh [DD * DD];
__device__ u32 g_Fhh [DD * DD];
__device__ u32 g_Frx [DD * DD];
__device__ u32 g_Fux [DD * DD];
__device__ u32 g_Fhx [DD * DD];

// grid barrier
__device__ unsigned int          g_cnt = 0;
__device__ volatile unsigned int g_gen = 0;

__device__ __forceinline__ float sigf(float x) { return 1.0f / (1.0f + __expf(-x)); }

__device__ __forceinline__ u32 packbf(float x) {
    __nv_bfloat16 hi = __float2bfloat16(x);
    float hf = __bfloat162float(hi);
    __nv_bfloat16 lo = __float2bfloat16(x - hf);
    return (u32)__bfloat16_as_ushort(hi) | ((u32)__bfloat16_as_ushort(lo) << 16);
}

__device__ __forceinline__ void grid_barrier(int nb) {
    __syncthreads();
    if (threadIdx.x == 0) {
        __threadfence();
        unsigned int gen = g_gen;
        unsigned int old = atomicAdd(&g_cnt, 1u);
        if (old == (unsigned)(nb - 1)) {
            atomicExch(&g_cnt, 0u);
            __threadfence();
            atomicAdd((unsigned int*)&g_gen, 1u);
        } else {
            while (g_gen == gen) { }
        }
        __threadfence();
    }
    __syncthreads();
}

__device__ __forceinline__ void mma16(float* d, const u32* a, u32 b0, u32 b1) {
    asm volatile(
        "mma.sync.aligned.m16n8k16.row.col.f32.bf16.bf16.f32 "
        "{%0,%1,%2,%3},{%4,%5,%6,%7},{%8,%9},{%0,%1,%2,%3};"
        : "+f"(d[0]), "+f"(d[1]), "+f"(d[2]), "+f"(d[3])
        : "r"(a[0]), "r"(a[1]), "r"(a[2]), "r"(a[3]), "r"(b0), "r"(b1));
}

// ==================================================================
// 256-thread 128x64 core (unchanged — proven)
// ==================================================================
struct MMSmem { u32 A[2][16][136]; };

__device__ __forceinline__ void mm_core(
    MMSmem* sm, const u32* __restrict__ Ap,
    const u32* __restrict__ F, int gnt0,
    float acc[2][4][4])
{
    const int tid  = threadIdx.x;
    const int lane = tid & 31;
    const int gq = lane >> 2, tq = lane & 3;
    const int w  = tid >> 5;
    const int wm = w >> 1, wn = w & 1;
    const int r  = tid >> 1, h = tid & 1;

    const u32* arow = Ap + (size_t)r * DD + h * 8;

    uint4 bv[4], nbv[4], na0, na1;

    uint4 va0 = *(const uint4*)(arow + 0);
    uint4 va1 = *(const uint4*)(arow + 4);
    #pragma unroll
    for (int nt = 0; nt < 4; nt++) {
        int gnt = gnt0 + wn * 4 + nt;
        bv[nt] = *(const uint4*)(F + (((size_t)gnt * 32 + 0) * 32 + lane) * 4);
    }
    {
        u32 e0[4] = {va0.x, va0.y, va0.z, va0.w};
        u32 e1[4] = {va1.x, va1.y, va1.z, va1.w};
        #pragma unroll
        for (int j = 0; j < 4; j++) {
            int jj = (j + 2 * h) & 3;
            sm->A[0][h * 8 + 0 + jj][r] = e0[jj];
            sm->A[0][h * 8 + 4 + jj][r] = e1[jj];
        }
    }
    __syncthreads();

    #pragma unroll 1
    for (int s2 = 0; s2 < 32; s2++) {
        const int buf = s2 & 1;
        if (s2 < 31) {
            const u32* ar = arow + (s2 + 1) * 16;
            na0 = *(const uint4*)(ar);
            na1 = *(const uint4*)(ar + 4);
            #pragma unroll
            for (int nt = 0; nt < 4; nt++) {
                int gnt = gnt0 + wn * 4 + nt;
                nbv[nt] = *(const uint4*)(F + (((size_t)gnt * 32 + (s2 + 1)) * 32 + lane) * 4);
            }
        }
        #pragma unroll
        for (int sl = 0; sl < 2; sl++) {
            u32 a[2][4], as[2][4];
            #pragma unroll
            for (int mt = 0; mt < 2; mt++) {
                int rb = wm * 32 + mt * 16 + gq;
                a[mt][0] = sm->A[buf][sl * 8 + tq][rb];
                a[mt][1] = sm->A[buf][sl * 8 + tq][rb + 8];
                a[mt][2] = sm->A[buf][sl * 8 + tq + 4][rb];
                a[mt][3] = sm->A[buf][sl * 8 + tq + 4][rb + 8];
                #pragma unroll
                for (int q = 0; q < 4; q++)
                    as[mt][q] = __funnelshift_l(a[mt][q], a[mt][q], 16);
            }
            #pragma unroll
            for (int nt = 0; nt < 4; nt++) {
                u32 b0 = sl ? bv[nt].z : bv[nt].x;
                u32 b1 = sl ? bv[nt].w : bv[nt].y;
                #pragma unroll
                for (int mt = 0; mt < 2; mt++) {
                    mma16(acc[mt][nt], a[mt],  b0, b1);
                    mma16(acc[mt][nt], as[mt], b0, b1);
                }
            }
        }
        if (s2 < 31) {
            u32 e0[4] = {na0.x, na0.y, na0.z, na0.w};
            u32 e1[4] = {na1.x, na1.y, na1.z, na1.w};
            #pragma unroll
            for (int j = 0; j < 4; j++) {
                int jj = (j + 2 * h) & 3;
                sm->A[buf ^ 1][h * 8 + 0 + jj][r] = e0[jj];
                sm->A[buf ^ 1][h * 8 + 4 + jj][r] = e1[jj];
            }
            #pragma unroll
            for (int nt = 0; nt < 4; nt++) bv[nt] = nbv[nt];
        }
        __syncthreads();
    }
}

__global__ __launch_bounds__(256) void mm_big(
    const u32* __restrict__ Ap,
    const u32* __restrict__ F,
    const float* __restrict__ bias,
    float* __restrict__ C, int ldc)
{
    __shared__ MMSmem sm;
    const int bm = blockIdx.x * 128, bn = blockIdx.y * 64;
    float acc[2][4][4];
    #pragma unroll
    for (int i = 0; i < 2; i++)
        #pragma unroll
        for (int j = 0; j < 4; j++)
            #pragma unroll
            for (int e = 0; e < 4; e++) acc[i][j][e] = 0.f;
    mm_core(&sm, Ap + (size_t)bm * DD, F, bn >> 3, acc);

    const int lane = threadIdx.x & 31;
    const int gq = lane >> 2, tq = lane & 3;
    const int w = threadIdx.x >> 5;
    const int wm = w >> 1, wn = w & 1;
    #pragma unroll
    for (int mt = 0; mt < 2; mt++)
        #pragma unroll
        for (int nt = 0; nt < 4; nt++) {
            int row = bm + wm * 32 + mt * 16 + gq;
            int col = bn + wn * 32 + nt * 8 + 2 * tq;
            float b0 = bias ? bias[col] : 0.f;
            float b1 = bias ? bias[col + 1] : 0.f;
            *(float2*)(C + (size_t)row * ldc + col) =
                make_float2(acc[mt][nt][0] + b0, acc[mt][nt][1] + b1);
            *(float2*)(C + (size_t)(row + 8) * ldc + col) =
                make_float2(acc[mt][nt][2] + b0, acc[mt][nt][3] + b1);
        }
}

// ==================================================================
// 256-thread recurrence core: 64 rows x 16 cols, K split across 2 warp-groups
// ==================================================================
struct RSmem2 { u32 A[2][2][16][72]; };   // [buf][k-half][ok][row]  (36 KB)

template<int NG>
__device__ __forceinline__ void rec_core2(
    RSmem2* sm, const u32* __restrict__ Ap,
    const u32* const* Fp, const int* gb,
    float acc[NG][2][4])
{
    const int tid  = threadIdx.x;
    const int lane = tid & 31;
    const int gq = lane >> 2, tq = lane & 3;
    const int w  = tid >> 5;
    const int wk = w >> 2;              // compute k-half
    const int wm = (w >> 1) & 1;
    const int wn = w & 1;
    const int lt = tid & 127;           // loader id within half
    const int lkh = tid >> 7;           // loader k-half
    const int r = lt >> 1, h = lt & 1;

    const u32* arow = Ap + (size_t)r * DD + lkh * 256 + h * 8;

    uint4 bv[NG], nbv[NG], na0, na1;

    uint4 va0 = *(const uint4*)(arow + 0);
    uint4 va1 = *(const uint4*)(arow + 4);
    #pragma unroll
    for (int g = 0; g < NG; g++)
        bv[g] = *(const uint4*)(Fp[g] +
            (((size_t)(gb[g] + wn) * 32 + wk * 16) * 32 + lane) * 4);
    {
        u32 e0[4] = {va0.x, va0.y, va0.z, va0.w};
        u32 e1[4] = {va1.x, va1.y, va1.z, va1.w};
        #pragma unroll
        for (int j = 0; j < 4; j++) {
            int jj = (j + 2 * h) & 3;
            sm->A[0][lkh][h * 8 + 0 + jj][r] = e0[jj];
            sm->A[0][lkh][h * 8 + 4 + jj][r] = e1[jj];
        }
    }
    __syncthreads();

    #pragma unroll 1
    for (int s2 = 0; s2 < 16; s2++) {
        const int buf = s2 & 1;
        if (s2 < 15) {
            const u32* ar = arow + (s2 + 1) * 16;
            na0 = *(const uint4*)(ar);
            na1 = *(const uint4*)(ar + 4);
            #pragma unroll
            for (int g = 0; g < NG; g++)
                nbv[g] = *(const uint4*)(Fp[g] +
                    (((size_t)(gb[g] + wn) * 32 + wk * 16 + s2 + 1) * 32 + lane) * 4);
        }
        #pragma unroll
        for (int sl = 0; sl < 2; sl++) {
            u32 a[2][4], as[2][4];
            #pragma unroll
            for (int mt = 0; mt < 2; mt++) {
                int rb = wm * 32 + mt * 16 + gq;
                a[mt][0] = sm->A[buf][wk][sl * 8 + tq][rb];
                a[mt][1] = sm->A[buf][wk][sl * 8 + tq][rb + 8];
                a[mt][2] = sm->A[buf][wk][sl * 8 + tq + 4][rb];
                a[mt][3] = sm->A[buf][wk][sl * 8 + tq + 4][rb + 8];
                #pragma unroll
                for (int q = 0; q < 4; q++)
                    as[mt][q] = __funnelshift_l(a[mt][q], a[mt][q], 16);
            }
            #pragma unroll
            for (int g = 0; g < NG; g++) {
                u32 b0 = sl ? bv[g].z : bv[g].x;
                u32 b1 = sl ? bv[g].w : bv[g].y;
                #pragma unroll
                for (int mt = 0; mt < 2; mt++) {
                    mma16(acc[g][mt], a[mt],  b0, b1);
                    mma16(acc[g][mt], as[mt], b0, b1);
                }
            }
        }
        if (s2 < 15) {
            u32 e0[4] = {na0.x, na0.y, na0.z, na0.w};
            u32 e1[4] = {na1.x, na1.y, na1.z, na1.w};
            #pragma unroll
            for (int j = 0; j < 4; j++) {
                int jj = (j + 2 * h) & 3;
                sm->A[buf ^ 1][lkh][h * 8 + 0 + jj][r] = e0[jj];
                sm->A[buf ^ 1][lkh][h * 8 + 4 + jj][r] = e1[jj];
            }
            #pragma unroll
            for (int g = 0; g < NG; g++) bv[g] = nbv[g];
        }
        __syncthreads();
    }

    // reduce wk=1 partials into wk=0 threads (padded stride: conflict-light)
    float* red = (float*)sm;
    const int stride = NG * 8 + 1;
    if (wk == 1) {
        int base = (tid - 128) * stride;
        #pragma unroll
        for (int g = 0; g < NG; g++)
            #pragma unroll
            for (int i = 0; i < 2; i++)
                #pragma unroll
                for (int e = 0; e < 4; e++)
                    red[base + (g * 2 + i) * 4 + e] = acc[g][i][e];
    }
    __syncthreads();
    if (wk == 0) {
        int base = tid * stride;
        #pragma unroll
        for (int g = 0; g < NG; g++)
            #pragma unroll
            for (int i = 0; i < 2; i++)
                #pragma unroll
                for (int e = 0; e < 4; e++)
                    acc[g][i][e] += red[base + (g * 2 + i) * 4 + e];
    }
    __syncthreads();
}

#define REC_VARS() \
    const int lane_ = threadIdx.x & 31; \
    const int gq_ = lane_ >> 2, tq_ = lane_ & 3; \
    const int w_ = threadIdx.x >> 5; \
    const int wm_ = (w_ >> 1) & 1, wn_ = w_ & 1;

// ---------------- persistent GRU (128 blocks x 256 thr, 64x16 tiles, K-split) ----------------
#define RECB 128
__global__ __launch_bounds__(256) void gru2(
    const float* __restrict__ zero, const u32* __restrict__ Pzero,
    const u32* __restrict__ Fwhh, const float* __restrict__ bhh,
    const float* __restrict__ xproj,
    float* __restrict__ sseq, u32* __restrict__ Psseq)
{
    __shared__ RSmem2 sm;
    const int blk = blockIdx.x;
    const int mi = blk >> 5, di = blk & 31;        // 4 row-tiles x 32 col-tiles
    const int bm = mi * 64, bnd = di * 16;
    REC_VARS();

    const u32* Fp[3] = {Fwhh, Fwhh, Fwhh};
    int gb[3] = {di * 2, 64 + di * 2, 128 + di * 2};

    const int col = bnd + wn_ * 8 + 2 * tq_;
    float bh[3][2];
    #pragma unroll
    for (int g = 0; g < 3; g++) {
        bh[g][0] = bhh[g * 512 + col];
        bh[g][1] = bhh[g * 512 + col + 1];
    }

    for (int l = 0; l < LL; l++) {
        const u32* Ap = (l ? Psseq + (size_t)(l - 1) * BBDD : Pzero) + (size_t)bm * DD;
        float acc[3][2][4];
        #pragma unroll
        for (int g = 0; g < 3; g++)
            #pragma unroll
            for (int i = 0; i < 2; i++)
                #pragma unroll
                for (int e = 0; e < 4; e++) acc[g][i][e] = 0.f;

        rec_core2<3>(&sm, Ap, Fp, gb, acc);

        if (threadIdx.x < 128) {
            const float* hprev = l ? sseq + (size_t)(l - 1) * BBDD : zero;
            float* sl_ = sseq + (size_t)l * BBDD;
            u32* pl = Psseq + (size_t)l * BBDD;

            #pragma unroll
            for (int mt = 0; mt < 2; mt++)
                #pragma unroll
                for (int half = 0; half < 2; half++) {
                    int row = bm + wm_ * 32 + mt * 16 + gq_ + half * 8;
                    const float* xb = xproj + ((size_t)row * LL + l) * 1536;
                    size_t ix = (size_t)row * DD + col;
                    #pragma unroll
                    for (int c = 0; c < 2; c++) {
                        int e = half * 2 + c;
                        float rr = sigf(xb[col + c] + acc[0][mt][e] + bh[0][c]);
                        float zz = sigf(xb[512 + col + c] + acc[1][mt][e] + bh[1][c]);
                        float nn = tanhf(xb[1024 + col + c] + rr * (acc[2][mt][e] + bh[2][c]));
                        float h0 = hprev[ix + c];
                        float hn = nn + zz * (h0 - nn);
                        sl_[ix + c] = hn;
                        pl[ix + c] = packbf(hn);
                    }
                }
        }

        grid_barrier(RECB);
    }
}

// ---------------- persistent AUGRU (128 blocks x 256 thr, K-split) ----------------
__global__ __launch_bounds__(256) void augru2(
    const float* __restrict__ hlast, const u32* __restrict__ Pinit,
    const u32* __restrict__ Frh, const u32* __restrict__ Fuh, const u32* __restrict__ Fhh,
    const float* __restrict__ rx, const float* __restrict__ ux, const float* __restrict__ nx,
    const float* __restrict__ att,
    float* __restrict__ hf, u32* __restrict__ Pp,
    u32* __restrict__ Phr, float* __restrict__ ue,
    float* __restrict__ out)
{
    __shared__ RSmem2 sm;
    const int blk = blockIdx.x;
    const int mi = blk >> 5, di = blk & 31;
    const int bm = mi * 64, bnd = di * 16;
    REC_VARS();
    const int col = bnd + wn_ * 8 + 2 * tq_;

    for (int l = 0; l < LL; l++) {
        const float* hc = l ? hf + (size_t)(l & 1) * BBDD : hlast;
        const u32* Pc = l ? Pp + (size_t)(l & 1) * BBDD : Pinit;

        {   // phase A: r and u_eff
            const u32* Fp[2] = {Frh, Fuh};
            int gb[2] = {di * 2, di * 2};
            float acc[2][2][4];
            #pragma unroll
            for (int g = 0; g < 2; g++)
                #pragma unroll
                for (int i = 0; i < 2; i++)
                    #pragma unroll
                    for (int e = 0; e < 4; e++) acc[g][i][e] = 0.f;

            rec_core2<2>(&sm, Pc + (size_t)bm * DD, Fp, gb, acc);

            if (threadIdx.x < 128) {
                const float* rxl = rx + (size_t)l * BBDD;
                const float* uxl = ux + (size_t)l * BBDD;
                #pragma unroll
                for (int mt = 0; mt < 2; mt++)
                    #pragma unroll
                    for (int half = 0; half < 2; half++) {
                        int row = bm + wm_ * 32 + mt * 16 + gq_ + half * 8;
                        size_t ix = (size_t)row * DD + col;
                        float a = att[(size_t)l * BB + row];
                        #pragma unroll
                        for (int c = 0; c < 2; c++) {
                            int e = half * 2 + c;
                            float vr = acc[0][mt][e] + rxl[ix + c];
                            float vu = acc[1][mt][e] + uxl[ix + c];
                            Phr[ix + c] = packbf(hc[ix + c] * sigf(vr));
                            ue[ix + c]  = a * sigf(vu);
                        }
                    }
            }
        }

        grid_barrier(RECB);

        {   // phase B: hhat + output update
            const u32* Fp[1] = {Fhh};
            int gb[1] = {di * 2};
            float acc[1][2][4];
            #pragma unroll
            for (int i = 0; i < 2; i++)
                #pragma unroll
                for (int e = 0; e < 4; e++) acc[0][i][e] = 0.f;

            rec_core2<1>(&sm, Phr + (size_t)bm * DD, Fp, gb, acc);

            if (threadIdx.x < 128) {
                float* ho = (l == LL - 1) ? out : hf + (size_t)((l + 1) & 1) * BBDD;
                u32* Pn = Pp + (size_t)((l + 1) & 1) * BBDD;
                const float* nxl = nx + (size_t)l * BBDD;
                #pragma unroll
                for (int mt = 0; mt < 2; mt++)
                    #pragma unroll
                    for (int half = 0; half < 2; half++) {
                        int row = bm + wm_ * 32 + mt * 16 + gq_ + half * 8;
                        size_t ix = (size_t)row * DD + col;
                        #pragma unroll
                        for (int c = 0; c < 2; c++) {
                            int e = half * 2 + c;
                            float hh = tanhf(acc[0][mt][e] + nxl[ix + c]);
                            float h0 = hc[ix + c];
                            float u0 = ue[ix + c];
                            float hn = h0 + u0 * (hh - h0);
                            ho[ix + c] = hn;
                            Pn[ix + c] = packbf(hn);
                        }
                    }
            }
        }

        grid_barrier(RECB);
    }
}

// ---------------- conversion kernels ----------------
__global__ void pack_zero_kernel(const float* __restrict__ x, u32* __restrict__ p, int n4,
                                 float* __restrict__ z, int zn4)
{
    int i = blockIdx.x * 256 + threadIdx.x;
    if (i < n4) {
        float4 v = ((const float4*)x)[i];
        uint4 o;
        o.x = packbf(v.x); o.y = packbf(v.y); o.z = packbf(v.z); o.w = packbf(v.w);
        ((uint4*)p)[i] = o;
    }
    if (i < zn4) ((float4*)z)[i] = make_float4(0.f, 0.f, 0.f, 0.f);
}

__global__ void pack_kernel(const float* __restrict__ x, u32* __restrict__ p, int n4)
{
    int i = blockIdx.x * 256 + threadIdx.x;
    if (i < n4) {
        float4 v = ((const float4*)x)[i];
        uint4 o;
        o.x = packbf(v.x); o.y = packbf(v.y); o.z = packbf(v.z); o.w = packbf(v.w);
        ((uint4*)p)[i] = o;
    }
}

__device__ __forceinline__ void wfrag_one(const float* W, int ldw, int woff,
                                          u32* F, int idx)
{
    int j = idx & 3, lane = (idx >> 2) & 31, s2 = (idx >> 7) & 31, gnt = idx >> 12;
    int g = lane >> 2, t = lane & 3;
    int sl = s2 * 2 + (j >> 1), b = j & 1;
    int ok = sl * 8 + t + 4 * b;
    int n = gnt * 8 + g;
    F[idx] = packbf(W[(size_t)n * ldw + woff + ok]);
}

// both wih and whh in one launch
__global__ void wfrag2_kernel(const float* __restrict__ W1, const float* __restrict__ W2,
                              u32* __restrict__ F1, u32* __restrict__ F2, int total)
{
    int idx0 = blockIdx.x * 256 + threadIdx.x;
    if (idx0 < total)               wfrag_one(W1, DD, 0, F1, idx0);
    else if (idx0 < 2 * total)      wfrag_one(W2, DD, 0, F2, idx0 - total);
}

__global__ void wfrag_kernel(const float* __restrict__ W, int ldw, int woff,
                             u32* __restrict__ F, int total)
{
    int idx = blockIdx.x * 256 + threadIdx.x;
    if (idx < total) wfrag_one(W, ldw, woff, F, idx);
}

// ---------------- attention ----------------
__global__ void attn_logits(const float* __restrict__ s, const float* __restrict__ u,
                            float* __restrict__ logits)
{
    int gw = (blockIdx.x * blockDim.x + threadIdx.x) >> 5;
    int lane = threadIdx.x & 31;
    int b = gw & (BB - 1);
    const float4* sr = (const float4*)(s + (size_t)gw * DD);
    const float4* ur = (const float4*)(u + (size_t)b * DD);
    float acc = 0.f;
    #pragma unroll
    for (int k = lane; k < DD / 4; k += 32) {
        float4 a = sr[k], c = ur[k];
        acc += a.x * c.x + a.y * c.y + a.z * c.z + a.w * c.w;
    }
    #pragma unroll
    for (int o = 16; o > 0; o >>= 1) acc += __shfl_xor_sync(0xffffffffu, acc, o);
    if (lane == 0) logits[gw] = acc;
}

__global__ void attn_softmax(const float* __restrict__ logits, float* __restrict__ att)
{
    int b = blockIdx.x, t = threadIdx.x;
    __shared__ float red[256];
    float v = (t < LL) ? logits[t * BB + b] : -1e30f;
    red[t] = v;
    __syncthreads();
    for (int s = 128; s > 0; s >>= 1) {
        if (t < s) red[t] = fmaxf(red[t], red[t + s]);
        __syncthreads();
    }
    float mx = red[0];
    __syncthreads();
    float e = (t < LL) ? expf(v - mx) : 0.f;
    red[t] = e;
    __syncthreads();
    for (int s = 128; s > 0; s >>= 1) {
        if (t < s) red[t] += red[t + s];
        __syncthreads();
    }
    float inv = 1.f / red[0];
    if (t < LL) att[t * BB + b] = e * inv;
}

// ---------------- host ----------------
extern "C" void kernel_launch(void* const* d_in, const int* in_sizes, int n_in,
                              void* d_out, int out_size)
{
    const float* session  = (const float*)d_in[0];
    const float* target   = (const float*)d_in[1];
    const float* w        = (const float*)d_in[2];
    const float* wih      = (const float*)d_in[3];
    const float* whh      = (const float*)d_in[4];
    const float* bih      = (const float*)d_in[5];
    const float* bhh      = (const float*)d_in[6];
    const float* reset_w  = (const float*)d_in[7];
    const float* reset_b  = (const float*)d_in[8];
    const float* update_w = (const float*)d_in[9];
    const float* update_b = (const float*)d_in[10];
    const float* hhat_w   = (const float*)d_in[11];
    const float* hhat_b   = (const float*)d_in[12];
    float* out = (float*)d_out;

    float *xproj, *sseq, *rx, *ux, *nx, *u, *logits, *att, *ue, *hf, *zero;
    u32 *Psess, *Ptar, *Psseq, *Phr, *Pp;
    u32 *Fwih, *Fwhh, *Fw, *Frh, *Fuh, *Fhh, *Frx, *Fux, *Fhx;

    cudaGetSymbolAddress((void**)&xproj,  g_xproj);
    cudaGetSymbolAddress((void**)&sseq,   g_sseq);
    cudaGetSymbolAddress((void**)&rx,     g_rx);
    cudaGetSymbolAddress((void**)&ux,     g_ux);
    cudaGetSymbolAddress((void**)&nx,     g_nx);
    cudaGetSymbolAddress((void**)&u,      g_u);
    cudaGetSymbolAddress((void**)&logits, g_logits);
    cudaGetSymbolAddress((void**)&att,    g_att);
    cudaGetSymbolAddress((void**)&ue,     g_ue);
    cudaGetSymbolAddress((void**)&hf,     g_hf);
    cudaGetSymbolAddress((void**)&zero,   g_zero);
    cudaGetSymbolAddress((void**)&Psess,  g_Psess);
    cudaGetSymbolAddress((void**)&Ptar,   g_Ptar);
    cudaGetSymbolAddress((void**)&Psseq,  g_Psseq);
    cudaGetSymbolAddress((void**)&Phr,    g_Phr);
    cudaGetSymbolAddress((void**)&Pp,     g_Pp);
    cudaGetSymbolAddress((void**)&Fwih,   g_Fwih);
    cudaGetSymbolAddress((void**)&Fwhh,   g_Fwhh);
    cudaGetSymbolAddress((void**)&Fw,     g_Fw);
    cudaGetSymbolAddress((void**)&Frh,    g_Frh);
    cudaGetSymbolAddress((void**)&Fuh,    g_Fuh);
    cudaGetSymbolAddress((void**)&Fhh,    g_Fhh);
    cudaGetSymbolAddress((void**)&Frx,    g_Frx);
    cudaGetSymbolAddress((void**)&Fux,    g_Fux);
    cudaGetSymbolAddress((void**)&Fhx,    g_Fhx);

    // launch 1: pack session + zero buffer
    pack_zero_kernel<<<(BB * LL * DD / 4 + 255) / 256, 256>>>(
        session, Psess, BB * LL * DD / 4, zero, BB * DD / 4);
    // launch 2: both GRU weight fragment sets
    wfrag2_kernel<<<(2 * 1536 * DD + 255) / 256, 256>>>(wih, whh, Fwih, Fwhh, 1536 * DD);
    // launch 3: x_proj
    {
        dim3 g(BB * LL / 128, 3 * DD / 64);
        mm_big<<<g, 256>>>(Psess, Fwih, bih, xproj, 3 * DD);
    }
    // launch 4: persistent GRU  <- ncu capture slot
    gru2<<<RECB, 256>>>(zero, (const u32*)zero, Fwhh, bhh, xproj, sseq, Psseq);

    // remaining prep
    pack_kernel<<<(BB * DD / 4 + 255) / 256, 256>>>(target, Ptar, BB * DD / 4);
    wfrag_kernel<<<(DD * DD + 255) / 256, 256>>>(w,        DD,     0,  Fw,  DD * DD);
    wfrag_kernel<<<(DD * DD + 255) / 256, 256>>>(reset_w,  2 * DD, 0,  Frh, DD * DD);
    wfrag_kernel<<<(DD * DD + 255) / 256, 256>>>(update_w, 2 * DD, 0,  Fuh, DD * DD);
    wfrag_kernel<<<(DD * DD + 255) / 256, 256>>>(hhat_w,   2 * DD, 0,  Fhh, DD * DD);
    wfrag_kernel<<<(DD * DD + 255) / 256, 256>>>(reset_w,  2 * DD, DD, Frx, DD * DD);
    wfrag_kernel<<<(DD * DD + 255) / 256, 256>>>(update_w, 2 * DD, DD, Fux, DD * DD);
    wfrag_kernel<<<(DD * DD + 255) / 256, 256>>>(hhat_w,   2 * DD, DD, Fhx, DD * DD);

    // u = target @ w^T
    {
        dim3 g(BB / 128, DD / 64);
        mm_big<<<g, 256>>>(Ptar, Fw, nullptr, u, DD);
    }
    // AUGRU x-projections (biases folded)
    {
        dim3 g(BB * LL / 128, DD / 64);
        mm_big<<<g, 256>>>(Psseq, Frx, reset_b,  rx, DD);
        mm_big<<<g, 256>>>(Psseq, Fux, update_b, ux, DD);
        mm_big<<<g, 256>>>(Psseq, Fhx, hhat_b,   nx, DD);
    }
    // attention
    attn_logits<<<LL * BB / 8, 256>>>(sseq, u, logits);
    attn_softmax<<<BB, 256>>>(logits, att);

    // persistent AUGRU; init h = sseq[L-1]
    augru2<<<RECB, 256>>>(sseq + (size_t)(LL - 1) * BBDD,
                          Psseq + (size_t)(LL - 1) * BBDD,
                          Frh, Fuh, Fhh,
                          rx, ux, nx, att,
                          hf, Pp, Phr, ue, out);
}

// round 12
// speedup vs baseline: 2.2405x; 1.0369x over previous
#include <cuda_runtime.h>
#include <cuda_bf16.h>
#include <math.h>
#include <stdint.h>

#define BB 256
#define LL 200
#define DD 512
#define BBDD (BB * DD)
typedef uint32_t u32;

// ---------------- fp32 scratch ----------------
__device__ float g_xproj[(size_t)BB * LL * 3 * DD];   // [B,L,3D] (+bih)
__device__ float g_sseq [(size_t)LL * BB * DD];       // [L,B,D]
__device__ float g_rx   [(size_t)LL * BB * DD];
__device__ float g_ux   [(size_t)LL * BB * DD];
__device__ float g_nx   [(size_t)LL * BB * DD];
__device__ float g_u    [BB * DD];
__device__ float g_logits[LL * BB];
__device__ float g_att   [LL * BB];
__device__ float g_ue    [BB * DD];
__device__ float g_hf    [2 * BB * DD];
__device__ float g_zero  [BB * DD];                   // fp32 zeros == packed zeros

// ---------------- packed (bf16-pair) activations ----------------
__device__ u32 g_Psess[(size_t)BB * LL * DD];
__device__ u32 g_Ptar [BB * DD];
__device__ u32 g_Psseq[(size_t)LL * BB * DD];
__device__ u32 g_Phr  [BB * DD];
__device__ u32 g_Pp   [2 * BB * DD];

// ---------------- weight fragments (B-operand order) ----------------
__device__ u32 g_Fwih[1536 * DD];
__device__ u32 g_Fwhh[1536 * DD];
__device__ u32 g_Fw  [DD * DD];
__device__ u32 g_Frh [DD * DD];
__device__ u32 g_Fuh [DD * DD];
__device__ u32 g_Fhh [DD * DD];
__device__ u32 g_Frx [DD * DD];
__device__ u32 g_Fux [DD * DD];
__device__ u32 g_Fhx [DD * DD];

// grid barrier
__device__ unsigned int          g_cnt = 0;
__device__ volatile unsigned int g_gen = 0;

__device__ __forceinline__ float sigf(float x) { return 1.0f / (1.0f + __expf(-x)); }

__device__ __forceinline__ u32 packbf(float x) {
    __nv_bfloat16 hi = __float2bfloat16(x);
    float hf = __bfloat162float(hi);
    __nv_bfloat16 lo = __float2bfloat16(x - hf);
    return (u32)__bfloat16_as_ushort(hi) | ((u32)__bfloat16_as_ushort(lo) << 16);
}

__device__ __forceinline__ void grid_barrier(int nb) {
    __syncthreads();
    if (threadIdx.x == 0) {
        __threadfence();
        unsigned int gen = g_gen;
        unsigned int old = atomicAdd(&g_cnt, 1u);
        if (old == (unsigned)(nb - 1)) {
            atomicExch(&g_cnt, 0u);
            __threadfence();
            atomicAdd((unsigned int*)&g_gen, 1u);
        } else {
            while (g_gen == gen) { }
        }
        __threadfence();
    }
    __syncthreads();
}

__device__ __forceinline__ void mma16(float* d, const u32* a, u32 b0, u32 b1) {
    asm volatile(
        "mma.sync.aligned.m16n8k16.row.col.f32.bf16.bf16.f32 "
        "{%0,%1,%2,%3},{%4,%5,%6,%7},{%8,%9},{%0,%1,%2,%3};"
        : "+f"(d[0]), "+f"(d[1]), "+f"(d[2]), "+f"(d[3])
        : "r"(a[0]), "r"(a[1]), "r"(a[2]), "r"(a[3]), "r"(b0), "r"(b1));
}

// ==================================================================
// 256-thread 128x64 core (unchanged — proven)
// ==================================================================
struct MMSmem { u32 A[2][16][136]; };

__device__ __forceinline__ void mm_core(
    MMSmem* sm, const u32* __restrict__ Ap,
    const u32* __restrict__ F, int gnt0,
    float acc[2][4][4])
{
    const int tid  = threadIdx.x;
    const int lane = tid & 31;
    const int gq = lane >> 2, tq = lane & 3;
    const int w  = tid >> 5;
    const int wm = w >> 1, wn = w & 1;
    const int r  = tid >> 1, h = tid & 1;

    const u32* arow = Ap + (size_t)r * DD + h * 8;

    uint4 bv[4], nbv[4], na0, na1;

    uint4 va0 = *(const uint4*)(arow + 0);
    uint4 va1 = *(const uint4*)(arow + 4);
    #pragma unroll
    for (int nt = 0; nt < 4; nt++) {
        int gnt = gnt0 + wn * 4 + nt;
        bv[nt] = *(const uint4*)(F + (((size_t)gnt * 32 + 0) * 32 + lane) * 4);
    }
    {
        u32 e0[4] = {va0.x, va0.y, va0.z, va0.w};
        u32 e1[4] = {va1.x, va1.y, va1.z, va1.w};
        #pragma unroll
        for (int j = 0; j < 4; j++) {
            int jj = (j + 2 * h) & 3;
            sm->A[0][h * 8 + 0 + jj][r] = e0[jj];
            sm->A[0][h * 8 + 4 + jj][r] = e1[jj];
        }
    }
    __syncthreads();

    #pragma unroll 1
    for (int s2 = 0; s2 < 32; s2++) {
        const int buf = s2 & 1;
        if (s2 < 31) {
            const u32* ar = arow + (s2 + 1) * 16;
            na0 = *(const uint4*)(ar);
            na1 = *(const uint4*)(ar + 4);
            #pragma unroll
            for (int nt = 0; nt < 4; nt++) {
                int gnt = gnt0 + wn * 4 + nt;
                nbv[nt] = *(const uint4*)(F + (((size_t)gnt * 32 + (s2 + 1)) * 32 + lane) * 4);
            }
        }
        #pragma unroll
        for (int sl = 0; sl < 2; sl++) {
            u32 a[2][4], as[2][4];
            #pragma unroll
            for (int mt = 0; mt < 2; mt++) {
                int rb = wm * 32 + mt * 16 + gq;
                a[mt][0] = sm->A[buf][sl * 8 + tq][rb];
                a[mt][1] = sm->A[buf][sl * 8 + tq][rb + 8];
                a[mt][2] = sm->A[buf][sl * 8 + tq + 4][rb];
                a[mt][3] = sm->A[buf][sl * 8 + tq + 4][rb + 8];
                #pragma unroll
                for (int q = 0; q < 4; q++)
                    as[mt][q] = __funnelshift_l(a[mt][q], a[mt][q], 16);
            }
            #pragma unroll
            for (int nt = 0; nt < 4; nt++) {
                u32 b0 = sl ? bv[nt].z : bv[nt].x;
                u32 b1 = sl ? bv[nt].w : bv[nt].y;
                #pragma unroll
                for (int mt = 0; mt < 2; mt++) {
                    mma16(acc[mt][nt], a[mt],  b0, b1);
                    mma16(acc[mt][nt], as[mt], b0, b1);
                }
            }
        }
        if (s2 < 31) {
            u32 e0[4] = {na0.x, na0.y, na0.z, na0.w};
            u32 e1[4] = {na1.x, na1.y, na1.z, na1.w};
            #pragma unroll
            for (int j = 0; j < 4; j++) {
                int jj = (j + 2 * h) & 3;
                sm->A[buf ^ 1][h * 8 + 0 + jj][r] = e0[jj];
                sm->A[buf ^ 1][h * 8 + 4 + jj][r] = e1[jj];
            }
            #pragma unroll
            for (int nt = 0; nt < 4; nt++) bv[nt] = nbv[nt];
        }
        __syncthreads();
    }
}

__global__ __launch_bounds__(256) void mm_big(
    const u32* __restrict__ Ap,
    const u32* __restrict__ F,
    const float* __restrict__ bias,
    float* __restrict__ C, int ldc)
{
    __shared__ MMSmem sm;
    const int bm = blockIdx.x * 128, bn = blockIdx.y * 64;
    float acc[2][4][4];
    #pragma unroll
    for (int i = 0; i < 2; i++)
        #pragma unroll
        for (int j = 0; j < 4; j++)
            #pragma unroll
            for (int e = 0; e < 4; e++) acc[i][j][e] = 0.f;
    mm_core(&sm, Ap + (size_t)bm * DD, F, bn >> 3, acc);

    const int lane = threadIdx.x & 31;
    const int gq = lane >> 2, tq = lane & 3;
    const int w = threadIdx.x >> 5;
    const int wm = w >> 1, wn = w & 1;
    #pragma unroll
    for (int mt = 0; mt < 2; mt++)
        #pragma unroll
        for (int nt = 0; nt < 4; nt++) {
            int row = bm + wm * 32 + mt * 16 + gq;
            int col = bn + wn * 32 + nt * 8 + 2 * tq;
            float b0 = bias ? bias[col] : 0.f;
            float b1 = bias ? bias[col + 1] : 0.f;
            *(float2*)(C + (size_t)row * ldc + col) =
                make_float2(acc[mt][nt][0] + b0, acc[mt][nt][1] + b1);
            *(float2*)(C + (size_t)(row + 8) * ldc + col) =
                make_float2(acc[mt][nt][2] + b0, acc[mt][nt][3] + b1);
        }
}

// ==================================================================
// 512-thread recurrence core: 64 rows x 16 cols, K split across 4 warp-groups
// ==================================================================
struct RSmem4 {
    union {
        u32 A[2][4][16][72];        // [buf][k-quarter][ok][row]  36864 B
        float red[3 * 128 * 25];    // reduction scratch          38400 B
    };
};

template<int NG>
__device__ __forceinline__ void rec_core4(
    RSmem4* sm, const u32* __restrict__ Ap,
    const u32* const* Fp, const int* gb,
    float acc[NG][2][4])
{
    const int tid  = threadIdx.x;
    const int lane = tid & 31;
    const int gq = lane >> 2, tq = lane & 3;
    const int w  = tid >> 5;            // 0..15
    const int wk = w >> 2;              // compute k-quarter
    const int wm = (w >> 1) & 1;
    const int wn = w & 1;
    const int lt = tid & 127;           // loader id within quarter
    const int lkh = tid >> 7;           // loader k-quarter
    const int r = lt >> 1, h = lt & 1;

    const u32* arow = Ap + (size_t)r * DD + lkh * 128 + h * 8;

    uint4 bv[NG], nbv[NG], na0, na1;

    uint4 va0 = *(const uint4*)(arow + 0);
    uint4 va1 = *(const uint4*)(arow + 4);
    #pragma unroll
    for (int g = 0; g < NG; g++)
        bv[g] = *(const uint4*)(Fp[g] +
            (((size_t)(gb[g] + wn) * 32 + wk * 8) * 32 + lane) * 4);
    {
        u32 e0[4] = {va0.x, va0.y, va0.z, va0.w};
        u32 e1[4] = {va1.x, va1.y, va1.z, va1.w};
        #pragma unroll
        for (int j = 0; j < 4; j++) {
            int jj = (j + 2 * h) & 3;
            sm->A[0][lkh][h * 8 + 0 + jj][r] = e0[jj];
            sm->A[0][lkh][h * 8 + 4 + jj][r] = e1[jj];
        }
    }
    __syncthreads();

    #pragma unroll 1
    for (int s2 = 0; s2 < 8; s2++) {
        const int buf = s2 & 1;
        if (s2 < 7) {
            const u32* ar = arow + (s2 + 1) * 16;
            na0 = *(const uint4*)(ar);
            na1 = *(const uint4*)(ar + 4);
            #pragma unroll
            for (int g = 0; g < NG; g++)
                nbv[g] = *(const uint4*)(Fp[g] +
                    (((size_t)(gb[g] + wn) * 32 + wk * 8 + s2 + 1) * 32 + lane) * 4);
        }
        #pragma unroll
        for (int sl = 0; sl < 2; sl++) {
            u32 a[2][4], as[2][4];
            #pragma unroll
            for (int mt = 0; mt < 2; mt++) {
                int rb = wm * 32 + mt * 16 + gq;
                a[mt][0] = sm->A[buf][wk][sl * 8 + tq][rb];
                a[mt][1] = sm->A[buf][wk][sl * 8 + tq][rb + 8];
                a[mt][2] = sm->A[buf][wk][sl * 8 + tq + 4][rb];
                a[mt][3] = sm->A[buf][wk][sl * 8 + tq + 4][rb + 8];
                #pragma unroll
                for (int q = 0; q < 4; q++)
                    as[mt][q] = __funnelshift_l(a[mt][q], a[mt][q], 16);
            }
            #pragma unroll
            for (int g = 0; g < NG; g++) {
                u32 b0 = sl ? bv[g].z : bv[g].x;
                u32 b1 = sl ? bv[g].w : bv[g].y;
                #pragma unroll
                for (int mt = 0; mt < 2; mt++) {
                    mma16(acc[g][mt], a[mt],  b0, b1);
                    mma16(acc[g][mt], as[mt], b0, b1);
                }
            }
        }
        if (s2 < 7) {
            u32 e0[4] = {na0.x, na0.y, na0.z, na0.w};
            u32 e1[4] = {na1.x, na1.y, na1.z, na1.w};
            #pragma unroll
            for (int j = 0; j < 4; j++) {
                int jj = (j + 2 * h) & 3;
                sm->A[buf ^ 1][lkh][h * 8 + 0 + jj][r] = e0[jj];
                sm->A[buf ^ 1][lkh][h * 8 + 4 + jj][r] = e1[jj];
            }
            #pragma unroll
            for (int g = 0; g < NG; g++) bv[g] = nbv[g];
        }
        __syncthreads();
    }

    // reduce wk=1..3 partials into wk=0 threads (stride 25: conflict-free)
    const int stride = NG * 8 + 1;
    if (wk) {
        int base = (tid - 128) * stride;     // (wk-1)*128 + lt, contiguous
        #pragma unroll
        for (int g = 0; g < NG; g++)
            #pragma unroll
            for (int i = 0; i < 2; i++)
                #pragma unroll
                for (int e = 0; e < 4; e++)
                    sm->red[base + (g * 2 + i) * 4 + e] = acc[g][i][e];
    }
    __syncthreads();
    if (!wk) {
        #pragma unroll
        for (int k = 0; k < 3; k++) {
            int base = (k * 128 + tid) * stride;
            #pragma unroll
            for (int g = 0; g < NG; g++)
                #pragma unroll
                for (int i = 0; i < 2; i++)
                    #pragma unroll
                    for (int e = 0; e < 4; e++)
                        acc[g][i][e] += sm->red[base + (g * 2 + i) * 4 + e];
        }
    }
    __syncthreads();
}

#define REC_VARS() \
    const int lane_ = threadIdx.x & 31; \
    const int gq_ = lane_ >> 2, tq_ = lane_ & 3; \
    const int w_ = threadIdx.x >> 5; \
    const int wm_ = (w_ >> 1) & 1, wn_ = w_ & 1;

// ---------------- persistent GRU (128 blocks x 512 thr, 64x16 tiles, 4-way K) ----------------
#define RECB 128
__global__ __launch_bounds__(512) void gru2(
    const float* __restrict__ zero, const u32* __restrict__ Pzero,
    const u32* __restrict__ Fwhh, const float* __restrict__ bhh,
    const float* __restrict__ xproj,
    float* __restrict__ sseq, u32* __restrict__ Psseq)
{
    __shared__ RSmem4 sm;
    const int blk = blockIdx.x;
    const int mi = blk >> 5, di = blk & 31;        // 4 row-tiles x 32 col-tiles
    const int bm = mi * 64, bnd = di * 16;
    REC_VARS();

    const u32* Fp[3] = {Fwhh, Fwhh, Fwhh};
    int gb[3] = {di * 2, 64 + di * 2, 128 + di * 2};

    const int col = bnd + wn_ * 8 + 2 * tq_;
    float bh[3][2];
    #pragma unroll
    for (int g = 0; g < 3; g++) {
        bh[g][0] = bhh[g * 512 + col];
        bh[g][1] = bhh[g * 512 + col + 1];
    }

    for (int l = 0; l < LL; l++) {
        const u32* Ap = (l ? Psseq + (size_t)(l - 1) * BBDD : Pzero) + (size_t)bm * DD;
        float acc[3][2][4];
        #pragma unroll
        for (int g = 0; g < 3; g++)
            #pragma unroll
            for (int i = 0; i < 2; i++)
                #pragma unroll
                for (int e = 0; e < 4; e++) acc[g][i][e] = 0.f;

        rec_core4<3>(&sm, Ap, Fp, gb, acc);

        if (threadIdx.x < 128) {
            const float* hprev = l ? sseq + (size_t)(l - 1) * BBDD : zero;
            float* sl_ = sseq + (size_t)l * BBDD;
            u32* pl = Psseq + (size_t)l * BBDD;

            #pragma unroll
            for (int mt = 0; mt < 2; mt++)
                #pragma unroll
                for (int half = 0; half < 2; half++) {
                    int row = bm + wm_ * 32 + mt * 16 + gq_ + half * 8;
                    const float* xb = xproj + ((size_t)row * LL + l) * 1536;
                    size_t ix = (size_t)row * DD + col;
                    #pragma unroll
                    for (int c = 0; c < 2; c++) {
                        int e = half * 2 + c;
                        float rr = sigf(xb[col + c] + acc[0][mt][e] + bh[0][c]);
                        float zz = sigf(xb[512 + col + c] + acc[1][mt][e] + bh[1][c]);
                        float nn = tanhf(xb[1024 + col + c] + rr * (acc[2][mt][e] + bh[2][c]));
                        float h0 = hprev[ix + c];
                        float hn = nn + zz * (h0 - nn);
                        sl_[ix + c] = hn;
                        pl[ix + c] = packbf(hn);
                    }
                }
        }

        grid_barrier(RECB);
    }
}

// ---------------- persistent AUGRU (128 blocks x 512 thr, 4-way K) ----------------
__global__ __launch_bounds__(512) void augru2(
    const float* __restrict__ hlast, const u32* __restrict__ Pinit,
    const u32* __restrict__ Frh, const u32* __restrict__ Fuh, const u32* __restrict__ Fhh,
    const float* __restrict__ rx, const float* __restrict__ ux, const float* __restrict__ nx,
    const float* __restrict__ att,
    float* __restrict__ hf, u32* __restrict__ Pp,
    u32* __restrict__ Phr, float* __restrict__ ue,
    float* __restrict__ out)
{
    __shared__ RSmem4 sm;
    const int blk = blockIdx.x;
    const int mi = blk >> 5, di = blk & 31;
    const int bm = mi * 64, bnd = di * 16;
    REC_VARS();
    const int col = bnd + wn_ * 8 + 2 * tq_;

    for (int l = 0; l < LL; l++) {
        const float* hc = l ? hf + (size_t)(l & 1) * BBDD : hlast;
        const u32* Pc = l ? Pp + (size_t)(l & 1) * BBDD : Pinit;

        {   // phase A: r and u_eff
            const u32* Fp[2] = {Frh, Fuh};
            int gb[2] = {di * 2, di * 2};
            float acc[2][2][4];
            #pragma unroll
            for (int g = 0; g < 2; g++)
                #pragma unroll
                for (int i = 0; i < 2; i++)
                    #pragma unroll
                    for (int e = 0; e < 4; e++) acc[g][i][e] = 0.f;

            rec_core4<2>(&sm, Pc + (size_t)bm * DD, Fp, gb, acc);

            if (threadIdx.x < 128) {
                const float* rxl = rx + (size_t)l * BBDD;
                const float* uxl = ux + (size_t)l * BBDD;
                #pragma unroll
                for (int mt = 0; mt < 2; mt++)
                    #pragma unroll
                    for (int half = 0; half < 2; half++) {
                        int row = bm + wm_ * 32 + mt * 16 + gq_ + half * 8;
                        size_t ix = (size_t)row * DD + col;
                        float a = att[(size_t)l * BB + row];
                        #pragma unroll
                        for (int c = 0; c < 2; c++) {
                            int e = half * 2 + c;
                            float vr = acc[0][mt][e] + rxl[ix + c];
                            float vu = acc[1][mt][e] + uxl[ix + c];
                            Phr[ix + c] = packbf(hc[ix + c] * sigf(vr));
                            ue[ix + c]  = a * sigf(vu);
                        }
                    }
            }
        }

        grid_barrier(RECB);

        {   // phase B: hhat + output update
            const u32* Fp[1] = {Fhh};
            int gb[1] = {di * 2};
            float acc[1][2][4];
            #pragma unroll
            for (int i = 0; i < 2; i++)
                #pragma unroll
                for (int e = 0; e < 4; e++) acc[0][i][e] = 0.f;

            rec_core4<1>(&sm, Phr + (size_t)bm * DD, Fp, gb, acc);

            if (threadIdx.x < 128) {
                float* ho = (l == LL - 1) ? out : hf + (size_t)((l + 1) & 1) * BBDD;
                u32* Pn = Pp + (size_t)((l + 1) & 1) * BBDD;
                const float* nxl = nx + (size_t)l * BBDD;
                #pragma unroll
                for (int mt = 0; mt < 2; mt++)
                    #pragma unroll
                    for (int half = 0; half < 2; half++) {
                        int row = bm + wm_ * 32 + mt * 16 + gq_ + half * 8;
                        size_t ix = (size_t)row * DD + col;
                        #pragma unroll
                        for (int c = 0; c < 2; c++) {
                            int e = half * 2 + c;
                            float hh = tanhf(acc[0][mt][e] + nxl[ix + c]);
                            float h0 = hc[ix + c];
                            float u0 = ue[ix + c];
                            float hn = h0 + u0 * (hh - h0);
                            ho[ix + c] = hn;
                            Pn[ix + c] = packbf(hn);
                        }
                    }
            }
        }

        grid_barrier(RECB);
    }
}

// ---------------- conversion kernels ----------------
__global__ void pack_zero_kernel(const float* __restrict__ x, u32* __restrict__ p, int n4,
                                 float* __restrict__ z, int zn4)
{
    int i = blockIdx.x * 256 + threadIdx.x;
    if (i < n4) {
        float4 v = ((const float4*)x)[i];
        uint4 o;
        o.x = packbf(v.x); o.y = packbf(v.y); o.z = packbf(v.z); o.w = packbf(v.w);
        ((uint4*)p)[i] = o;
    }
    if (i < zn4) ((float4*)z)[i] = make_float4(0.f, 0.f, 0.f, 0.f);
}

__global__ void pack_kernel(const float* __restrict__ x, u32* __restrict__ p, int n4)
{
    int i = blockIdx.x * 256 + threadIdx.x;
    if (i < n4) {
        float4 v = ((const float4*)x)[i];
        uint4 o;
        o.x = packbf(v.x); o.y = packbf(v.y); o.z = packbf(v.z); o.w = packbf(v.w);
        ((uint4*)p)[i] = o;
    }
}

__device__ __forceinline__ void wfrag_one(const float* W, int ldw, int woff,
                                          u32* F, int idx)
{
    int j = idx & 3, lane = (idx >> 2) & 31, s2 = (idx >> 7) & 31, gnt = idx >> 12;
    int g = lane >> 2, t = lane & 3;
    int sl = s2 * 2 + (j >> 1), b = j & 1;
    int ok = sl * 8 + t + 4 * b;
    int n = gnt * 8 + g;
    F[idx] = packbf(W[(size_t)n * ldw + woff + ok]);
}

// both wih and whh in one launch
__global__ void wfrag2_kernel(const float* __restrict__ W1, const float* __restrict__ W2,
                              u32* __restrict__ F1, u32* __restrict__ F2, int total)
{
    int idx0 = blockIdx.x * 256 + threadIdx.x;
    if (idx0 < total)               wfrag_one(W1, DD, 0, F1, idx0);
    else if (idx0 < 2 * total)      wfrag_one(W2, DD, 0, F2, idx0 - total);
}

__global__ void wfrag_kernel(const float* __restrict__ W, int ldw, int woff,
                             u32* __restrict__ F, int total)
{
    int idx = blockIdx.x * 256 + threadIdx.x;
    if (idx < total) wfrag_one(W, ldw, woff, F, idx);
}

// ---------------- attention ----------------
__global__ void attn_logits(const float* __restrict__ s, const float* __restrict__ u,
                            float* __restrict__ logits)
{
    int gw = (blockIdx.x * blockDim.x + threadIdx.x) >> 5;
    int lane = threadIdx.x & 31;
    int b = gw & (BB - 1);
    const float4* sr = (const float4*)(s + (size_t)gw * DD);
    const float4* ur = (const float4*)(u + (size_t)b * DD);
    float acc = 0.f;
    #pragma unroll
    for (int k = lane; k < DD / 4; k += 32) {
        float4 a = sr[k], c = ur[k];
        acc += a.x * c.x + a.y * c.y + a.z * c.z + a.w * c.w;
    }
    #pragma unroll
    for (int o = 16; o > 0; o >>= 1) acc += __shfl_xor_sync(0xffffffffu, acc, o);
    if (lane == 0) logits[gw] = acc;
}

__global__ void attn_softmax(const float* __restrict__ logits, float* __restrict__ att)
{
    int b = blockIdx.x, t = threadIdx.x;
    __shared__ float red[256];
    float v = (t < LL) ? logits[t * BB + b] : -1e30f;
    red[t] = v;
    __syncthreads();
    for (int s = 128; s > 0; s >>= 1) {
        if (t < s) red[t] = fmaxf(red[t], red[t + s]);
        __syncthreads();
    }
    float mx = red[0];
    __syncthreads();
    float e = (t < LL) ? expf(v - mx) : 0.f;
    red[t] = e;
    __syncthreads();
    for (int s = 128; s > 0; s >>= 1) {
        if (t < s) red[t] += red[t + s];
        __syncthreads();
    }
    float inv = 1.f / red[0];
    if (t < LL) att[t * BB + b] = e * inv;
}

// ---------------- host ----------------
extern "C" void kernel_launch(void* const* d_in, const int* in_sizes, int n_in,
                              void* d_out, int out_size)
{
    const float* session  = (const float*)d_in[0];
    const float* target   = (const float*)d_in[1];
    const float* w        = (const float*)d_in[2];
    const float* wih      = (const float*)d_in[3];
    const float* whh      = (const float*)d_in[4];
    const float* bih      = (const float*)d_in[5];
    const float* bhh      = (const float*)d_in[6];
    const float* reset_w  = (const float*)d_in[7];
    const float* reset_b  = (const float*)d_in[8];
    const float* update_w = (const float*)d_in[9];
    const float* update_b = (const float*)d_in[10];
    const float* hhat_w   = (const float*)d_in[11];
    const float* hhat_b   = (const float*)d_in[12];
    float* out = (float*)d_out;

    float *xproj, *sseq, *rx, *ux, *nx, *u, *logits, *att, *ue, *hf, *zero;
    u32 *Psess, *Ptar, *Psseq, *Phr, *Pp;
    u32 *Fwih, *Fwhh, *Fw, *Frh, *Fuh, *Fhh, *Frx, *Fux, *Fhx;

    cudaGetSymbolAddress((void**)&xproj,  g_xproj);
    cudaGetSymbolAddress((void**)&sseq,   g_sseq);
    cudaGetSymbolAddress((void**)&rx,     g_rx);
    cudaGetSymbolAddress((void**)&ux,     g_ux);
    cudaGetSymbolAddress((void**)&nx,     g_nx);
    cudaGetSymbolAddress((void**)&u,      g_u);
    cudaGetSymbolAddress((void**)&logits, g_logits);
    cudaGetSymbolAddress((void**)&att,    g_att);
    cudaGetSymbolAddress((void**)&ue,     g_ue);
    cudaGetSymbolAddress((void**)&hf,     g_hf);
    cudaGetSymbolAddress((void**)&zero,   g_zero);
    cudaGetSymbolAddress((void**)&Psess,  g_Psess);
    cudaGetSymbolAddress((void**)&Ptar,   g_Ptar);
    cudaGetSymbolAddress((void**)&Psseq,  g_Psseq);
    cudaGetSymbolAddress((void**)&Phr,    g_Phr);
    cudaGetSymbolAddress((void**)&Pp,     g_Pp);
    cudaGetSymbolAddress((void**)&Fwih,   g_Fwih);
    cudaGetSymbolAddress((void**)&Fwhh,   g_Fwhh);
    cudaGetSymbolAddress((void**)&Fw,     g_Fw);
    cudaGetSymbolAddress((void**)&Frh,    g_Frh);
    cudaGetSymbolAddress((void**)&Fuh,    g_Fuh);
    cudaGetSymbolAddress((void**)&Fhh,    g_Fhh);
    cudaGetSymbolAddress((void**)&Frx,    g_Frx);
    cudaGetSymbolAddress((void**)&Fux,    g_Fux);
    cudaGetSymbolAddress((void**)&Fhx,    g_Fhx);

    // launch 1: pack session + zero buffer
    pack_zero_kernel<<<(BB * LL * DD / 4 + 255) / 256, 256>>>(
        session, Psess, BB * LL * DD / 4, zero, BB * DD / 4);
    // launch 2: both GRU weight fragment sets
    wfrag2_kernel<<<(2 * 1536 * DD + 255) / 256, 256>>>(wih, whh, Fwih, Fwhh, 1536 * DD);
    // launch 3: x_proj
    {
        dim3 g(BB * LL / 128, 3 * DD / 64);
        mm_big<<<g, 256>>>(Psess, Fwih, bih, xproj, 3 * DD);
    }
    // launch 4: persistent GRU  <- ncu capture slot
    gru2<<<RECB, 512>>>(zero, (const u32*)zero, Fwhh, bhh, xproj, sseq, Psseq);

    // remaining prep
    pack_kernel<<<(BB * DD / 4 + 255) / 256, 256>>>(target, Ptar, BB * DD / 4);
    wfrag_kernel<<<(DD * DD + 255) / 256, 256>>>(w,        DD,     0,  Fw,  DD * DD);
    wfrag_kernel<<<(DD * DD + 255) / 256, 256>>>(reset_w,  2 * DD, 0,  Frh, DD * DD);
    wfrag_kernel<<<(DD * DD + 255) / 256, 256>>>(update_w, 2 * DD, 0,  Fuh, DD * DD);
    wfrag_kernel<<<(DD * DD + 255) / 256, 256>>>(hhat_w,   2 * DD, 0,  Fhh, DD * DD);
    wfrag_kernel<<<(DD * DD + 255) / 256, 256>>>(reset_w,  2 * DD, DD, Frx, DD * DD);
    wfrag_kernel<<<(DD * DD + 255) / 256, 256>>>(update_w, 2 * DD, DD, Fux, DD * DD);
    wfrag_kernel<<<(DD * DD + 255) / 256, 256>>>(hhat_w,   2 * DD, DD, Fhx, DD * DD);

    // u = target @ w^T
    {
        dim3 g(BB / 128, DD / 64);
        mm_big<<<g, 256>>>(Ptar, Fw, nullptr, u, DD);
    }
    // AUGRU x-projections (biases folded)
    {
        dim3 g(BB * LL / 128, DD / 64);
        mm_big<<<g, 256>>>(Psseq, Frx, reset_b,  rx, DD);
        mm_big<<<g, 256>>>(Psseq, Fux, update_b, ux, DD);
        mm_big<<<g, 256>>>(Psseq, Fhx, hhat_b,   nx, DD);
    }
    // attention
    attn_logits<<<LL * BB / 8, 256>>>(sseq, u, logits);
    attn_softmax<<<BB, 256>>>(logits, att);

    // persistent AUGRU; init h = sseq[L-1]
    augru2<<<RECB, 512>>>(sseq + (size_t)(LL - 1) * BBDD,
                          Psseq + (size_t)(LL - 1) * BBDD,
                          Frh, Fuh, Fhh,
                          rx, ux, nx, att,
                          hf, Pp, Phr, ue, out);
}

// round 13
// speedup vs baseline: 2.7561x; 1.2302x over previous
#include <cuda_runtime.h>
#include <cuda_bf16.h>
#include <math.h>
#include <stdint.h>

#define BB 256
#define LL 200
#define DD 512
#define BBDD (BB * DD)
typedef uint32_t u32;

// ---------------- fp32 scratch ----------------
__device__ float g_xproj[(size_t)BB * LL * 3 * DD];   // [B,L,3D] (+bih)
__device__ float g_sseq [(size_t)LL * BB * DD];       // [L,B,D]
__device__ float g_rx   [(size_t)LL * BB * DD];
__device__ float g_ux   [(size_t)LL * BB * DD];
__device__ float g_nx   [(size_t)LL * BB * DD];
__device__ float g_u    [BB * DD];
__device__ float g_logits[LL * BB];
__device__ float g_att   [LL * BB];
__device__ float g_ue    [BB * DD];
__device__ float g_hf    [2 * BB * DD];
__device__ float g_zero  [BB * DD];                   // fp32 zeros == packed zeros

// ---------------- packed (bf16-pair) activations ----------------
__device__ u32 g_Psess[(size_t)BB * LL * DD];
__device__ u32 g_Ptar [BB * DD];
__device__ u32 g_Psseq[(size_t)LL * BB * DD];
__device__ u32 g_Phr  [BB * DD];
__device__ u32 g_Pp   [2 * BB * DD];

// ---------------- weight fragments (B-operand order) ----------------
__device__ u32 g_Fwih[1536 * DD];
__device__ u32 g_Fwhh[1536 * DD];
__device__ u32 g_Fw  [DD * DD];
__device__ u32 g_Frh [DD * DD];
__device__ u32 g_Fuh [DD * DD];
__device__ u32 g_Fhh [DD * DD];
__device__ u32 g_Frx [DD * DD];
__device__ u32 g_Fux [DD * DD];
__device__ u32 g_Fhx [DD * DD];

// per-row-group barriers (16 groups, counters padded 128B apart)
__device__ unsigned int          g_gcnt[16 * 32];
__device__ volatile unsigned int g_ggen[16 * 32];

__device__ __forceinline__ float sigf(float x) { return 1.0f / (1.0f + __expf(-x)); }

__device__ __forceinline__ u32 packbf(float x) {
    __nv_bfloat16 hi = __float2bfloat16(x);
    float hf = __bfloat162float(hi);
    __nv_bfloat16 lo = __float2bfloat16(x - hf);
    return (u32)__bfloat16_as_ushort(hi) | ((u32)__bfloat16_as_ushort(lo) << 16);
}

// 8-block barrier over one row group
__device__ __forceinline__ void group_barrier(int mi) {
    __syncthreads();
    if (threadIdx.x == 0) {
        __threadfence();
        unsigned int gen = g_ggen[mi * 32];
        unsigned int old = atomicAdd(&g_gcnt[mi * 32], 1u);
        if (old == 7u) {
            atomicExch(&g_gcnt[mi * 32], 0u);
            __threadfence();
            atomicAdd((unsigned int*)&g_ggen[mi * 32], 1u);
        } else {
            while (g_ggen[mi * 32] == gen) { }
        }
        __threadfence();
    }
    __syncthreads();
}

__device__ __forceinline__ void mma16(float* d, const u32* a, u32 b0, u32 b1) {
    asm volatile(
        "mma.sync.aligned.m16n8k16.row.col.f32.bf16.bf16.f32 "
        "{%0,%1,%2,%3},{%4,%5,%6,%7},{%8,%9},{%0,%1,%2,%3};"
        : "+f"(d[0]), "+f"(d[1]), "+f"(d[2]), "+f"(d[3])
        : "r"(a[0]), "r"(a[1]), "r"(a[2]), "r"(a[3]), "r"(b0), "r"(b1));
}

// ==================================================================
// 256-thread 128x64 core (unchanged — proven) for the big GEMMs
// ==================================================================
struct MMSmem { u32 A[2][16][136]; };

__device__ __forceinline__ void mm_core(
    MMSmem* sm, const u32* __restrict__ Ap,
    const u32* __restrict__ F, int gnt0,
    float acc[2][4][4])
{
    const int tid  = threadIdx.x;
    const int lane = tid & 31;
    const int gq = lane >> 2, tq = lane & 3;
    const int w  = tid >> 5;
    const int wm = w >> 1, wn = w & 1;
    const int r  = tid >> 1, h = tid & 1;

    const u32* arow = Ap + (size_t)r * DD + h * 8;

    uint4 bv[4], nbv[4], na0, na1;

    uint4 va0 = *(const uint4*)(arow + 0);
    uint4 va1 = *(const uint4*)(arow + 4);
    #pragma unroll
    for (int nt = 0; nt < 4; nt++) {
        int gnt = gnt0 + wn * 4 + nt;
        bv[nt] = *(const uint4*)(F + (((size_t)gnt * 32 + 0) * 32 + lane) * 4);
    }
    {
        u32 e0[4] = {va0.x, va0.y, va0.z, va0.w};
        u32 e1[4] = {va1.x, va1.y, va1.z, va1.w};
        #pragma unroll
        for (int j = 0; j < 4; j++) {
            int jj = (j + 2 * h) & 3;
            sm->A[0][h * 8 + 0 + jj][r] = e0[jj];
            sm->A[0][h * 8 + 4 + jj][r] = e1[jj];
        }
    }
    __syncthreads();

    #pragma unroll 1
    for (int s2 = 0; s2 < 32; s2++) {
        const int buf = s2 & 1;
        if (s2 < 31) {
            const u32* ar = arow + (s2 + 1) * 16;
            na0 = *(const uint4*)(ar);
            na1 = *(const uint4*)(ar + 4);
            #pragma unroll
            for (int nt = 0; nt < 4; nt++) {
                int gnt = gnt0 + wn * 4 + nt;
                nbv[nt] = *(const uint4*)(F + (((size_t)gnt * 32 + (s2 + 1)) * 32 + lane) * 4);
            }
        }
        #pragma unroll
        for (int sl = 0; sl < 2; sl++) {
            u32 a[2][4], as[2][4];
            #pragma unroll
            for (int mt = 0; mt < 2; mt++) {
                int rb = wm * 32 + mt * 16 + gq;
                a[mt][0] = sm->A[buf][sl * 8 + tq][rb];
                a[mt][1] = sm->A[buf][sl * 8 + tq][rb + 8];
                a[mt][2] = sm->A[buf][sl * 8 + tq + 4][rb];
                a[mt][3] = sm->A[buf][sl * 8 + tq + 4][rb + 8];
                #pragma unroll
                for (int q = 0; q < 4; q++)
                    as[mt][q] = __funnelshift_l(a[mt][q], a[mt][q], 16);
            }
            #pragma unroll
            for (int nt = 0; nt < 4; nt++) {
                u32 b0 = sl ? bv[nt].z : bv[nt].x;
                u32 b1 = sl ? bv[nt].w : bv[nt].y;
                #pragma unroll
                for (int mt = 0; mt < 2; mt++) {
                    mma16(acc[mt][nt], a[mt],  b0, b1);
                    mma16(acc[mt][nt], as[mt], b0, b1);
                }
            }
        }
        if (s2 < 31) {
            u32 e0[4] = {na0.x, na0.y, na0.z, na0.w};
            u32 e1[4] = {na1.x, na1.y, na1.z, na1.w};
            #pragma unroll
            for (int j = 0; j < 4; j++) {
                int jj = (j + 2 * h) & 3;
                sm->A[buf ^ 1][h * 8 + 0 + jj][r] = e0[jj];
                sm->A[buf ^ 1][h * 8 + 4 + jj][r] = e1[jj];
            }
            #pragma unroll
            for (int nt = 0; nt < 4; nt++) bv[nt] = nbv[nt];
        }
        __syncthreads();
    }
}

__global__ __launch_bounds__(256) void mm_big(
    const u32* __restrict__ Ap,
    const u32* __restrict__ F,
    const float* __restrict__ bias,
    float* __restrict__ C, int ldc)
{
    __shared__ MMSmem sm;
    const int bm = blockIdx.x * 128, bn = blockIdx.y * 64;
    float acc[2][4][4];
    #pragma unroll
    for (int i = 0; i < 2; i++)
        #pragma unroll
        for (int j = 0; j < 4; j++)
            #pragma unroll
            for (int e = 0; e < 4; e++) acc[i][j][e] = 0.f;
    mm_core(&sm, Ap + (size_t)bm * DD, F, bn >> 3, acc);

    const int lane = threadIdx.x & 31;
    const int gq = lane >> 2, tq = lane & 3;
    const int w = threadIdx.x >> 5;
    const int wm = w >> 1, wn = w & 1;
    #pragma unroll
    for (int mt = 0; mt < 2; mt++)
        #pragma unroll
        for (int nt = 0; nt < 4; nt++) {
            int row = bm + wm * 32 + mt * 16 + gq;
            int col = bn + wn * 32 + nt * 8 + 2 * tq;
            float b0 = bias ? bias[col] : 0.f;
            float b1 = bias ? bias[col + 1] : 0.f;
            *(float2*)(C + (size_t)row * ldc + col) =
                make_float2(acc[mt][nt][0] + b0, acc[mt][nt][1] + b1);
            *(float2*)(C + (size_t)(row + 8) * ldc + col) =
                make_float2(acc[mt][nt][2] + b0, acc[mt][nt][3] + b1);
        }
}

// ==================================================================
// Row-group recurrence core: 16 rows x 64 h-cols x NG gates, 512 thr
// 4 n-warps x 4 k-quarters. A plane stride 24: conflict-free LDS/STS.
// ==================================================================
struct RSG {
    union {
        u32 A[2][4][16][24];        // [buf][kq][ok][row pad24]  12,288 B
        float red[384 * 25];        // k-partial reduction       38,400 B
    };
};

template<int NG>
__device__ __forceinline__ void rec_coreG(
    RSG* sm, const u32* __restrict__ Ap,       // 16 rows, stride DD
    const u32* const* Fp, const int* gb,       // per-gate base gnt
    float acc[NG][2][4])
{
    const int tid  = threadIdx.x;
    const int lane = tid & 31;
    const int gq = lane >> 2, tq = lane & 3;
    const int w  = tid >> 5;
    const int wk = w >> 2;          // k-quarter 0..3
    const int wn = w & 3;           // n-warp 0..3
    const bool loader = tid < 256;
    const int lt  = tid & 255;
    const int lkq = lt >> 6;        // 0..3
    const int lr  = (lt >> 2) & 15; // row 0..15
    const int lsg = lt & 3;         // 4-u32 segment 0..3

    const u32* arow = Ap + (size_t)lr * DD + lkq * 128 + lsg * 4;

    uint4 bv[NG][2], nbv[NG][2], na, va;

    if (loader) va = *(const uint4*)(arow);
    #pragma unroll
    for (int g = 0; g < NG; g++)
        #pragma unroll
        for (int nt = 0; nt < 2; nt++)
            bv[g][nt] = *(const uint4*)(Fp[g] +
                (((size_t)(gb[g] + wn * 2 + nt) * 32 + wk * 8) * 32 + lane) * 4);
    if (loader) {
        u32 e[4] = {va.x, va.y, va.z, va.w};
        #pragma unroll
        for (int j = 0; j < 4; j++) {
            int jj = (j + lsg) & 3;
            sm->A[0][lkq][lsg * 4 + jj][lr] = e[jj];
        }
    }
    __syncthreads();

    #pragma unroll 1
    for (int s2 = 0; s2 < 8; s2++) {
        const int buf = s2 & 1;
        if (s2 < 7) {
            if (loader) na = *(const uint4*)(arow + (s2 + 1) * 16);
            #pragma unroll
            for (int g = 0; g < NG; g++)
                #pragma unroll
                for (int nt = 0; nt < 2; nt++)
                    nbv[g][nt] = *(const uint4*)(Fp[g] +
                        (((size_t)(gb[g] + wn * 2 + nt) * 32 + wk * 8 + s2 + 1) * 32 + lane) * 4);
        }
        #pragma unroll
        for (int sl = 0; sl < 2; sl++) {
            u32 a[4], as[4];
            a[0] = sm->A[buf][wk][sl * 8 + tq][gq];
            a[1] = sm->A[buf][wk][sl * 8 + tq][gq + 8];
            a[2] = sm->A[buf][wk][sl * 8 + tq + 4][gq];
            a[3] = sm->A[buf][wk][sl * 8 + tq + 4][gq + 8];
            #pragma unroll
            for (int q = 0; q < 4; q++) as[q] = __funnelshift_l(a[q], a[q], 16);
            #pragma unroll
            for (int g = 0; g < NG; g++)
                #pragma unroll
                for (int nt = 0; nt < 2; nt++) {
                    u32 b0 = sl ? bv[g][nt].z : bv[g][nt].x;
                    u32 b1 = sl ? bv[g][nt].w : bv[g][nt].y;
                    mma16(acc[g][nt], a,  b0, b1);
                    mma16(acc[g][nt], as, b0, b1);
                }
        }
        if (s2 < 7) {
            if (loader) {
                u32 e[4] = {na.x, na.y, na.z, na.w};
                #pragma unroll
                for (int j = 0; j < 4; j++) {
                    int jj = (j + lsg) & 3;
                    sm->A[buf ^ 1][lkq][lsg * 4 + jj][lr] = e[jj];
                }
            }
            #pragma unroll
            for (int g = 0; g < NG; g++) {
                bv[g][0] = nbv[g][0];
                bv[g][1] = nbv[g][1];
            }
        }
        __syncthreads();
    }

    // reduce wk=1..3 partials into wk=0 (stride 25: conflict-free)
    const int stride = NG * 8 + 1;
    if (wk) {
        int base = (tid - 128) * stride;
        #pragma unroll
        for (int g = 0; g < NG; g++)
            #pragma unroll
            for (int nt = 0; nt < 2; nt++)
                #pragma unroll
                for (int e = 0; e < 4; e++)
                    sm->red[base + (g * 2 + nt) * 4 + e] = acc[g][nt][e];
    }
    __syncthreads();
    if (!wk) {
        #pragma unroll
        for (int k = 0; k < 3; k++) {
            int base = (k * 128 + tid) * stride;
            #pragma unroll
            for (int g = 0; g < NG; g++)
                #pragma unroll
                for (int nt = 0; nt < 2; nt++)
                    #pragma unroll
                    for (int e = 0; e < 4; e++)
                        acc[g][nt][e] += sm->red[base + (g * 2 + nt) * 4 + e];
        }
    }
    __syncthreads();
}

// ---------------- persistent GRU: 16 row-groups x 8 col-blocks ----------------
__global__ __launch_bounds__(512) void gru2G(
    const float* __restrict__ zero, const u32* __restrict__ Pzero,
    const u32* __restrict__ Fwhh, const float* __restrict__ bhh,
    const float* __restrict__ xproj,
    float* __restrict__ sseq, u32* __restrict__ Psseq)
{
    __shared__ RSG sm;
    const int blk = blockIdx.x;
    const int mi = blk >> 3, di = blk & 7;
    const int bm = mi * 16;
    const int lane = threadIdx.x & 31;
    const int gq = lane >> 2, tq = lane & 3;
    const int wn = (threadIdx.x >> 5) & 3;

    const u32* Fp[3] = {Fwhh, Fwhh, Fwhh};
    int gb[3] = {di * 8, 64 + di * 8, 128 + di * 8};

    float bh[3][2][2];
    #pragma unroll
    for (int g = 0; g < 3; g++)
        #pragma unroll
        for (int nt = 0; nt < 2; nt++) {
            int col = di * 64 + wn * 16 + nt * 8 + 2 * tq;
            bh[g][nt][0] = bhh[g * 512 + col];
            bh[g][nt][1] = bhh[g * 512 + col + 1];
        }

    for (int l = 0; l < LL; l++) {
        const u32* Ap = (l ? Psseq + (size_t)(l - 1) * BBDD : Pzero) + (size_t)bm * DD;
        float acc[3][2][4];
        #pragma unroll
        for (int g = 0; g < 3; g++)
            #pragma unroll
            for (int nt = 0; nt < 2; nt++)
                #pragma unroll
                for (int e = 0; e < 4; e++) acc[g][nt][e] = 0.f;

        rec_coreG<3>(&sm, Ap, Fp, gb, acc);

        if (threadIdx.x < 128) {
            const float* hprev = l ? sseq + (size_t)(l - 1) * BBDD : zero;
            float* sl_ = sseq + (size_t)l * BBDD;
            u32* pl = Psseq + (size_t)l * BBDD;

            #pragma unroll
            for (int nt = 0; nt < 2; nt++) {
                int col = di * 64 + wn * 16 + nt * 8 + 2 * tq;
                #pragma unroll
                for (int half = 0; half < 2; half++) {
                    int row = bm + gq + half * 8;
                    const float* xb = xproj + ((size_t)row * LL + l) * 1536;
                    size_t ix = (size_t)row * DD + col;
                    #pragma unroll
                    for (int c = 0; c < 2; c++) {
                        int e = half * 2 + c;
                        float rr = sigf(xb[col + c] + acc[0][nt][e] + bh[0][nt][c]);
                        float zz = sigf(xb[512 + col + c] + acc[1][nt][e] + bh[1][nt][c]);
                        float nn = tanhf(xb[1024 + col + c] + rr * (acc[2][nt][e] + bh[2][nt][c]));
                        float h0 = hprev[ix + c];
                        float hn = nn + zz * (h0 - nn);
                        sl_[ix + c] = hn;
                        pl[ix + c] = packbf(hn);
                    }
                }
            }
        }

        group_barrier(mi);
    }
}

// ---------------- persistent AUGRU: same grouping ----------------
__global__ __launch_bounds__(512) void augru2G(
    const float* __restrict__ hlast, const u32* __restrict__ Pinit,
    const u32* __restrict__ Frh, const u32* __restrict__ Fuh, const u32* __restrict__ Fhh,
    const float* __restrict__ rx, const float* __restrict__ ux, const float* __restrict__ nx,
    const float* __restrict__ att,
    float* __restrict__ hf, u32* __restrict__ Pp,
    u32* __restrict__ Phr, float* __restrict__ ue,
    float* __restrict__ out)
{
    __shared__ RSG sm;
    const int blk = blockIdx.x;
    const int mi = blk >> 3, di = blk & 7;
    const int bm = mi * 16;
    const int lane = threadIdx.x & 31;
    const int gq = lane >> 2, tq = lane & 3;
    const int wn = (threadIdx.x >> 5) & 3;

    for (int l = 0; l < LL; l++) {
        const float* hc = l ? hf + (size_t)(l & 1) * BBDD : hlast;
        const u32* Pc = l ? Pp + (size_t)(l & 1) * BBDD : Pinit;

        {   // phase A: r and u_eff for own 64 h-cols
            const u32* Fp[2] = {Frh, Fuh};
            int gb[2] = {di * 8, di * 8};
            float acc[2][2][4];
            #pragma unroll
            for (int g = 0; g < 2; g++)
                #pragma unroll
                for (int nt = 0; nt < 2; nt++)
                    #pragma unroll
                    for (int e = 0; e < 4; e++) acc[g][nt][e] = 0.f;

            rec_coreG<2>(&sm, Pc + (size_t)bm * DD, Fp, gb, acc);

            if (threadIdx.x < 128) {
                const float* rxl = rx + (size_t)l * BBDD;
                const float* uxl = ux + (size_t)l * BBDD;
                #pragma unroll
                for (int nt = 0; nt < 2; nt++) {
                    int col = di * 64 + wn * 16 + nt * 8 + 2 * tq;
                    #pragma unroll
                    for (int half = 0; half < 2; half++) {
                        int row = bm + gq + half * 8;
                        size_t ix = (size_t)row * DD + col;
                        float a = att[(size_t)l * BB + row];
                        #pragma unroll
                        for (int c = 0; c < 2; c++) {
                            int e = half * 2 + c;
                            float vr = acc[0][nt][e] + rxl[ix + c];
                            float vu = acc[1][nt][e] + uxl[ix + c];
                            Phr[ix + c] = packbf(hc[ix + c] * sigf(vr));
                            ue[ix + c]  = a * sigf(vu);
                        }
                    }
                }
            }
        }

        group_barrier(mi);

        {   // phase B: hhat + output update for own 64 h-cols
            const u32* Fp[1] = {Fhh};
            int gb[1] = {di * 8};
            float acc[1][2][4];
            #pragma unroll
            for (int nt = 0; nt < 2; nt++)
                #pragma unroll
                for (int e = 0; e < 4; e++) acc[0][nt][e] = 0.f;

            rec_coreG<1>(&sm, Phr + (size_t)bm * DD, Fp, gb, acc);

            if (threadIdx.x < 128) {
                float* ho = (l == LL - 1) ? out : hf + (size_t)((l + 1) & 1) * BBDD;
                u32* Pn = Pp + (size_t)((l + 1) & 1) * BBDD;
                const float* nxl = nx + (size_t)l * BBDD;
                #pragma unroll
                for (int nt = 0; nt < 2; nt++) {
                    int col = di * 64 + wn * 16 + nt * 8 + 2 * tq;
                    #pragma unroll
                    for (int half = 0; half < 2; half++) {
                        int row = bm + gq + half * 8;
                        size_t ix = (size_t)row * DD + col;
                        #pragma unroll
                        for (int c = 0; c < 2; c++) {
                            int e = half * 2 + c;
                            float hh = tanhf(acc[0][nt][e] + nxl[ix + c]);
                            float h0 = hc[ix + c];
                            float u0 = ue[ix + c];
                            float hn = h0 + u0 * (hh - h0);
                            ho[ix + c] = hn;
                            Pn[ix + c] = packbf(hn);
                        }
                    }
                }
            }
        }

        group_barrier(mi);
    }
}

// ---------------- conversion kernels ----------------
__global__ void pack_zero_kernel(const float* __restrict__ x, u32* __restrict__ p, int n4,
                                 float* __restrict__ z, int zn4)
{
    int i = blockIdx.x * 256 + threadIdx.x;
    if (i < n4) {
        float4 v = ((const float4*)x)[i];
        uint4 o;
        o.x = packbf(v.x); o.y = packbf(v.y); o.z = packbf(v.z); o.w = packbf(v.w);
        ((uint4*)p)[i] = o;
    }
    if (i < zn4) ((float4*)z)[i] = make_float4(0.f, 0.f, 0.f, 0.f);
}

__global__ void pack_kernel(const float* __restrict__ x, u32* __restrict__ p, int n4)
{
    int i = blockIdx.x * 256 + threadIdx.x;
    if (i < n4) {
        float4 v = ((const float4*)x)[i];
        uint4 o;
        o.x = packbf(v.x); o.y = packbf(v.y); o.z = packbf(v.z); o.w = packbf(v.w);
        ((uint4*)p)[i] = o;
    }
}

__device__ __forceinline__ void wfrag_one(const float* W, int ldw, int woff,
                                          u32* F, int idx)
{
    int j = idx & 3, lane = (idx >> 2) & 31, s2 = (idx >> 7) & 31, gnt = idx >> 12;
    int g = lane >> 2, t = lane & 3;
    int sl = s2 * 2 + (j >> 1), b = j & 1;
    int ok = sl * 8 + t + 4 * b;
    int n = gnt * 8 + g;
    F[idx] = packbf(W[(size_t)n * ldw + woff + ok]);
}

__global__ void wfrag2_kernel(const float* __restrict__ W1, const float* __restrict__ W2,
                              u32* __restrict__ F1, u32* __restrict__ F2, int total)
{
    int idx0 = blockIdx.x * 256 + threadIdx.x;
    if (idx0 < total)               wfrag_one(W1, DD, 0, F1, idx0);
    else if (idx0 < 2 * total)      wfrag_one(W2, DD, 0, F2, idx0 - total);
}

__global__ void wfrag_kernel(const float* __restrict__ W, int ldw, int woff,
                             u32* __restrict__ F, int total)
{
    int idx = blockIdx.x * 256 + threadIdx.x;
    if (idx < total) wfrag_one(W, ldw, woff, F, idx);
}

// ---------------- attention ----------------
__global__ void attn_logits(const float* __restrict__ s, const float* __restrict__ u,
                            float* __restrict__ logits)
{
    int gw = (blockIdx.x * blockDim.x + threadIdx.x) >> 5;
    int lane = threadIdx.x & 31;
    int b = gw & (BB - 1);
    const float4* sr = (const float4*)(s + (size_t)gw * DD);
    const float4* ur = (const float4*)(u + (size_t)b * DD);
    float acc = 0.f;
    #pragma unroll
    for (int k = lane; k < DD / 4; k += 32) {
        float4 a = sr[k], c = ur[k];
        acc += a.x * c.x + a.y * c.y + a.z * c.z + a.w * c.w;
    }
    #pragma unroll
    for (int o = 16; o > 0; o >>= 1) acc += __shfl_xor_sync(0xffffffffu, acc, o);
    if (lane == 0) logits[gw] = acc;
}

__global__ void attn_softmax(const float* __restrict__ logits, float* __restrict__ att)
{
    int b = blockIdx.x, t = threadIdx.x;
    __shared__ float red[256];
    float v = (t < LL) ? logits[t * BB + b] : -1e30f;
    red[t] = v;
    __syncthreads();
    for (int s = 128; s > 0; s >>= 1) {
        if (t < s) red[t] = fmaxf(red[t], red[t + s]);
        __syncthreads();
    }
    float mx = red[0];
    __syncthreads();
    float e = (t < LL) ? expf(v - mx) : 0.f;
    red[t] = e;
    __syncthreads();
    for (int s = 128; s > 0; s >>= 1) {
        if (t < s) red[t] += red[t + s];
        __syncthreads();
    }
    float inv = 1.f / red[0];
    if (t < LL) att[t * BB + b] = e * inv;
}

// ---------------- host ----------------
extern "C" void kernel_launch(void* const* d_in, const int* in_sizes, int n_in,
                              void* d_out, int out_size)
{
    const float* session  = (const float*)d_in[0];
    const float* target   = (const float*)d_in[1];
    const float* w        = (const float*)d_in[2];
    const float* wih      = (const float*)d_in[3];
    const float* whh      = (const float*)d_in[4];
    const float* bih      = (const float*)d_in[5];
    const float* bhh      = (const float*)d_in[6];
    const float* reset_w  = (const float*)d_in[7];
    const float* reset_b  = (const float*)d_in[8];
    const float* update_w = (const float*)d_in[9];
    const float* update_b = (const float*)d_in[10];
    const float* hhat_w   = (const float*)d_in[11];
    const float* hhat_b   = (const float*)d_in[12];
    float* out = (float*)d_out;

    float *xproj, *sseq, *rx, *ux, *nx, *u, *logits, *att, *ue, *hf, *zero;
    u32 *Psess, *Ptar, *Psseq, *Phr, *Pp;
    u32 *Fwih, *Fwhh, *Fw, *Frh, *Fuh, *Fhh, *Frx, *Fux, *Fhx;

    cudaGetSymbolAddress((void**)&xproj,  g_xproj);
    cudaGetSymbolAddress((void**)&sseq,   g_sseq);
    cudaGetSymbolAddress((void**)&rx,     g_rx);
    cudaGetSymbolAddress((void**)&ux,     g_ux);
    cudaGetSymbolAddress((void**)&nx,     g_nx);
    cudaGetSymbolAddress((void**)&u,      g_u);
    cudaGetSymbolAddress((void**)&logits, g_logits);
    cudaGetSymbolAddress((void**)&att,    g_att);
    cudaGetSymbolAddress((void**)&ue,     g_ue);
    cudaGetSymbolAddress((void**)&hf,     g_hf);
    cudaGetSymbolAddress((void**)&zero,   g_zero);
    cudaGetSymbolAddress((void**)&Psess,  g_Psess);
    cudaGetSymbolAddress((void**)&Ptar,   g_Ptar);
    cudaGetSymbolAddress((void**)&Psseq,  g_Psseq);
    cudaGetSymbolAddress((void**)&Phr,    g_Phr);
    cudaGetSymbolAddress((void**)&Pp,     g_Pp);
    cudaGetSymbolAddress((void**)&Fwih,   g_Fwih);
    cudaGetSymbolAddress((void**)&Fwhh,   g_Fwhh);
    cudaGetSymbolAddress((void**)&Fw,     g_Fw);
    cudaGetSymbolAddress((void**)&Frh,    g_Frh);
    cudaGetSymbolAddress((void**)&Fuh,    g_Fuh);
    cudaGetSymbolAddress((void**)&Fhh,    g_Fhh);
    cudaGetSymbolAddress((void**)&Frx,    g_Frx);
    cudaGetSymbolAddress((void**)&Fux,    g_Fux);
    cudaGetSymbolAddress((void**)&Fhx,    g_Fhx);

    // launch 1: pack session + zero buffer
    pack_zero_kernel<<<(BB * LL * DD / 4 + 255) / 256, 256>>>(
        session, Psess, BB * LL * DD / 4, zero, BB * DD / 4);
    // launch 2: both GRU weight fragment sets
    wfrag2_kernel<<<(2 * 1536 * DD + 255) / 256, 256>>>(wih, whh, Fwih, Fwhh, 1536 * DD);
    // launch 3: x_proj
    {
        dim3 g(BB * LL / 128, 3 * DD / 64);
        mm_big<<<g, 256>>>(Psess, Fwih, bih, xproj, 3 * DD);
    }
    // launch 4: persistent GRU  <- ncu capture slot
    gru2G<<<128, 512>>>(zero, (const u32*)zero, Fwhh, bhh, xproj, sseq, Psseq);

    // remaining prep
    pack_kernel<<<(BB * DD / 4 + 255) / 256, 256>>>(target, Ptar, BB * DD / 4);
    wfrag_kernel<<<(DD * DD + 255) / 256, 256>>>(w,        DD,     0,  Fw,  DD * DD);
    wfrag_kernel<<<(DD * DD + 255) / 256, 256>>>(reset_w,  2 * DD, 0,  Frh, DD * DD);
    wfrag_kernel<<<(DD * DD + 255) / 256, 256>>>(update_w, 2 * DD, 0,  Fuh, DD * DD);
    wfrag_kernel<<<(DD * DD + 255) / 256, 256>>>(hhat_w,   2 * DD, 0,  Fhh, DD * DD);
    wfrag_kernel<<<(DD * DD + 255) / 256, 256>>>(reset_w,  2 * DD, DD, Frx, DD * DD);
    wfrag_kernel<<<(DD * DD + 255) / 256, 256>>>(update_w, 2 * DD, DD, Fux, DD * DD);
    wfrag_kernel<<<(DD * DD + 255) / 256, 256>>>(hhat_w,   2 * DD, DD, Fhx, DD * DD);

    // u = target @ w^T
    {
        dim3 g(BB / 128, DD / 64);
        mm_big<<<g, 256>>>(Ptar, Fw, nullptr, u, DD);
    }
    // AUGRU x-projections (biases folded)
    {
        dim3 g(BB * LL / 128, DD / 64);
        mm_big<<<g, 256>>>(Psseq, Frx, reset_b,  rx, DD);
        mm_big<<<g, 256>>>(Psseq, Fux, update_b, ux, DD);
        mm_big<<<g, 256>>>(Psseq, Fhx, hhat_b,   nx, DD);
    }
    // attention
    attn_logits<<<LL * BB / 8, 256>>>(sseq, u, logits);
    attn_softmax<<<BB, 256>>>(logits, att);

    // persistent AUGRU; init h = sseq[L-1]
    augru2G<<<128, 512>>>(sseq + (size_t)(LL - 1) * BBDD,
                          Psseq + (size_t)(LL - 1) * BBDD,
                          Frh, Fuh, Fhh,
                          rx, ux, nx, att,
                          hf, Pp, Phr, ue, out);
}

// round 14
// speedup vs baseline: 3.3195x; 1.2044x over previous
#include <cuda_runtime.h>
#include <cuda_bf16.h>
#include <math.h>
#include <stdint.h>

#define BB 256
#define LL 200
#define DD 512
#define BBDD (BB * DD)
typedef uint32_t u32;

// ---------------- fp32 scratch ----------------
__device__ float g_xproj[(size_t)BB * LL * 3 * DD];   // [B,L,3D] (+bih)
__device__ float g_sseq [(size_t)LL * BB * DD];       // [L,B,D]
__device__ float g_rx   [(size_t)LL * BB * DD];
__device__ float g_ux   [(size_t)LL * BB * DD];
__device__ float g_nx   [(size_t)LL * BB * DD];
__device__ float g_u    [BB * DD];
__device__ float g_logits[LL * BB];
__device__ float g_att   [LL * BB];
__device__ float g_ue    [BB * DD];
__device__ float g_hf    [2 * BB * DD];
__device__ float g_zero  [BB * DD];                   // fp32 zeros == packed zeros

// ---------------- packed (bf16-pair) activations ----------------
__device__ u32 g_Psess[(size_t)BB * LL * DD];
__device__ u32 g_Ptar [BB * DD];
__device__ u32 g_Psseq[(size_t)LL * BB * DD];
__device__ u32 g_Phr  [BB * DD];
__device__ u32 g_Pp   [2 * BB * DD];

// ---------------- weight fragments (B-operand order) ----------------
__device__ u32 g_Fwih[1536 * DD];
__device__ u32 g_Fwhh[1536 * DD];
__device__ u32 g_Fw  [DD * DD];
__device__ u32 g_Frh [DD * DD];
__device__ u32 g_Fuh [DD * DD];
__device__ u32 g_Fhh [DD * DD];
__device__ u32 g_Frx [DD * DD];
__device__ u32 g_Fux [DD * DD];
__device__ u32 g_Fhx [DD * DD];

// per-row-group barriers (16 groups, counters padded 128B apart)
__device__ unsigned int          g_gcnt[16 * 32];
__device__ volatile unsigned int g_ggen[16 * 32];

__device__ __forceinline__ float sigf(float x) { return 1.0f / (1.0f + __expf(-x)); }

__device__ __forceinline__ u32 packbf(float x) {
    __nv_bfloat16 hi = __float2bfloat16(x);
    float hf = __bfloat162float(hi);
    __nv_bfloat16 lo = __float2bfloat16(x - hf);
    return (u32)__bfloat16_as_ushort(hi) | ((u32)__bfloat16_as_ushort(lo) << 16);
}

__device__ __forceinline__ void pf2(const void* p) {
    asm volatile("prefetch.global.L2 [%0];" :: "l"(p));
}

// 8-block barrier over one row group
__device__ __forceinline__ void group_barrier(int mi) {
    __syncthreads();
    if (threadIdx.x == 0) {
        __threadfence();
        unsigned int gen = g_ggen[mi * 32];
        unsigned int old = atomicAdd(&g_gcnt[mi * 32], 1u);
        if (old == 7u) {
            atomicExch(&g_gcnt[mi * 32], 0u);
            __threadfence();
            atomicAdd((unsigned int*)&g_ggen[mi * 32], 1u);
        } else {
            while (g_ggen[mi * 32] == gen) { }
        }
        __threadfence();
    }
    __syncthreads();
}

__device__ __forceinline__ void mma16(float* d, const u32* a, u32 b0, u32 b1) {
    asm volatile(
        "mma.sync.aligned.m16n8k16.row.col.f32.bf16.bf16.f32 "
        "{%0,%1,%2,%3},{%4,%5,%6,%7},{%8,%9},{%0,%1,%2,%3};"
        : "+f"(d[0]), "+f"(d[1]), "+f"(d[2]), "+f"(d[3])
        : "r"(a[0]), "r"(a[1]), "r"(a[2]), "r"(a[3]), "r"(b0), "r"(b1));
}

// ==================================================================
// 256-thread 128x64 core (unchanged — proven) for the big GEMMs
// ==================================================================
struct MMSmem { u32 A[2][16][136]; };

__device__ __forceinline__ void mm_core(
    MMSmem* sm, const u32* __restrict__ Ap,
    const u32* __restrict__ F, int gnt0,
    float acc[2][4][4])
{
    const int tid  = threadIdx.x;
    const int lane = tid & 31;
    const int gq = lane >> 2, tq = lane & 3;
    const int w  = tid >> 5;
    const int wm = w >> 1, wn = w & 1;
    const int r  = tid >> 1, h = tid & 1;

    const u32* arow = Ap + (size_t)r * DD + h * 8;

    uint4 bv[4], nbv[4], na0, na1;

    uint4 va0 = *(const uint4*)(arow + 0);
    uint4 va1 = *(const uint4*)(arow + 4);
    #pragma unroll
    for (int nt = 0; nt < 4; nt++) {
        int gnt = gnt0 + wn * 4 + nt;
        bv[nt] = *(const uint4*)(F + (((size_t)gnt * 32 + 0) * 32 + lane) * 4);
    }
    {
        u32 e0[4] = {va0.x, va0.y, va0.z, va0.w};
        u32 e1[4] = {va1.x, va1.y, va1.z, va1.w};
        #pragma unroll
        for (int j = 0; j < 4; j++) {
            int jj = (j + 2 * h) & 3;
            sm->A[0][h * 8 + 0 + jj][r] = e0[jj];
            sm->A[0][h * 8 + 4 + jj][r] = e1[jj];
        }
    }
    __syncthreads();

    #pragma unroll 1
    for (int s2 = 0; s2 < 32; s2++) {
        const int buf = s2 & 1;
        if (s2 < 31) {
            const u32* ar = arow + (s2 + 1) * 16;
            na0 = *(const uint4*)(ar);
            na1 = *(const uint4*)(ar + 4);
            #pragma unroll
            for (int nt = 0; nt < 4; nt++) {
                int gnt = gnt0 + wn * 4 + nt;
                nbv[nt] = *(const uint4*)(F + (((size_t)gnt * 32 + (s2 + 1)) * 32 + lane) * 4);
            }
        }
        #pragma unroll
        for (int sl = 0; sl < 2; sl++) {
            u32 a[2][4], as[2][4];
            #pragma unroll
            for (int mt = 0; mt < 2; mt++) {
                int rb = wm * 32 + mt * 16 + gq;
                a[mt][0] = sm->A[buf][sl * 8 + tq][rb];
                a[mt][1] = sm->A[buf][sl * 8 + tq][rb + 8];
                a[mt][2] = sm->A[buf][sl * 8 + tq + 4][rb];
                a[mt][3] = sm->A[buf][sl * 8 + tq + 4][rb + 8];
                #pragma unroll
                for (int q = 0; q < 4; q++)
                    as[mt][q] = __funnelshift_l(a[mt][q], a[mt][q], 16);
            }
            #pragma unroll
            for (int nt = 0; nt < 4; nt++) {
                u32 b0 = sl ? bv[nt].z : bv[nt].x;
                u32 b1 = sl ? bv[nt].w : bv[nt].y;
                #pragma unroll
                for (int mt = 0; mt < 2; mt++) {
                    mma16(acc[mt][nt], a[mt],  b0, b1);
                    mma16(acc[mt][nt], as[mt], b0, b1);
                }
            }
        }
        if (s2 < 31) {
            u32 e0[4] = {na0.x, na0.y, na0.z, na0.w};
            u32 e1[4] = {na1.x, na1.y, na1.z, na1.w};
            #pragma unroll
            for (int j = 0; j < 4; j++) {
                int jj = (j + 2 * h) & 3;
                sm->A[buf ^ 1][h * 8 + 0 + jj][r] = e0[jj];
                sm->A[buf ^ 1][h * 8 + 4 + jj][r] = e1[jj];
            }
            #pragma unroll
            for (int nt = 0; nt < 4; nt++) bv[nt] = nbv[nt];
        }
        __syncthreads();
    }
}

__global__ __launch_bounds__(256) void mm_big(
    const u32* __restrict__ Ap,
    const u32* __restrict__ F,
    const float* __restrict__ bias,
    float* __restrict__ C, int ldc)
{
    __shared__ MMSmem sm;
    const int bm = blockIdx.x * 128, bn = blockIdx.y * 64;
    float acc[2][4][4];
    #pragma unroll
    for (int i = 0; i < 2; i++)
        #pragma unroll
        for (int j = 0; j < 4; j++)
            #pragma unroll
            for (int e = 0; e < 4; e++) acc[i][j][e] = 0.f;
    mm_core(&sm, Ap + (size_t)bm * DD, F, bn >> 3, acc);

    const int lane = threadIdx.x & 31;
    const int gq = lane >> 2, tq = lane & 3;
    const int w = threadIdx.x >> 5;
    const int wm = w >> 1, wn = w & 1;
    #pragma unroll
    for (int mt = 0; mt < 2; mt++)
        #pragma unroll
        for (int nt = 0; nt < 4; nt++) {
            int row = bm + wm * 32 + mt * 16 + gq;
            int col = bn + wn * 32 + nt * 8 + 2 * tq;
            float b0 = bias ? bias[col] : 0.f;
            float b1 = bias ? bias[col + 1] : 0.f;
            *(float2*)(C + (size_t)row * ldc + col) =
                make_float2(acc[mt][nt][0] + b0, acc[mt][nt][1] + b1);
            *(float2*)(C + (size_t)(row + 8) * ldc + col) =
                make_float2(acc[mt][nt][2] + b0, acc[mt][nt][3] + b1);
        }
}

// ==================================================================
// Row-group recurrence core: 16 rows x 64 h-cols x NG gates, 512 thr
// SINGLE-SHOT A tile: [kq][row][128+4] (stride 132 -> conflict-free),
// no syncthreads inside the k-loop.
// ==================================================================
struct RSG {
    union {
        u32 A[4][16][132];          // 33,792 B
        float red[384 * 25];        // 38,400 B
    };
};

template<int NG>
__device__ __forceinline__ void rec_coreG(
    RSG* sm, const u32* __restrict__ Ap,       // 16 rows, stride DD
    const u32* const* Fp, const int* gb,       // per-gate base gnt
    float acc[NG][2][4])
{
    const int tid  = threadIdx.x;
    const int lane = tid & 31;
    const int gq = lane >> 2, tq = lane & 3;
    const int w  = tid >> 5;
    const int wk = w >> 2;          // k-quarter 0..3
    const int wn = w & 3;           // n-warp 0..3

    // one-shot A load: 256 loader threads x 8 uint4 (full MLP)
    if (tid < 256) {
        const int lkq = tid >> 6;
        const int lr  = (tid >> 2) & 15;
        const int lsg = tid & 3;
        const u32* arow = Ap + (size_t)lr * DD + lkq * 128 + lsg * 4;
        #pragma unroll
        for (int s = 0; s < 8; s++) {
            uint4 v = *(const uint4*)(arow + s * 16);
            *(uint4*)&sm->A[lkq][lr][s * 16 + lsg * 4] = v;
        }
    }

    uint4 bv[NG][2], nbv[NG][2];
    #pragma unroll
    for (int g = 0; g < NG; g++)
        #pragma unroll
        for (int nt = 0; nt < 2; nt++)
            bv[g][nt] = *(const uint4*)(Fp[g] +
                (((size_t)(gb[g] + wn * 2 + nt) * 32 + wk * 8) * 32 + lane) * 4);

    __syncthreads();

    #pragma unroll 1
    for (int s2 = 0; s2 < 8; s2++) {
        if (s2 < 7) {
            #pragma unroll
            for (int g = 0; g < NG; g++)
                #pragma unroll
                for (int nt = 0; nt < 2; nt++)
                    nbv[g][nt] = *(const uint4*)(Fp[g] +
                        (((size_t)(gb[g] + wn * 2 + nt) * 32 + wk * 8 + s2 + 1) * 32 + lane) * 4);
        }
        #pragma unroll
        for (int sl = 0; sl < 2; sl++) {
            const int kb = s2 * 16 + sl * 8;
            u32 a[4], as[4];
            a[0] = sm->A[wk][gq][kb + tq];
            a[1] = sm->A[wk][gq + 8][kb + tq];
            a[2] = sm->A[wk][gq][kb + tq + 4];
            a[3] = sm->A[wk][gq + 8][kb + tq + 4];
            #pragma unroll
            for (int q = 0; q < 4; q++) as[q] = __funnelshift_l(a[q], a[q], 16);
            #pragma unroll
            for (int g = 0; g < NG; g++)
                #pragma unroll
                for (int nt = 0; nt < 2; nt++) {
                    u32 b0 = sl ? bv[g][nt].z : bv[g][nt].x;
                    u32 b1 = sl ? bv[g][nt].w : bv[g][nt].y;
                    mma16(acc[g][nt], a,  b0, b1);
                    mma16(acc[g][nt], as, b0, b1);
                }
        }
        if (s2 < 7) {
            #pragma unroll
            for (int g = 0; g < NG; g++) {
                bv[g][0] = nbv[g][0];
                bv[g][1] = nbv[g][1];
            }
        }
    }

    __syncthreads();   // A no longer needed; red overlays it

    // reduce wk=1..3 partials into wk=0 (stride 25: conflict-free)
    const int stride = NG * 8 + 1;
    if (wk) {
        int base = (tid - 128) * stride;
        #pragma unroll
        for (int g = 0; g < NG; g++)
            #pragma unroll
            for (int nt = 0; nt < 2; nt++)
                #pragma unroll
                for (int e = 0; e < 4; e++)
                    sm->red[base + (g * 2 + nt) * 4 + e] = acc[g][nt][e];
    }
    __syncthreads();
    if (!wk) {
        #pragma unroll
        for (int k = 0; k < 3; k++) {
            int base = (k * 128 + tid) * stride;
            #pragma unroll
            for (int g = 0; g < NG; g++)
                #pragma unroll
                for (int nt = 0; nt < 2; nt++)
                    #pragma unroll
                    for (int e = 0; e < 4; e++)
                        acc[g][nt][e] += sm->red[base + (g * 2 + nt) * 4 + e];
        }
    }
    __syncthreads();
}

// ---------------- persistent GRU: 16 row-groups x 8 col-blocks ----------------
__global__ __launch_bounds__(512) void gru2G(
    const float* __restrict__ zero, const u32* __restrict__ Pzero,
    const u32* __restrict__ Fwhh, const float* __restrict__ bhh,
    const float* __restrict__ xproj,
    float* __restrict__ sseq, u32* __restrict__ Psseq)
{
    __shared__ RSG sm;
    const int blk = blockIdx.x;
    const int mi = blk >> 3, di = blk & 7;
    const int bm = mi * 16;
    const int lane = threadIdx.x & 31;
    const int gq = lane >> 2, tq = lane & 3;
    const int wn = (threadIdx.x >> 5) & 3;

    const u32* Fp[3] = {Fwhh, Fwhh, Fwhh};
    int gb[3] = {di * 8, 64 + di * 8, 128 + di * 8};

    float bh[3][2][2];
    #pragma unroll
    for (int g = 0; g < 3; g++)
        #pragma unroll
        for (int nt = 0; nt < 2; nt++) {
            int col = di * 64 + wn * 16 + nt * 8 + 2 * tq;
            bh[g][nt][0] = bhh[g * 512 + col];
            bh[g][nt][1] = bhh[g * 512 + col + 1];
        }

    for (int l = 0; l < LL; l++) {
        const u32* Ap = (l ? Psseq + (size_t)(l - 1) * BBDD : Pzero) + (size_t)bm * DD;
        const float* hprev = l ? sseq + (size_t)(l - 1) * BBDD : zero;

        // prefetch epilogue lines early (overlaps entire GEMM)
        if (threadIdx.x < 128) {
            int colp = di * 64 + wn * 16;
            #pragma unroll
            for (int half = 0; half < 2; half++) {
                int row = bm + gq + half * 8;
                const float* xb = xproj + ((size_t)row * LL + l) * 1536 + colp;
                pf2(xb); pf2(xb + 512); pf2(xb + 1024);
                pf2(hprev + (size_t)row * DD + colp);
            }
        }

        float acc[3][2][4];
        #pragma unroll
        for (int g = 0; g < 3; g++)
            #pragma unroll
            for (int nt = 0; nt < 2; nt++)
                #pragma unroll
                for (int e = 0; e < 4; e++) acc[g][nt][e] = 0.f;

        rec_coreG<3>(&sm, Ap, Fp, gb, acc);

        if (threadIdx.x < 128) {
            float* sl_ = sseq + (size_t)l * BBDD;
            u32* pl = Psseq + (size_t)l * BBDD;

            #pragma unroll
            for (int nt = 0; nt < 2; nt++) {
                int col = di * 64 + wn * 16 + nt * 8 + 2 * tq;
                #pragma unroll
                for (int half = 0; half < 2; half++) {
                    int row = bm + gq + half * 8;
                    const float* xb = xproj + ((size_t)row * LL + l) * 1536;
                    size_t ix = (size_t)row * DD + col;
                    #pragma unroll
                    for (int c = 0; c < 2; c++) {
                        int e = half * 2 + c;
                        float rr = sigf(xb[col + c] + acc[0][nt][e] + bh[0][nt][c]);
                        float zz = sigf(xb[512 + col + c] + acc[1][nt][e] + bh[1][nt][c]);
                        float nn = tanhf(xb[1024 + col + c] + rr * (acc[2][nt][e] + bh[2][nt][c]));
                        float h0 = hprev[ix + c];
                        float hn = nn + zz * (h0 - nn);
                        sl_[ix + c] = hn;
                        pl[ix + c] = packbf(hn);
                    }
                }
            }
        }

        group_barrier(mi);
    }
}

// ---------------- persistent AUGRU: same grouping ----------------
__global__ __launch_bounds__(512) void augru2G(
    const float* __restrict__ hlast, const u32* __restrict__ Pinit,
    const u32* __restrict__ Frh, const u32* __restrict__ Fuh, const u32* __restrict__ Fhh,
    const float* __restrict__ rx, const float* __restrict__ ux, const float* __restrict__ nx,
    const float* __restrict__ att,
    float* __restrict__ hf, u32* __restrict__ Pp,
    u32* __restrict__ Phr, float* __restrict__ ue,
    float* __restrict__ out)
{
    __shared__ RSG sm;
    const int blk = blockIdx.x;
    const int mi = blk >> 3, di = blk & 7;
    const int bm = mi * 16;
    const int lane = threadIdx.x & 31;
    const int gq = lane >> 2, tq = lane & 3;
    const int wn = (threadIdx.x >> 5) & 3;

    for (int l = 0; l < LL; l++) {
        const float* hc = l ? hf + (size_t)(l & 1) * BBDD : hlast;
        const u32* Pc = l ? Pp + (size_t)(l & 1) * BBDD : Pinit;

        {   // phase A: r and u_eff for own 64 h-cols
            if (threadIdx.x < 128) {
                int colp = di * 64 + wn * 16;
                const float* rxl = rx + (size_t)l * BBDD;
                const float* uxl = ux + (size_t)l * BBDD;
                const float* nxl = nx + (size_t)l * BBDD;
                #pragma unroll
                for (int half = 0; half < 2; half++) {
                    int row = bm + gq + half * 8;
                    size_t ixp = (size_t)row * DD + colp;
                    pf2(rxl + ixp); pf2(uxl + ixp); pf2(nxl + ixp);
                    pf2(hc + ixp);
                }
                pf2(att + (size_t)l * BB + bm);
            }

            const u32* Fp[2] = {Frh, Fuh};
            int gb[2] = {di * 8, di * 8};
            float acc[2][2][4];
            #pragma unroll
            for (int g = 0; g < 2; g++)
                #pragma unroll
                for (int nt = 0; nt < 2; nt++)
                    #pragma unroll
                    for (int e = 0; e < 4; e++) acc[g][nt][e] = 0.f;

            rec_coreG<2>(&sm, Pc + (size_t)bm * DD, Fp, gb, acc);

            if (threadIdx.x < 128) {
                const float* rxl = rx + (size_t)l * BBDD;
                const float* uxl = ux + (size_t)l * BBDD;
                #pragma unroll
                for (int nt = 0; nt < 2; nt++) {
                    int col = di * 64 + wn * 16 + nt * 8 + 2 * tq;
                    #pragma unroll
                    for (int half = 0; half < 2; half++) {
                        int row = bm + gq + half * 8;
                        size_t ix = (size_t)row * DD + col;
                        float a = att[(size_t)l * BB + row];
                        #pragma unroll
                        for (int c = 0; c < 2; c++) {
                            int e = half * 2 + c;
                            float vr = acc[0][nt][e] + rxl[ix + c];
                            float vu = acc[1][nt][e] + uxl[ix + c];
                            Phr[ix + c] = packbf(hc[ix + c] * sigf(vr));
                            ue[ix + c]  = a * sigf(vu);
                        }
                    }
                }
            }
        }

        group_barrier(mi);

        {   // phase B: hhat + output update for own 64 h-cols
            const u32* Fp[1] = {Fhh};
            int gb[1] = {di * 8};
            float acc[1][2][4];
            #pragma unroll
            for (int nt = 0; nt < 2; nt++)
                #pragma unroll
                for (int e = 0; e < 4; e++) acc[0][nt][e] = 0.f;

            rec_coreG<1>(&sm, Phr + (size_t)bm * DD, Fp, gb, acc);

            if (threadIdx.x < 128) {
                float* ho = (l == LL - 1) ? out : hf + (size_t)((l + 1) & 1) * BBDD;
                u32* Pn = Pp + (size_t)((l + 1) & 1) * BBDD;
                const float* nxl = nx + (size_t)l * BBDD;
                #pragma unroll
                for (int nt = 0; nt < 2; nt++) {
                    int col = di * 64 + wn * 16 + nt * 8 + 2 * tq;
                    #pragma unroll
                    for (int half = 0; half < 2; half++) {
                        int row = bm + gq + half * 8;
                        size_t ix = (size_t)row * DD + col;
                        #pragma unroll
                        for (int c = 0; c < 2; c++) {
                            int e = half * 2 + c;
                            float hh = tanhf(acc[0][nt][e] + nxl[ix + c]);
                            float h0 = hc[ix + c];
                            float u0 = ue[ix + c];
                            float hn = h0 + u0 * (hh - h0);
                            ho[ix + c] = hn;
                            Pn[ix + c] = packbf(hn);
                        }
                    }
                }
            }
        }

        group_barrier(mi);
    }
}

// ---------------- conversion kernels ----------------
__global__ void pack_zero_kernel(const float* __restrict__ x, u32* __restrict__ p, int n4,
                                 float* __restrict__ z, int zn4)
{
    int i = blockIdx.x * 256 + threadIdx.x;
    if (i < n4) {
        float4 v = ((const float4*)x)[i];
        uint4 o;
        o.x = packbf(v.x); o.y = packbf(v.y); o.z = packbf(v.z); o.w = packbf(v.w);
        ((uint4*)p)[i] = o;
    }
    if (i < zn4) ((float4*)z)[i] = make_float4(0.f, 0.f, 0.f, 0.f);
}

__global__ void pack_kernel(const float* __restrict__ x, u32* __restrict__ p, int n4)
{
    int i = blockIdx.x * 256 + threadIdx.x;
    if (i < n4) {
        float4 v = ((const float4*)x)[i];
        uint4 o;
        o.x = packbf(v.x); o.y = packbf(v.y); o.z = packbf(v.z); o.w = packbf(v.w);
        ((uint4*)p)[i] = o;
    }
}

__device__ __forceinline__ void wfrag_one(const float* W, int ldw, int woff,
                                          u32* F, int idx)
{
    int j = idx & 3, lane = (idx >> 2) & 31, s2 = (idx >> 7) & 31, gnt = idx >> 12;
    int g = lane >> 2, t = lane & 3;
    int sl = s2 * 2 + (j >> 1), b = j & 1;
    int ok = sl * 8 + t + 4 * b;
    int n = gnt * 8 + g;
    F[idx] = packbf(W[(size_t)n * ldw + woff + ok]);
}

__global__ void wfrag2_kernel(const float* __restrict__ W1, const float* __restrict__ W2,
                              u32* __restrict__ F1, u32* __restrict__ F2, int total)
{
    int idx0 = blockIdx.x * 256 + threadIdx.x;
    if (idx0 < total)               wfrag_one(W1, DD, 0, F1, idx0);
    else if (idx0 < 2 * total)      wfrag_one(W2, DD, 0, F2, idx0 - total);
}

__global__ void wfrag_kernel(const float* __restrict__ W, int ldw, int woff,
                             u32* __restrict__ F, int total)
{
    int idx = blockIdx.x * 256 + threadIdx.x;
    if (idx < total) wfrag_one(W, ldw, woff, F, idx);
}

// ---------------- attention ----------------
__global__ void attn_logits(const float* __restrict__ s, const float* __restrict__ u,
                            float* __restrict__ logits)
{
    int gw = (blockIdx.x * blockDim.x + threadIdx.x) >> 5;
    int lane = threadIdx.x & 31;
    int b = gw & (BB - 1);
    const float4* sr = (const float4*)(s + (size_t)gw * DD);
    const float4* ur = (const float4*)(u + (size_t)b * DD);
    float acc = 0.f;
    #pragma unroll
    for (int k = lane; k < DD / 4; k += 32) {
        float4 a = sr[k], c = ur[k];
        acc += a.x * c.x + a.y * c.y + a.z * c.z + a.w * c.w;
    }
    #pragma unroll
    for (int o = 16; o > 0; o >>= 1) acc += __shfl_xor_sync(0xffffffffu, acc, o);
    if (lane == 0) logits[gw] = acc;
}

__global__ void attn_softmax(const float* __restrict__ logits, float* __restrict__ att)
{
    int b = blockIdx.x, t = threadIdx.x;
    __shared__ float red[256];
    float v = (t < LL) ? logits[t * BB + b] : -1e30f;
    red[t] = v;
    __syncthreads();
    for (int s = 128; s > 0; s >>= 1) {
        if (t < s) red[t] = fmaxf(red[t], red[t + s]);
        __syncthreads();
    }
    float mx = red[0];
    __syncthreads();
    float e = (t < LL) ? expf(v - mx) : 0.f;
    red[t] = e;
    __syncthreads();
    for (int s = 128; s > 0; s >>= 1) {
        if (t < s) red[t] += red[t + s];
        __syncthreads();
    }
    float inv = 1.f / red[0];
    if (t < LL) att[t * BB + b] = e * inv;
}

// ---------------- host ----------------
extern "C" void kernel_launch(void* const* d_in, const int* in_sizes, int n_in,
                              void* d_out, int out_size)
{
    const float* session  = (const float*)d_in[0];
    const float* target   = (const float*)d_in[1];
    const float* w        = (const float*)d_in[2];
    const float* wih      = (const float*)d_in[3];
    const float* whh      = (const float*)d_in[4];
    const float* bih      = (const float*)d_in[5];
    const float* bhh      = (const float*)d_in[6];
    const float* reset_w  = (const float*)d_in[7];
    const float* reset_b  = (const float*)d_in[8];
    const float* update_w = (const float*)d_in[9];
    const float* update_b = (const float*)d_in[10];
    const float* hhat_w   = (const float*)d_in[11];
    const float* hhat_b   = (const float*)d_in[12];
    float* out = (float*)d_out;

    float *xproj, *sseq, *rx, *ux, *nx, *u, *logits, *att, *ue, *hf, *zero;
    u32 *Psess, *Ptar, *Psseq, *Phr, *Pp;
    u32 *Fwih, *Fwhh, *Fw, *Frh, *Fuh, *Fhh, *Frx, *Fux, *Fhx;

    cudaGetSymbolAddress((void**)&xproj,  g_xproj);
    cudaGetSymbolAddress((void**)&sseq,   g_sseq);
    cudaGetSymbolAddress((void**)&rx,     g_rx);
    cudaGetSymbolAddress((void**)&ux,     g_ux);
    cudaGetSymbolAddress((void**)&nx,     g_nx);
    cudaGetSymbolAddress((void**)&u,      g_u);
    cudaGetSymbolAddress((void**)&logits, g_logits);
    cudaGetSymbolAddress((void**)&att,    g_att);
    cudaGetSymbolAddress((void**)&ue,     g_ue);
    cudaGetSymbolAddress((void**)&hf,     g_hf);
    cudaGetSymbolAddress((void**)&zero,   g_zero);
    cudaGetSymbolAddress((void**)&Psess,  g_Psess);
    cudaGetSymbolAddress((void**)&Ptar,   g_Ptar);
    cudaGetSymbolAddress((void**)&Psseq,  g_Psseq);
    cudaGetSymbolAddress((void**)&Phr,    g_Phr);
    cudaGetSymbolAddress((void**)&Pp,     g_Pp);
    cudaGetSymbolAddress((void**)&Fwih,   g_Fwih);
    cudaGetSymbolAddress((void**)&Fwhh,   g_Fwhh);
    cudaGetSymbolAddress((void**)&Fw,     g_Fw);
    cudaGetSymbolAddress((void**)&Frh,    g_Frh);
    cudaGetSymbolAddress((void**)&Fuh,    g_Fuh);
    cudaGetSymbolAddress((void**)&Fhh,    g_Fhh);
    cudaGetSymbolAddress((void**)&Frx,    g_Frx);
    cudaGetSymbolAddress((void**)&Fux,    g_Fux);
    cudaGetSymbolAddress((void**)&Fhx,    g_Fhx);

    // launch 1: pack session + zero buffer
    pack_zero_kernel<<<(BB * LL * DD / 4 + 255) / 256, 256>>>(
        session, Psess, BB * LL * DD / 4, zero, BB * DD / 4);
    // launch 2: both GRU weight fragment sets
    wfrag2_kernel<<<(2 * 1536 * DD + 255) / 256, 256>>>(wih, whh, Fwih, Fwhh, 1536 * DD);
    // launch 3: x_proj
    {
        dim3 g(BB * LL / 128, 3 * DD / 64);
        mm_big<<<g, 256>>>(Psess, Fwih, bih, xproj, 3 * DD);
    }
    // launch 4: persistent GRU  <- ncu capture slot
    gru2G<<<128, 512>>>(zero, (const u32*)zero, Fwhh, bhh, xproj, sseq, Psseq);

    // remaining prep
    pack_kernel<<<(BB * DD / 4 + 255) / 256, 256>>>(target, Ptar, BB * DD / 4);
    wfrag_kernel<<<(DD * DD + 255) / 256, 256>>>(w,        DD,     0,  Fw,  DD * DD);
    wfrag_kernel<<<(DD * DD + 255) / 256, 256>>>(reset_w,  2 * DD, 0,  Frh, DD * DD);
    wfrag_kernel<<<(DD * DD + 255) / 256, 256>>>(update_w, 2 * DD, 0,  Fuh, DD * DD);
    wfrag_kernel<<<(DD * DD + 255) / 256, 256>>>(hhat_w,   2 * DD, 0,  Fhh, DD * DD);
    wfrag_kernel<<<(DD * DD + 255) / 256, 256>>>(reset_w,  2 * DD, DD, Frx, DD * DD);
    wfrag_kernel<<<(DD * DD + 255) / 256, 256>>>(update_w, 2 * DD, DD, Fux, DD * DD);
    wfrag_kernel<<<(DD * DD + 255) / 256, 256>>>(hhat_w,   2 * DD, DD, Fhx, DD * DD);

    // u = target @ w^T
    {
        dim3 g(BB / 128, DD / 64);
        mm_big<<<g, 256>>>(Ptar, Fw, nullptr, u, DD);
    }
    // AUGRU x-projections (biases folded)
    {
        dim3 g(BB * LL / 128, DD / 64);
        mm_big<<<g, 256>>>(Psseq, Frx, reset_b,  rx, DD);
        mm_big<<<g, 256>>>(Psseq, Fux, update_b, ux, DD);
        mm_big<<<g, 256>>>(Psseq, Fhx, hhat_b,   nx, DD);
    }
    // attention
    attn_logits<<<LL * BB / 8, 256>>>(sseq, u, logits);
    attn_softmax<<<BB, 256>>>(logits, att);

    // persistent AUGRU; init h = sseq[L-1]
    augru2G<<<128, 512>>>(sseq + (size_t)(LL - 1) * BBDD,
                          Psseq + (size_t)(LL - 1) * BBDD,
                          Frh, Fuh, Fhh,
                          rx, ux, nx, att,
                          hf, Pp, Phr, ue, out);
}